// round 4
// baseline (speedup 1.0000x reference)
#include <cuda_runtime.h>
#include <math.h>

// Problem constants (fixed by the reference)
#define NBATCH 2
#define SEQ    2048
#define HID    2048
#define NHEADS 16
#define HD     128        // head dim
#define MROWS  (NBATCH*SEQ)   // 4096

// ---------------------------------------------------------------------------
// Device scratch (allocation-free rule: __device__ globals)
// ---------------------------------------------------------------------------
__device__ float g_q[(size_t)NBATCH*NHEADS*SEQ*HD];   // 32 MB  [B][NH][S][D]
__device__ float g_k[(size_t)NBATCH*NHEADS*SEQ*HD];   // 32 MB
__device__ float g_v[(size_t)NBATCH*NHEADS*SEQ*HD];   // 32 MB
__device__ float g_att[(size_t)NBATCH*SEQ*HID];       // 32 MB  [B][S][H]

// ---------------------------------------------------------------------------
// SGEMM  C[m][n] = sum_k A[m][k] * W[n][k]   (both row-major, K contiguous)
// 128x128 tile, BK=16, 256 threads, 8x8 micro-tile per thread.
// MODE 0: A = x, W = qkv_w, scatter into g_q/g_k/g_v with [B][NH][S][D] layout
// MODE 1: A = g_att, W = o_w, C = d_out  (plain [M][N] store)
// ---------------------------------------------------------------------------
template<int MODE>
__global__ __launch_bounds__(256)
void sgemm_nt(const float* __restrict__ A_in, const float* __restrict__ W,
              float* __restrict__ Cout, int Kdim)
{
    const int BM = 128, BN = 128, BK = 16;
    __shared__ __align__(16) float As[BK][132];
    __shared__ __align__(16) float Bs[BK][132];

    const float* A = (MODE == 0) ? A_in : g_att;

    int tid = threadIdx.x;
    int tx  = tid & 15;        // 0..15  -> 8 output cols
    int ty  = tid >> 4;        // 0..15  -> 8 output rows
    int m0  = blockIdx.y * BM;
    int n0  = blockIdx.x * BN;

    const float* Ab = A + (size_t)m0 * Kdim;
    const float* Wb = W + (size_t)n0 * Kdim;

    float acc[8][8];
#pragma unroll
    for (int i = 0; i < 8; i++)
#pragma unroll
        for (int j = 0; j < 8; j++) acc[i][j] = 0.f;

    for (int kt = 0; kt < Kdim; kt += BK) {
#pragma unroll
        for (int i = 0; i < 2; i++) {
            int lin = tid + i * 256;      // 0..511
            int row = lin >> 2;           // 0..127
            int kc  = lin & 3;            // 0..3 (float4 along K)
            float4 va = *(const float4*)(Ab + (size_t)row * Kdim + kt + kc * 4);
            As[kc*4+0][row] = va.x; As[kc*4+1][row] = va.y;
            As[kc*4+2][row] = va.z; As[kc*4+3][row] = va.w;
            float4 vb = *(const float4*)(Wb + (size_t)row * Kdim + kt + kc * 4);
            Bs[kc*4+0][row] = vb.x; Bs[kc*4+1][row] = vb.y;
            Bs[kc*4+2][row] = vb.z; Bs[kc*4+3][row] = vb.w;
        }
        __syncthreads();

#pragma unroll
        for (int kk = 0; kk < BK; kk++) {
            float a[8], b[8];
            *(float4*)(a)     = *(const float4*)&As[kk][ty * 8];
            *(float4*)(a + 4) = *(const float4*)&As[kk][ty * 8 + 4];
            *(float4*)(b)     = *(const float4*)&Bs[kk][tx * 8];
            *(float4*)(b + 4) = *(const float4*)&Bs[kk][tx * 8 + 4];
#pragma unroll
            for (int i = 0; i < 8; i++)
#pragma unroll
                for (int j = 0; j < 8; j++)
                    acc[i][j] = fmaf(a[i], b[j], acc[i][j]);
        }
        __syncthreads();
    }

    // Epilogue
#pragma unroll
    for (int i = 0; i < 8; i++) {
        int m = m0 + ty * 8 + i;
        int b = m >> 11;            // / SEQ
        int s = m & 2047;           // % SEQ
#pragma unroll
        for (int j = 0; j < 8; j++) {
            int n = n0 + tx * 8 + j;
            if (MODE == 0) {
                int which = n >> 11;            // 0=q 1=k 2=v
                int hn    = (n & 2047) >> 7;    // head
                int d     = n & 127;
                size_t idx = ((((size_t)b * NHEADS + hn) * SEQ + s) << 7) + d;
                float* dst = (which == 0) ? g_q : (which == 1) ? g_k : g_v;
                dst[idx] = acc[i][j];
            } else {
                Cout[(size_t)m * HID + n] = acc[i][j];
            }
        }
    }
}

// ---------------------------------------------------------------------------
// Rotary on q and k in place. One thread per (bh, s, d<64) pair, both bufs.
// ---------------------------------------------------------------------------
__global__ __launch_bounds__(256)
void rotary_kernel(const float* __restrict__ cosb,
                   const float* __restrict__ sinb)
{
    int idx = blockIdx.x * blockDim.x + threadIdx.x;   // NBATCH*NHEADS*SEQ*64
    int d  = idx & 63;
    int s  = (idx >> 6) & 2047;
    int bh = idx >> 17;                                // 0..31
    size_t base = (((size_t)bh * SEQ + s) << 7);
    float c  = __ldg(cosb + s * 64 + d);
    float sn = __ldg(sinb + s * 64 + d);

    float q1 = g_q[base + d], q2 = g_q[base + d + 64];
    g_q[base + d]      = q1 * c - q2 * sn;
    g_q[base + d + 64] = q2 * c + q1 * sn;

    float k1 = g_k[base + d], k2 = g_k[base + d + 64];
    g_k[base + d]      = k1 * c - k2 * sn;
    g_k[base + d + 64] = k2 * c + k1 * sn;
}

// ---------------------------------------------------------------------------
// Causal flash attention, fp32. 64 q-rows x 64 kv-rows tiles, d=128.
// 256 threads: thread t -> row r = t & 63, quarter ch = t >> 6.
//   S phase : thread computes S[r][ch*16 .. +16)  (K reads warp-uniform=bcast)
//   PV phase: thread owns O[r][ch*32 .. +32)      (V reads warp-uniform=bcast)
// Writes directly into g_att ([B][S][H]) — no pointer passing needed.
// ---------------------------------------------------------------------------
#define FLASH_SMEM_FLOATS (64*129 + 64*128 + 64*128 + 64*65 + 256 + 256)

__global__ __launch_bounds__(256)
void flash_kernel()
{
    extern __shared__ __align__(16) float sm[];
    float* Qs   = sm;                    // [64][129]
    float* Ks   = Qs + 64 * 129;         // [64][128]
    float* Vs   = Ks + 64 * 128;         // [64][128]
    float* Ss   = Vs + 64 * 128;         // [64][65]
    float* pmax = Ss + 64 * 65;          // [4][64]
    float* psum = pmax + 256;            // [4][64]

    int bh = blockIdx.x;                 // b*NHEADS + h
    int qt = blockIdx.y;
    int m0 = qt * 64;
    int t  = threadIdx.x;
    int r  = t & 63;
    int ch = t >> 6;                     // 0..3

    // Load Q tile (64x128) into smem, stride 129
    const float* Qg = g_q + ((size_t)bh * SEQ + m0) * HD;
#pragma unroll
    for (int i = 0; i < 8; i++) {
        int lin = t + i * 256;           // 0..2047
        int row = lin >> 5, c4 = lin & 31;
        float4 v = *(const float4*)(Qg + (size_t)row * HD + c4 * 4);
        float* dst = Qs + row * 129 + c4 * 4;
        dst[0] = v.x; dst[1] = v.y; dst[2] = v.z; dst[3] = v.w;
    }

    float o[32];
#pragma unroll
    for (int c = 0; c < 32; c++) o[c] = 0.f;
    float m_st = -INFINITY, l_st = 0.f;
    const float scale = 0.08838834764831845f;   // 1/sqrt(128)
    const int gi = m0 + r;

    int ntiles = qt + 1;                 // causal
    for (int tkv = 0; tkv < ntiles; tkv++) {
        int j0 = tkv * 64;
        __syncthreads();                 // prior PV done before K/V overwrite

        const float* Kg = g_k + ((size_t)bh * SEQ + j0) * HD;
        const float* Vg = g_v + ((size_t)bh * SEQ + j0) * HD;
#pragma unroll
        for (int i = 0; i < 8; i++) {
            int lin = t + i * 256;
            int row = lin >> 5, c4 = lin & 31;
            *(float4*)(Ks + row * 128 + c4 * 4) =
                *(const float4*)(Kg + (size_t)row * HD + c4 * 4);
            *(float4*)(Vs + row * 128 + c4 * 4) =
                *(const float4*)(Vg + (size_t)row * HD + c4 * 4);
        }
        __syncthreads();

        // ---- S = Q K^T (this thread: 16 cols) ----
        float sacc[16];
#pragma unroll
        for (int j = 0; j < 16; j++) sacc[j] = 0.f;
#pragma unroll
        for (int d0 = 0; d0 < 128; d0 += 8) {
            float qv[8];
#pragma unroll
            for (int e = 0; e < 8; e++) qv[e] = Qs[r * 129 + d0 + e];
#pragma unroll
            for (int j = 0; j < 16; j++) {
                const float* kp = Ks + (ch * 16 + j) * 128 + d0;  // warp-uniform
                float4 k0 = *(const float4*)kp;
                float4 k1 = *(const float4*)(kp + 4);
                float s0 = sacc[j];
                s0 = fmaf(qv[0], k0.x, s0); s0 = fmaf(qv[1], k0.y, s0);
                s0 = fmaf(qv[2], k0.z, s0); s0 = fmaf(qv[3], k0.w, s0);
                s0 = fmaf(qv[4], k1.x, s0); s0 = fmaf(qv[5], k1.y, s0);
                s0 = fmaf(qv[6], k1.z, s0); s0 = fmaf(qv[7], k1.w, s0);
                sacc[j] = s0;
            }
        }

        // ---- scale + causal mask + partial rowmax ----
        float pm = -INFINITY;
#pragma unroll
        for (int j = 0; j < 16; j++) {
            int gj = j0 + ch * 16 + j;
            float sv = sacc[j] * scale;
            if (gj > gi) sv = -INFINITY;
            sacc[j] = sv;
            pm = fmaxf(pm, sv);
        }
        pmax[ch * 64 + r] = pm;
        __syncthreads();

        float m_new = fmaxf(fmaxf(pmax[r], pmax[64 + r]),
                            fmaxf(pmax[128 + r], pmax[192 + r]));
        m_new = fmaxf(m_new, m_st);
        float corr = __expf(m_st - m_new);      // 0 on first tile (-inf arg)

        float ps = 0.f;
#pragma unroll
        for (int j = 0; j < 16; j++) {
            float p = __expf(sacc[j] - m_new);
            Ss[r * 65 + ch * 16 + j] = p;
            ps += p;
        }
        psum[ch * 64 + r] = ps;
#pragma unroll
        for (int c = 0; c < 32; c++) o[c] *= corr;
        __syncthreads();

        l_st = l_st * corr + psum[r] + psum[64 + r] + psum[128 + r] + psum[192 + r];
        m_st = m_new;

        // ---- O += P V (this thread: 32 cols) ----
#pragma unroll
        for (int j = 0; j < 64; j++) {
            float p = Ss[r * 65 + j];                 // conflict-free scalar
            const float* vp = Vs + j * 128 + ch * 32; // warp-uniform -> bcast
#pragma unroll
            for (int c = 0; c < 32; c += 4) {
                float4 vv = *(const float4*)(vp + c);
                o[c + 0] = fmaf(p, vv.x, o[c + 0]);
                o[c + 1] = fmaf(p, vv.y, o[c + 1]);
                o[c + 2] = fmaf(p, vv.z, o[c + 2]);
                o[c + 3] = fmaf(p, vv.w, o[c + 3]);
            }
        }
    }

    // ---- write O / l into g_att [B][S][H] ----
    float inv_l = 1.f / l_st;
    int b = bh >> 4, h = bh & 15;
    float* Og = g_att + ((size_t)b * SEQ + (m0 + r)) * HID + h * HD + ch * 32;
#pragma unroll
    for (int c = 0; c < 32; c += 4) {
        float4 vv = make_float4(o[c] * inv_l, o[c + 1] * inv_l,
                                o[c + 2] * inv_l, o[c + 3] * inv_l);
        *(float4*)(Og + c) = vv;
    }
}

// ---------------------------------------------------------------------------
extern "C" void kernel_launch(void* const* d_in, const int* in_sizes, int n_in,
                              void* d_out, int out_size)
{
    const float* x     = (const float*)d_in[0];
    const float* qkv_w = (const float*)d_in[1];
    const float* o_w   = (const float*)d_in[2];
    const float* cosb  = (const float*)d_in[3];
    const float* sinb  = (const float*)d_in[4];
    float* out = (float*)d_out;

    // 1) QKV projection: M=4096, N=6144, K=2048 -> scatter to g_q/g_k/g_v
    sgemm_nt<0><<<dim3(6144 / 128, MROWS / 128), 256>>>(x, qkv_w, nullptr, HID);

    // 2) rotary on q,k in place
    {
        int total = NBATCH * NHEADS * SEQ * 64;   // 4,194,304
        rotary_kernel<<<total / 256, 256>>>(cosb, sinb);
    }

    // 3) causal flash attention -> g_att  (needs >48KB dynamic smem)
    {
        const size_t smem = FLASH_SMEM_FLOATS * sizeof(float); // 117,248 B
        cudaFuncSetAttribute(flash_kernel,
                             cudaFuncAttributeMaxDynamicSharedMemorySize,
                             (int)smem);
        flash_kernel<<<dim3(NBATCH * NHEADS, SEQ / 64), 256, smem>>>();
    }

    // 4) output projection: M=4096, N=2048, K=2048 -> d_out
    sgemm_nt<1><<<dim3(HID / 128, MROWS / 128), 256>>>(nullptr, o_w, out, HID);
}

// round 5
// speedup vs baseline: 1.7875x; 1.7875x over previous
#include <cuda_runtime.h>
#include <math.h>
#include <stdint.h>

// Problem constants (fixed by the reference)
#define NBATCH 2
#define SEQ    2048
#define HID    2048
#define NHEADS 16
#define HD     128        // head dim
#define MROWS  (NBATCH*SEQ)   // 4096

// ---------------------------------------------------------------------------
// Device scratch (allocation-free rule: __device__ globals)
// ---------------------------------------------------------------------------
__device__ float g_q[(size_t)NBATCH*NHEADS*SEQ*HD];   // 32 MB  [B][NH][S][D]
__device__ float g_k[(size_t)NBATCH*NHEADS*SEQ*HD];   // 32 MB
__device__ float g_v[(size_t)NBATCH*NHEADS*SEQ*HD];   // 32 MB
__device__ float g_att[(size_t)NBATCH*SEQ*HID];       // 32 MB  [B][S][H]

// ---------------------------------------------------------------------------
// tf32 helpers
// ---------------------------------------------------------------------------
__device__ __forceinline__ float to_tf32(float x) {
    uint32_t u;
    asm("cvt.rna.tf32.f32 %0, %1;" : "=r"(u) : "f"(x));   // round-to-nearest!
    return __uint_as_float(u);
}

__device__ __forceinline__ void mma_tf32(float* c, const uint32_t* a,
                                         const uint32_t* b) {
    asm volatile(
        "mma.sync.aligned.m16n8k8.row.col.f32.tf32.tf32.f32 "
        "{%0,%1,%2,%3}, {%4,%5,%6,%7}, {%8,%9}, {%0,%1,%2,%3};"
        : "+f"(c[0]), "+f"(c[1]), "+f"(c[2]), "+f"(c[3])
        : "r"(a[0]), "r"(a[1]), "r"(a[2]), "r"(a[3]),
          "r"(b[0]), "r"(b[1]));
}

// ---------------------------------------------------------------------------
// Tensor-core GEMM  C[m][n] = sum_k A[m][k] * W[n][k]  (tf32 inputs, f32 acc)
// 128x128 block tile, BK=16, 128 threads = 4 warps (2x2), 64x64 per warp.
// Warp tile = 4 (m16) x 8 (n8) mma tiles per k8-step.
// MODE 0: A = x, W = qkv_w, scatter into g_q/g_k/g_v with [B][NH][S][D] layout
// MODE 1: A = g_att, W = o_w, C = d_out  (plain [M][N] store)
// ---------------------------------------------------------------------------
template<int MODE>
__global__ __launch_bounds__(128)
void mma_gemm(const float* __restrict__ A_in, const float* __restrict__ W,
              float* __restrict__ Cout, int Kdim)
{
    __shared__ __align__(16) float As[16][132];   // [k][m]
    __shared__ __align__(16) float Bs[16][132];   // [k][n]

    const float* A = (MODE == 0) ? A_in : g_att;

    const int tid  = threadIdx.x;
    const int warp = tid >> 5;
    const int lane = tid & 31;
    const int g    = lane >> 2;       // groupID: row within m16 / col within n8
    const int tig  = lane & 3;        // thread-in-group: k index base
    const int wm   = (warp >> 1) * 64;
    const int wn   = (warp & 1)  * 64;
    const int m0   = blockIdx.y * 128;
    const int n0   = blockIdx.x * 128;

    const float* Ab = A + (size_t)m0 * Kdim;
    const float* Wb = W + (size_t)n0 * Kdim;

    float acc[4][8][4];
#pragma unroll
    for (int mt = 0; mt < 4; mt++)
#pragma unroll
        for (int nt = 0; nt < 8; nt++)
#pragma unroll
            for (int r = 0; r < 4; r++) acc[mt][nt][r] = 0.f;

    for (int kt = 0; kt < Kdim; kt += 16) {
        // ---- cooperative load: A/B 128x16 each, converted to tf32 ----
#pragma unroll
        for (int i = 0; i < 4; i++) {
            int lin = tid + i * 128;          // 0..511
            int row = lin >> 2;               // 0..127
            int kc  = lin & 3;                // float4 slot along K
            float4 va = *(const float4*)(Ab + (size_t)row * Kdim + kt + kc * 4);
            As[kc*4+0][row] = to_tf32(va.x); As[kc*4+1][row] = to_tf32(va.y);
            As[kc*4+2][row] = to_tf32(va.z); As[kc*4+3][row] = to_tf32(va.w);
            float4 vb = *(const float4*)(Wb + (size_t)row * Kdim + kt + kc * 4);
            Bs[kc*4+0][row] = to_tf32(vb.x); Bs[kc*4+1][row] = to_tf32(vb.y);
            Bs[kc*4+2][row] = to_tf32(vb.z); Bs[kc*4+3][row] = to_tf32(vb.w);
        }
        __syncthreads();

#pragma unroll
        for (int ks = 0; ks < 16; ks += 8) {
            uint32_t af[4][4];
#pragma unroll
            for (int mt = 0; mt < 4; mt++) {
                int m = wm + mt * 16 + g;
                af[mt][0] = __float_as_uint(As[ks + tig    ][m]);
                af[mt][1] = __float_as_uint(As[ks + tig    ][m + 8]);
                af[mt][2] = __float_as_uint(As[ks + tig + 4][m]);
                af[mt][3] = __float_as_uint(As[ks + tig + 4][m + 8]);
            }
            uint32_t bf[8][2];
#pragma unroll
            for (int nt = 0; nt < 8; nt++) {
                int n = wn + nt * 8 + g;
                bf[nt][0] = __float_as_uint(Bs[ks + tig    ][n]);
                bf[nt][1] = __float_as_uint(Bs[ks + tig + 4][n]);
            }
#pragma unroll
            for (int mt = 0; mt < 4; mt++)
#pragma unroll
                for (int nt = 0; nt < 8; nt++)
                    mma_tf32(acc[mt][nt], af[mt], bf[nt]);
        }
        __syncthreads();
    }

    // ---- epilogue: c0,c1 = (row, col..col+1); c2,c3 = (row+8, col..col+1) ----
#pragma unroll
    for (int mt = 0; mt < 4; mt++) {
        int m = m0 + wm + mt * 16 + g;     // +8 stays inside the 128-row tile
        int b = m >> 11;
        int s = m & 2047;
#pragma unroll
        for (int nt = 0; nt < 8; nt++) {
            int n = n0 + wn + nt * 8 + tig * 2;
            if (MODE == 0) {
                int which = n >> 11;            // 0=q 1=k 2=v
                int hn    = (n & 2047) >> 7;    // head
                int d     = n & 127;            // even, float2-safe
                float* dst = (which == 0) ? g_q : (which == 1) ? g_k : g_v;
                size_t idx = ((((size_t)b * NHEADS + hn) * SEQ + s) << 7) + d;
                *(float2*)(dst + idx) =
                    make_float2(acc[mt][nt][0], acc[mt][nt][1]);
                *(float2*)(dst + idx + (8u << 7)) =
                    make_float2(acc[mt][nt][2], acc[mt][nt][3]);
            } else {
                *(float2*)(Cout + (size_t)m * HID + n) =
                    make_float2(acc[mt][nt][0], acc[mt][nt][1]);
                *(float2*)(Cout + (size_t)(m + 8) * HID + n) =
                    make_float2(acc[mt][nt][2], acc[mt][nt][3]);
            }
        }
    }
}

// ---------------------------------------------------------------------------
// Rotary on q and k in place. One thread per (bh, s, d<64) pair, both bufs.
// ---------------------------------------------------------------------------
__global__ __launch_bounds__(256)
void rotary_kernel(const float* __restrict__ cosb,
                   const float* __restrict__ sinb)
{
    int idx = blockIdx.x * blockDim.x + threadIdx.x;   // NBATCH*NHEADS*SEQ*64
    int d  = idx & 63;
    int s  = (idx >> 6) & 2047;
    int bh = idx >> 17;                                // 0..31
    size_t base = (((size_t)bh * SEQ + s) << 7);
    float c  = __ldg(cosb + s * 64 + d);
    float sn = __ldg(sinb + s * 64 + d);

    float q1 = g_q[base + d], q2 = g_q[base + d + 64];
    g_q[base + d]      = q1 * c - q2 * sn;
    g_q[base + d + 64] = q2 * c + q1 * sn;

    float k1 = g_k[base + d], k2 = g_k[base + d + 64];
    g_k[base + d]      = k1 * c - k2 * sn;
    g_k[base + d + 64] = k2 * c + k1 * sn;
}

// ---------------------------------------------------------------------------
// Causal flash attention, fp32. 64 q-rows x 64 kv-rows tiles, d=128.
// 256 threads: thread t -> row r = t & 63, quarter ch = t >> 6.
// Writes directly into g_att ([B][S][H]).
// ---------------------------------------------------------------------------
#define FLASH_SMEM_FLOATS (64*129 + 64*128 + 64*128 + 64*65 + 256 + 256)

__global__ __launch_bounds__(256)
void flash_kernel()
{
    extern __shared__ __align__(16) float sm[];
    float* Qs   = sm;                    // [64][129]
    float* Ks   = Qs + 64 * 129;         // [64][128]
    float* Vs   = Ks + 64 * 128;         // [64][128]
    float* Ss   = Vs + 64 * 128;         // [64][65]
    float* pmax = Ss + 64 * 65;          // [4][64]
    float* psum = pmax + 256;            // [4][64]

    int bh = blockIdx.x;                 // b*NHEADS + h
    int qt = blockIdx.y;
    int m0 = qt * 64;
    int t  = threadIdx.x;
    int r  = t & 63;
    int ch = t >> 6;                     // 0..3

    const float* Qg = g_q + ((size_t)bh * SEQ + m0) * HD;
#pragma unroll
    for (int i = 0; i < 8; i++) {
        int lin = t + i * 256;           // 0..2047
        int row = lin >> 5, c4 = lin & 31;
        float4 v = *(const float4*)(Qg + (size_t)row * HD + c4 * 4);
        float* dst = Qs + row * 129 + c4 * 4;
        dst[0] = v.x; dst[1] = v.y; dst[2] = v.z; dst[3] = v.w;
    }

    float o[32];
#pragma unroll
    for (int c = 0; c < 32; c++) o[c] = 0.f;
    float m_st = -INFINITY, l_st = 0.f;
    const float scale = 0.08838834764831845f;   // 1/sqrt(128)
    const int gi = m0 + r;

    int ntiles = qt + 1;                 // causal
    for (int tkv = 0; tkv < ntiles; tkv++) {
        int j0 = tkv * 64;
        __syncthreads();                 // prior PV done before K/V overwrite

        const float* Kg = g_k + ((size_t)bh * SEQ + j0) * HD;
        const float* Vg = g_v + ((size_t)bh * SEQ + j0) * HD;
#pragma unroll
        for (int i = 0; i < 8; i++) {
            int lin = t + i * 256;
            int row = lin >> 5, c4 = lin & 31;
            *(float4*)(Ks + row * 128 + c4 * 4) =
                *(const float4*)(Kg + (size_t)row * HD + c4 * 4);
            *(float4*)(Vs + row * 128 + c4 * 4) =
                *(const float4*)(Vg + (size_t)row * HD + c4 * 4);
        }
        __syncthreads();

        // ---- S = Q K^T (this thread: 16 cols) ----
        float sacc[16];
#pragma unroll
        for (int j = 0; j < 16; j++) sacc[j] = 0.f;
#pragma unroll
        for (int d0 = 0; d0 < 128; d0 += 8) {
            float qv[8];
#pragma unroll
            for (int e = 0; e < 8; e++) qv[e] = Qs[r * 129 + d0 + e];
#pragma unroll
            for (int j = 0; j < 16; j++) {
                const float* kp = Ks + (ch * 16 + j) * 128 + d0;  // warp-uniform
                float4 k0 = *(const float4*)kp;
                float4 k1 = *(const float4*)(kp + 4);
                float s0 = sacc[j];
                s0 = fmaf(qv[0], k0.x, s0); s0 = fmaf(qv[1], k0.y, s0);
                s0 = fmaf(qv[2], k0.z, s0); s0 = fmaf(qv[3], k0.w, s0);
                s0 = fmaf(qv[4], k1.x, s0); s0 = fmaf(qv[5], k1.y, s0);
                s0 = fmaf(qv[6], k1.z, s0); s0 = fmaf(qv[7], k1.w, s0);
                sacc[j] = s0;
            }
        }

        // ---- scale + causal mask + partial rowmax ----
        float pm = -INFINITY;
#pragma unroll
        for (int j = 0; j < 16; j++) {
            int gj = j0 + ch * 16 + j;
            float sv = sacc[j] * scale;
            if (gj > gi) sv = -INFINITY;
            sacc[j] = sv;
            pm = fmaxf(pm, sv);
        }
        pmax[ch * 64 + r] = pm;
        __syncthreads();

        float m_new = fmaxf(fmaxf(pmax[r], pmax[64 + r]),
                            fmaxf(pmax[128 + r], pmax[192 + r]));
        m_new = fmaxf(m_new, m_st);
        float corr = __expf(m_st - m_new);      // 0 on first tile (-inf arg)

        float ps = 0.f;
#pragma unroll
        for (int j = 0; j < 16; j++) {
            float p = __expf(sacc[j] - m_new);
            Ss[r * 65 + ch * 16 + j] = p;
            ps += p;
        }
        psum[ch * 64 + r] = ps;
#pragma unroll
        for (int c = 0; c < 32; c++) o[c] *= corr;
        __syncthreads();

        l_st = l_st * corr + psum[r] + psum[64 + r] + psum[128 + r] + psum[192 + r];
        m_st = m_new;

        // ---- O += P V (this thread: 32 cols) ----
#pragma unroll
        for (int j = 0; j < 64; j++) {
            float p = Ss[r * 65 + j];                 // conflict-free scalar
            const float* vp = Vs + j * 128 + ch * 32; // warp-uniform -> bcast
#pragma unroll
            for (int c = 0; c < 32; c += 4) {
                float4 vv = *(const float4*)(vp + c);
                o[c + 0] = fmaf(p, vv.x, o[c + 0]);
                o[c + 1] = fmaf(p, vv.y, o[c + 1]);
                o[c + 2] = fmaf(p, vv.z, o[c + 2]);
                o[c + 3] = fmaf(p, vv.w, o[c + 3]);
            }
        }
    }

    // ---- write O / l into g_att [B][S][H] ----
    float inv_l = 1.f / l_st;
    int b = bh >> 4, h = bh & 15;
    float* Og = g_att + ((size_t)b * SEQ + (m0 + r)) * HID + h * HD + ch * 32;
#pragma unroll
    for (int c = 0; c < 32; c += 4) {
        float4 vv = make_float4(o[c] * inv_l, o[c + 1] * inv_l,
                                o[c + 2] * inv_l, o[c + 3] * inv_l);
        *(float4*)(Og + c) = vv;
    }
}

// ---------------------------------------------------------------------------
extern "C" void kernel_launch(void* const* d_in, const int* in_sizes, int n_in,
                              void* d_out, int out_size)
{
    const float* x     = (const float*)d_in[0];
    const float* qkv_w = (const float*)d_in[1];
    const float* o_w   = (const float*)d_in[2];
    const float* cosb  = (const float*)d_in[3];
    const float* sinb  = (const float*)d_in[4];
    float* out = (float*)d_out;

    // 1) QKV projection: M=4096, N=6144, K=2048 -> scatter to g_q/g_k/g_v
    mma_gemm<0><<<dim3(6144 / 128, MROWS / 128), 128>>>(x, qkv_w, nullptr, HID);

    // 2) rotary on q,k in place
    {
        int total = NBATCH * NHEADS * SEQ * 64;   // 4,194,304
        rotary_kernel<<<total / 256, 256>>>(cosb, sinb);
    }

    // 3) causal flash attention -> g_att  (needs >48KB dynamic smem)
    {
        const size_t smem = FLASH_SMEM_FLOATS * sizeof(float); // 117,248 B
        cudaFuncSetAttribute(flash_kernel,
                             cudaFuncAttributeMaxDynamicSharedMemorySize,
                             (int)smem);
        flash_kernel<<<dim3(NBATCH * NHEADS, SEQ / 64), 256, smem>>>();
    }

    // 4) output projection: M=4096, N=2048, K=2048 -> d_out
    mma_gemm<1><<<dim3(HID / 128, MROWS / 128), 128>>>(nullptr, o_w, out, HID);
}

// round 6
// speedup vs baseline: 3.0558x; 1.7096x over previous
#include <cuda_runtime.h>
#include <math.h>
#include <stdint.h>

// Problem constants (fixed by the reference)
#define NBATCH 2
#define SEQ    2048
#define HID    2048
#define NHEADS 16
#define HD     128        // head dim
#define MROWS  (NBATCH*SEQ)   // 4096

// ---------------------------------------------------------------------------
// Device scratch (allocation-free rule: __device__ globals)
// ---------------------------------------------------------------------------
__device__ float g_q[(size_t)NBATCH*NHEADS*SEQ*HD];   // 32 MB  [B][NH][S][D]
__device__ float g_k[(size_t)NBATCH*NHEADS*SEQ*HD];   // 32 MB
__device__ float g_v[(size_t)NBATCH*NHEADS*SEQ*HD];   // 32 MB
__device__ float g_att[(size_t)NBATCH*SEQ*HID];       // 32 MB  [B][S][H]

// ---------------------------------------------------------------------------
// tf32 helpers
// ---------------------------------------------------------------------------
__device__ __forceinline__ float to_tf32(float x) {
    uint32_t u;
    asm("cvt.rna.tf32.f32 %0, %1;" : "=r"(u) : "f"(x));   // round-to-nearest!
    return __uint_as_float(u);
}

__device__ __forceinline__ void mma_tf32(float* c, const uint32_t* a,
                                         const uint32_t* b) {
    asm volatile(
        "mma.sync.aligned.m16n8k8.row.col.f32.tf32.tf32.f32 "
        "{%0,%1,%2,%3}, {%4,%5,%6,%7}, {%8,%9}, {%0,%1,%2,%3};"
        : "+f"(c[0]), "+f"(c[1]), "+f"(c[2]), "+f"(c[3])
        : "r"(a[0]), "r"(a[1]), "r"(a[2]), "r"(a[3]),
          "r"(b[0]), "r"(b[1]));
}

// ---------------------------------------------------------------------------
// Tensor-core GEMM  C[m][n] = sum_k A[m][k] * W[n][k]  (tf32 inputs, f32 acc)
// 128x128 block tile, BK=16, 128 threads = 4 warps (2x2), 64x64 per warp.
// MODE 0: A = x, W = qkv_w, scatter into g_q/g_k/g_v with [B][NH][S][D] layout
// MODE 1: A = g_att, W = o_w, C = d_out  (plain [M][N] store)
// ---------------------------------------------------------------------------
template<int MODE>
__global__ __launch_bounds__(128)
void mma_gemm(const float* __restrict__ A_in, const float* __restrict__ W,
              float* __restrict__ Cout, int Kdim)
{
    __shared__ __align__(16) float As[16][132];   // [k][m]
    __shared__ __align__(16) float Bs[16][132];   // [k][n]

    const float* A = (MODE == 0) ? A_in : g_att;

    const int tid  = threadIdx.x;
    const int warp = tid >> 5;
    const int lane = tid & 31;
    const int g    = lane >> 2;
    const int tig  = lane & 3;
    const int wm   = (warp >> 1) * 64;
    const int wn   = (warp & 1)  * 64;
    const int m0   = blockIdx.y * 128;
    const int n0   = blockIdx.x * 128;

    const float* Ab = A + (size_t)m0 * Kdim;
    const float* Wb = W + (size_t)n0 * Kdim;

    float acc[4][8][4];
#pragma unroll
    for (int mt = 0; mt < 4; mt++)
#pragma unroll
        for (int nt = 0; nt < 8; nt++)
#pragma unroll
            for (int r = 0; r < 4; r++) acc[mt][nt][r] = 0.f;

    for (int kt = 0; kt < Kdim; kt += 16) {
#pragma unroll
        for (int i = 0; i < 4; i++) {
            int lin = tid + i * 128;          // 0..511
            int row = lin >> 2;               // 0..127
            int kc  = lin & 3;
            float4 va = *(const float4*)(Ab + (size_t)row * Kdim + kt + kc * 4);
            As[kc*4+0][row] = to_tf32(va.x); As[kc*4+1][row] = to_tf32(va.y);
            As[kc*4+2][row] = to_tf32(va.z); As[kc*4+3][row] = to_tf32(va.w);
            float4 vb = *(const float4*)(Wb + (size_t)row * Kdim + kt + kc * 4);
            Bs[kc*4+0][row] = to_tf32(vb.x); Bs[kc*4+1][row] = to_tf32(vb.y);
            Bs[kc*4+2][row] = to_tf32(vb.z); Bs[kc*4+3][row] = to_tf32(vb.w);
        }
        __syncthreads();

#pragma unroll
        for (int ks = 0; ks < 16; ks += 8) {
            uint32_t af[4][4];
#pragma unroll
            for (int mt = 0; mt < 4; mt++) {
                int m = wm + mt * 16 + g;
                af[mt][0] = __float_as_uint(As[ks + tig    ][m]);
                af[mt][1] = __float_as_uint(As[ks + tig    ][m + 8]);
                af[mt][2] = __float_as_uint(As[ks + tig + 4][m]);
                af[mt][3] = __float_as_uint(As[ks + tig + 4][m + 8]);
            }
            uint32_t bf[8][2];
#pragma unroll
            for (int nt = 0; nt < 8; nt++) {
                int n = wn + nt * 8 + g;
                bf[nt][0] = __float_as_uint(Bs[ks + tig    ][n]);
                bf[nt][1] = __float_as_uint(Bs[ks + tig + 4][n]);
            }
#pragma unroll
            for (int mt = 0; mt < 4; mt++)
#pragma unroll
                for (int nt = 0; nt < 8; nt++)
                    mma_tf32(acc[mt][nt], af[mt], bf[nt]);
        }
        __syncthreads();
    }

#pragma unroll
    for (int mt = 0; mt < 4; mt++) {
        int m = m0 + wm + mt * 16 + g;
        int b = m >> 11;
        int s = m & 2047;
#pragma unroll
        for (int nt = 0; nt < 8; nt++) {
            int n = n0 + wn + nt * 8 + tig * 2;
            if (MODE == 0) {
                int which = n >> 11;            // 0=q 1=k 2=v
                int hn    = (n & 2047) >> 7;    // head
                int d     = n & 127;
                float* dst = (which == 0) ? g_q : (which == 1) ? g_k : g_v;
                size_t idx = ((((size_t)b * NHEADS + hn) * SEQ + s) << 7) + d;
                *(float2*)(dst + idx) =
                    make_float2(acc[mt][nt][0], acc[mt][nt][1]);
                *(float2*)(dst + idx + (8u << 7)) =
                    make_float2(acc[mt][nt][2], acc[mt][nt][3]);
            } else {
                *(float2*)(Cout + (size_t)m * HID + n) =
                    make_float2(acc[mt][nt][0], acc[mt][nt][1]);
                *(float2*)(Cout + (size_t)(m + 8) * HID + n) =
                    make_float2(acc[mt][nt][2], acc[mt][nt][3]);
            }
        }
    }
}

// ---------------------------------------------------------------------------
// Rotary on q and k in place.
// ---------------------------------------------------------------------------
__global__ __launch_bounds__(256)
void rotary_kernel(const float* __restrict__ cosb,
                   const float* __restrict__ sinb)
{
    int idx = blockIdx.x * blockDim.x + threadIdx.x;
    int d  = idx & 63;
    int s  = (idx >> 6) & 2047;
    int bh = idx >> 17;
    size_t base = (((size_t)bh * SEQ + s) << 7);
    float c  = __ldg(cosb + s * 64 + d);
    float sn = __ldg(sinb + s * 64 + d);

    float q1 = g_q[base + d], q2 = g_q[base + d + 64];
    g_q[base + d]      = q1 * c - q2 * sn;
    g_q[base + d + 64] = q2 * c + q1 * sn;

    float k1 = g_k[base + d], k2 = g_k[base + d + 64];
    g_k[base + d]      = k1 * c - k2 * sn;
    g_k[base + d + 64] = k2 * c + k1 * sn;
}

// ---------------------------------------------------------------------------
// Flash attention with tf32 MMA.
// Q-tile 128 rows, kv-tile 64, 256 threads = 8 warps; warp w owns q-rows
// [w*16, w*16+16) -> softmax stats are warp-local (quad shuffles only).
// Layouts ([row][col], float=tf32):
//   Qs[128][132] = Q[r][d]   (A operand, QK^T)        A-frag banks (4g+tig)
//   Ks[ 64][132] = K[j][d]   (B operand, QK^T, natural [n][k]) banks (4g+tig)
//   Vs[ 64][136] = V[j][d]   (B operand, PV,   natural [k][n]) banks (8t+g)
//   Ps[128][ 68] = P[r][j]   (A operand, PV)                   banks (4g+tig)
// All conflict-free, no transposes, all gmem loads coalesced float4.
// ---------------------------------------------------------------------------
#define FL_QS   (128*132)
#define FL_KS   (64*132)
#define FL_VS   (64*136)
#define FL_PS   (128*68)
#define FLASH2_SMEM_FLOATS (FL_QS + FL_KS + FL_VS + FL_PS)   // 42752 = 171 KB

__global__ __launch_bounds__(256, 1)
void flash_mma_kernel()
{
    extern __shared__ __align__(16) float sm[];
    float* Qs = sm;                 // [128][132]
    float* Ks = Qs + FL_QS;         // [64][132]
    float* Vs = Ks + FL_KS;         // [64][136]
    float* Ps = Vs + FL_VS;         // [128][68]

    const int bh = blockIdx.x;                       // 0..31
    const int qt = (int)gridDim.y - 1 - blockIdx.y;  // heavy tiles first
    const int m0 = qt * 128;
    const int t    = threadIdx.x;
    const int warp = t >> 5;
    const int lane = t & 31;
    const int g    = lane >> 2;
    const int tig  = lane & 3;
    const int r0   = warp * 16;     // warp's local q-row base
    const float scale = 0.08838834764831845f;        // 1/sqrt(128)

    // ---- load Q tile (128x128) -> Qs (tf32) ----
    const float* Qg = g_q + ((size_t)bh * SEQ + m0) * HD;
#pragma unroll
    for (int i = 0; i < 16; i++) {
        int lin = t + i * 256;            // 0..4095
        int row = lin >> 5, c4 = lin & 31;
        float4 v = *(const float4*)(Qg + (size_t)row * HD + c4 * 4);
        float* dst = Qs + row * 132 + c4 * 4;
        dst[0] = to_tf32(v.x); dst[1] = to_tf32(v.y);
        dst[2] = to_tf32(v.z); dst[3] = to_tf32(v.w);
    }

    float oacc[16][4];
#pragma unroll
    for (int nt = 0; nt < 16; nt++)
#pragma unroll
        for (int r = 0; r < 4; r++) oacc[nt][r] = 0.f;
    float m0r = -INFINITY, m1r = -INFINITY;   // running max, rows g / g+8
    float l0r = 0.f, l1r = 0.f;               // running sum

    const int gi0 = m0 + r0 + g;
    const int gi1 = gi0 + 8;
    const int ntiles = 2 * (qt + 1);

    for (int kt_i = 0; kt_i < ntiles; kt_i++) {
        int j0 = kt_i * 64;
        __syncthreads();     // prior PV reads of Vs done (also covers Q stores)

        // ---- load K,V tiles (64x128 each) -> Ks, Vs (tf32) ----
        const float* Kg = g_k + ((size_t)bh * SEQ + j0) * HD;
        const float* Vg = g_v + ((size_t)bh * SEQ + j0) * HD;
#pragma unroll
        for (int i = 0; i < 8; i++) {
            int lin = t + i * 256;        // 0..2047
            int row = lin >> 5, c4 = lin & 31;
            float4 kv = *(const float4*)(Kg + (size_t)row * HD + c4 * 4);
            float* kd = Ks + row * 132 + c4 * 4;
            kd[0] = to_tf32(kv.x); kd[1] = to_tf32(kv.y);
            kd[2] = to_tf32(kv.z); kd[3] = to_tf32(kv.w);
            float4 vv = *(const float4*)(Vg + (size_t)row * HD + c4 * 4);
            float* vd = Vs + row * 136 + c4 * 4;
            vd[0] = to_tf32(vv.x); vd[1] = to_tf32(vv.y);
            vd[2] = to_tf32(vv.z); vd[3] = to_tf32(vv.w);
        }
        __syncthreads();

        // ---- S = Q K^T : warp rows r0..r0+15, kv cols 0..63 ----
        float sacc[8][4];
#pragma unroll
        for (int nt = 0; nt < 8; nt++)
#pragma unroll
            for (int r = 0; r < 4; r++) sacc[nt][r] = 0.f;

#pragma unroll
        for (int ks = 0; ks < 16; ks++) {
            int kb = ks * 8;
            uint32_t a[4];
            a[0] = __float_as_uint(Qs[(r0 + g    ) * 132 + kb + tig    ]);
            a[1] = __float_as_uint(Qs[(r0 + g + 8) * 132 + kb + tig    ]);
            a[2] = __float_as_uint(Qs[(r0 + g    ) * 132 + kb + tig + 4]);
            a[3] = __float_as_uint(Qs[(r0 + g + 8) * 132 + kb + tig + 4]);
#pragma unroll
            for (int nt = 0; nt < 8; nt++) {
                uint32_t b[2];
                b[0] = __float_as_uint(Ks[(nt * 8 + g) * 132 + kb + tig    ]);
                b[1] = __float_as_uint(Ks[(nt * 8 + g) * 132 + kb + tig + 4]);
                mma_tf32(sacc[nt], a, b);
            }
        }

        // ---- softmax (warp-local; lanes of a quad share rows g / g+8) ----
        float pm0 = -INFINITY, pm1 = -INFINITY;
#pragma unroll
        for (int nt = 0; nt < 8; nt++) {
            int c = j0 + nt * 8 + tig * 2;
            float s0 = sacc[nt][0] * scale; if (c     > gi0) s0 = -INFINITY;
            float s1 = sacc[nt][1] * scale; if (c + 1 > gi0) s1 = -INFINITY;
            float s2 = sacc[nt][2] * scale; if (c     > gi1) s2 = -INFINITY;
            float s3 = sacc[nt][3] * scale; if (c + 1 > gi1) s3 = -INFINITY;
            sacc[nt][0] = s0; sacc[nt][1] = s1;
            sacc[nt][2] = s2; sacc[nt][3] = s3;
            pm0 = fmaxf(pm0, fmaxf(s0, s1));
            pm1 = fmaxf(pm1, fmaxf(s2, s3));
        }
        pm0 = fmaxf(pm0, __shfl_xor_sync(0xFFFFFFFFu, pm0, 1));
        pm0 = fmaxf(pm0, __shfl_xor_sync(0xFFFFFFFFu, pm0, 2));
        pm1 = fmaxf(pm1, __shfl_xor_sync(0xFFFFFFFFu, pm1, 1));
        pm1 = fmaxf(pm1, __shfl_xor_sync(0xFFFFFFFFu, pm1, 2));

        float mn0 = fmaxf(m0r, pm0);
        float mn1 = fmaxf(m1r, pm1);
        float corr0 = __expf(m0r - mn0);     // 0 on first tile (-inf - finite)
        float corr1 = __expf(m1r - mn1);

        float ps0 = 0.f, ps1 = 0.f;
#pragma unroll
        for (int nt = 0; nt < 8; nt++) {
            float p0 = __expf(sacc[nt][0] - mn0);
            float p1 = __expf(sacc[nt][1] - mn0);
            float p2 = __expf(sacc[nt][2] - mn1);
            float p3 = __expf(sacc[nt][3] - mn1);
            ps0 += p0 + p1; ps1 += p2 + p3;
            int jc = nt * 8 + tig * 2;
            *(float2*)(Ps + (r0 + g    ) * 68 + jc) =
                make_float2(to_tf32(p0), to_tf32(p1));
            *(float2*)(Ps + (r0 + g + 8) * 68 + jc) =
                make_float2(to_tf32(p2), to_tf32(p3));
        }
        ps0 += __shfl_xor_sync(0xFFFFFFFFu, ps0, 1);
        ps0 += __shfl_xor_sync(0xFFFFFFFFu, ps0, 2);
        ps1 += __shfl_xor_sync(0xFFFFFFFFu, ps1, 1);
        ps1 += __shfl_xor_sync(0xFFFFFFFFu, ps1, 2);

        l0r = l0r * corr0 + ps0;
        l1r = l1r * corr1 + ps1;
        m0r = mn0; m1r = mn1;

#pragma unroll
        for (int nt = 0; nt < 16; nt++) {
            oacc[nt][0] *= corr0; oacc[nt][1] *= corr0;
            oacc[nt][2] *= corr1; oacc[nt][3] *= corr1;
        }
        __syncwarp();   // Ps visible to own warp (only own rows are read)

        // ---- O += P V : K-dim 64 (8 k-steps), N-dim 128 (16 n-tiles) ----
#pragma unroll
        for (int ks = 0; ks < 8; ks++) {
            int kb = ks * 8;
            uint32_t a[4];
            a[0] = __float_as_uint(Ps[(r0 + g    ) * 68 + kb + tig    ]);
            a[1] = __float_as_uint(Ps[(r0 + g + 8) * 68 + kb + tig    ]);
            a[2] = __float_as_uint(Ps[(r0 + g    ) * 68 + kb + tig + 4]);
            a[3] = __float_as_uint(Ps[(r0 + g + 8) * 68 + kb + tig + 4]);
#pragma unroll
            for (int nt = 0; nt < 16; nt++) {
                uint32_t b[2];
                b[0] = __float_as_uint(Vs[(kb + tig    ) * 136 + nt * 8 + g]);
                b[1] = __float_as_uint(Vs[(kb + tig + 4) * 136 + nt * 8 + g]);
                mma_tf32(oacc[nt], a, b);
            }
        }
    }

    // ---- normalize + write to g_att [B][S][H] ----
    float inv0 = 1.f / l0r, inv1 = 1.f / l1r;
    int b = bh >> 4, h = bh & 15;
    int row0 = m0 + r0 + g;
    float* O0 = g_att + ((size_t)b * SEQ + row0    ) * HID + h * HD;
    float* O1 = g_att + ((size_t)b * SEQ + row0 + 8) * HID + h * HD;
#pragma unroll
    for (int nt = 0; nt < 16; nt++) {
        int d = nt * 8 + tig * 2;
        *(float2*)(O0 + d) = make_float2(oacc[nt][0] * inv0, oacc[nt][1] * inv0);
        *(float2*)(O1 + d) = make_float2(oacc[nt][2] * inv1, oacc[nt][3] * inv1);
    }
}

// ---------------------------------------------------------------------------
extern "C" void kernel_launch(void* const* d_in, const int* in_sizes, int n_in,
                              void* d_out, int out_size)
{
    const float* x     = (const float*)d_in[0];
    const float* qkv_w = (const float*)d_in[1];
    const float* o_w   = (const float*)d_in[2];
    const float* cosb  = (const float*)d_in[3];
    const float* sinb  = (const float*)d_in[4];
    float* out = (float*)d_out;

    // 1) QKV projection
    mma_gemm<0><<<dim3(6144 / 128, MROWS / 128), 128>>>(x, qkv_w, nullptr, HID);

    // 2) rotary
    {
        int total = NBATCH * NHEADS * SEQ * 64;
        rotary_kernel<<<total / 256, 256>>>(cosb, sinb);
    }

    // 3) flash attention (tf32 MMA), 171 KB dynamic smem
    {
        const size_t smem = FLASH2_SMEM_FLOATS * sizeof(float); // 171,008 B
        cudaFuncSetAttribute(flash_mma_kernel,
                             cudaFuncAttributeMaxDynamicSharedMemorySize,
                             (int)smem);
        flash_mma_kernel<<<dim3(NBATCH * NHEADS, SEQ / 128), 256, smem>>>();
    }

    // 4) output projection
    mma_gemm<1><<<dim3(HID / 128, MROWS / 128), 128>>>(nullptr, o_w, out, HID);
}

// round 7
// speedup vs baseline: 3.3881x; 1.1088x over previous
#include <cuda_runtime.h>
#include <math.h>
#include <stdint.h>

// Problem constants (fixed by the reference)
#define NBATCH 2
#define SEQ    2048
#define HID    2048
#define NHEADS 16
#define HD     128        // head dim
#define MROWS  (NBATCH*SEQ)   // 4096

// ---------------------------------------------------------------------------
// Device scratch (allocation-free rule: __device__ globals)
// ---------------------------------------------------------------------------
__device__ float g_q[(size_t)NBATCH*NHEADS*SEQ*HD];   // 32 MB  [B][NH][S][D]
__device__ float g_k[(size_t)NBATCH*NHEADS*SEQ*HD];   // 32 MB
__device__ float g_v[(size_t)NBATCH*NHEADS*SEQ*HD];   // 32 MB
__device__ float g_att[(size_t)NBATCH*SEQ*HID];       // 32 MB  [B][S][H]

// ---------------------------------------------------------------------------
// tf32 / cp.async helpers
// ---------------------------------------------------------------------------
__device__ __forceinline__ float to_tf32(float x) {
    uint32_t u;
    asm("cvt.rna.tf32.f32 %0, %1;" : "=r"(u) : "f"(x));   // round-to-nearest!
    return __uint_as_float(u);
}
__device__ __forceinline__ uint32_t tf32_bits(float x) {
    uint32_t u;
    asm("cvt.rna.tf32.f32 %0, %1;" : "=r"(u) : "f"(x));
    return u;
}

__device__ __forceinline__ void mma_tf32(float* c, const uint32_t* a,
                                         const uint32_t* b) {
    asm volatile(
        "mma.sync.aligned.m16n8k8.row.col.f32.tf32.tf32.f32 "
        "{%0,%1,%2,%3}, {%4,%5,%6,%7}, {%8,%9}, {%0,%1,%2,%3};"
        : "+f"(c[0]), "+f"(c[1]), "+f"(c[2]), "+f"(c[3])
        : "r"(a[0]), "r"(a[1]), "r"(a[2]), "r"(a[3]),
          "r"(b[0]), "r"(b[1]));
}

__device__ __forceinline__ void cp16(uint32_t smem_dst, const void* gsrc) {
    asm volatile("cp.async.cg.shared.global [%0], [%1], 16;"
                 :: "r"(smem_dst), "l"(gsrc));
}
__device__ __forceinline__ void cp_commit() {
    asm volatile("cp.async.commit_group;");
}
__device__ __forceinline__ void cp_wait1() {
    asm volatile("cp.async.wait_group 1;" ::: "memory");
}

// ---------------------------------------------------------------------------
// Pipelined tensor-core GEMM  C[m][n] = sum_k A[m][k] * W[n][k]
// Block tile 256(M) x 128(N), BK=16, 256 threads = 8 warps (4x2), 64x64/warp.
// smem: raw fp32, row-major [row][20] (stride 20 -> conflict-free frags),
// double-buffered, filled by cp.async; tf32 conversion at fragment load.
// MODE 0: A = x, W = qkv_w, scatter into g_q/g_k/g_v ([B][NH][S][D])
// MODE 1: A = g_att, W = o_w, C = d_out
// ---------------------------------------------------------------------------
#define GS_STRIDE 20
#define GS_ABUF   (256 * GS_STRIDE)            // 5120 floats
#define GS_BBUF   (128 * GS_STRIDE)            // 2560 floats
#define GS_BUF    (GS_ABUF + GS_BBUF)          // 7680 floats per stage
#define GEMM_SMEM_BYTES (2 * GS_BUF * 4)       // 61440 B

template<int MODE>
__global__ __launch_bounds__(256)
void mma_gemm(const float* __restrict__ A_in, const float* __restrict__ W,
              float* __restrict__ Cout, int Kdim)
{
    extern __shared__ __align__(16) float gsm[];
    const uint32_t sbase = (uint32_t)__cvta_generic_to_shared(gsm);

    const float* A = (MODE == 0) ? A_in : g_att;

    const int tid  = threadIdx.x;
    const int warp = tid >> 5;
    const int lane = tid & 31;
    const int g    = lane >> 2;
    const int tig  = lane & 3;
    const int wm   = (warp >> 1) * 64;      // 0,64,128,192
    const int wn   = (warp & 1)  * 64;      // 0,64
    const int m0   = blockIdx.y * 256;
    const int n0   = blockIdx.x * 128;

    const float* Ab = A + (size_t)m0 * Kdim;
    const float* Wb = W + (size_t)n0 * Kdim;

    // per-thread cp.async coordinates: row_base = tid>>2, kc = tid&3
    const int prow = tid >> 2;              // 0..63
    const int pkc  = tid & 3;               // 16B chunk along K

    float acc[4][8][4];
#pragma unroll
    for (int mt = 0; mt < 4; mt++)
#pragma unroll
        for (int nt = 0; nt < 8; nt++)
#pragma unroll
            for (int r = 0; r < 4; r++) acc[mt][nt][r] = 0.f;

    const int niter = Kdim >> 4;            // 128

    // ---- prefetch helper (macro-ish lambda) ----
    auto prefetch = [&](int kt, int buf) {
        const uint32_t b0 = sbase + (uint32_t)(buf * GS_BUF) * 4u;
#pragma unroll
        for (int j = 0; j < 4; j++) {       // A: rows prow+64j
            int row = prow + j * 64;
            cp16(b0 + (uint32_t)(row * GS_STRIDE + pkc * 4) * 4u,
                 Ab + (size_t)row * Kdim + kt * 16 + pkc * 4);
        }
#pragma unroll
        for (int j = 0; j < 2; j++) {       // B: rows prow+64j
            int row = prow + j * 64;
            cp16(b0 + (uint32_t)(GS_ABUF + row * GS_STRIDE + pkc * 4) * 4u,
                 Wb + (size_t)row * Kdim + kt * 16 + pkc * 4);
        }
    };

    prefetch(0, 0); cp_commit();
    prefetch(1, 1); cp_commit();            // Kdim >= 32 always here

    for (int kt = 0; kt < niter; kt++) {
        const int p = kt & 1;
        cp_wait1();                         // tile kt's group complete
        __syncthreads();

        const float* As = gsm + p * GS_BUF;             // [256][20]
        const float* Bs = As + GS_ABUF;                 // [128][20]

#pragma unroll
        for (int ks = 0; ks < 16; ks += 8) {
            uint32_t af[4][4];
#pragma unroll
            for (int mt = 0; mt < 4; mt++) {
                int m = wm + mt * 16 + g;
                af[mt][0] = tf32_bits(As[m       * GS_STRIDE + ks + tig    ]);
                af[mt][1] = tf32_bits(As[(m + 8) * GS_STRIDE + ks + tig    ]);
                af[mt][2] = tf32_bits(As[m       * GS_STRIDE + ks + tig + 4]);
                af[mt][3] = tf32_bits(As[(m + 8) * GS_STRIDE + ks + tig + 4]);
            }
            uint32_t bf[8][2];
#pragma unroll
            for (int nt = 0; nt < 8; nt++) {
                int n = wn + nt * 8 + g;
                bf[nt][0] = tf32_bits(Bs[n * GS_STRIDE + ks + tig    ]);
                bf[nt][1] = tf32_bits(Bs[n * GS_STRIDE + ks + tig + 4]);
            }
#pragma unroll
            for (int mt = 0; mt < 4; mt++)
#pragma unroll
                for (int nt = 0; nt < 8; nt++)
                    mma_tf32(acc[mt][nt], af[mt], bf[nt]);
        }
        __syncthreads();                    // all reads of buf p done
        if (kt + 2 < niter) prefetch(kt + 2, p);
        cp_commit();                        // dummy group in the tail keeps
    }                                       // wait_group 1 semantics exact

    // ---- epilogue ----
#pragma unroll
    for (int mt = 0; mt < 4; mt++) {
        int m = m0 + wm + mt * 16 + g;
        int b = m >> 11;
        int s = m & 2047;
#pragma unroll
        for (int nt = 0; nt < 8; nt++) {
            int n = n0 + wn + nt * 8 + tig * 2;
            if (MODE == 0) {
                int which = n >> 11;            // 0=q 1=k 2=v
                int hn    = (n & 2047) >> 7;    // head
                int d     = n & 127;
                float* dst = (which == 0) ? g_q : (which == 1) ? g_k : g_v;
                size_t idx = ((((size_t)b * NHEADS + hn) * SEQ + s) << 7) + d;
                *(float2*)(dst + idx) =
                    make_float2(acc[mt][nt][0], acc[mt][nt][1]);
                *(float2*)(dst + idx + (8u << 7)) =
                    make_float2(acc[mt][nt][2], acc[mt][nt][3]);
            } else {
                *(float2*)(Cout + (size_t)m * HID + n) =
                    make_float2(acc[mt][nt][0], acc[mt][nt][1]);
                *(float2*)(Cout + (size_t)(m + 8) * HID + n) =
                    make_float2(acc[mt][nt][2], acc[mt][nt][3]);
            }
        }
    }
}

// ---------------------------------------------------------------------------
// Rotary on q and k in place.
// ---------------------------------------------------------------------------
__global__ __launch_bounds__(256)
void rotary_kernel(const float* __restrict__ cosb,
                   const float* __restrict__ sinb)
{
    int idx = blockIdx.x * blockDim.x + threadIdx.x;
    int d  = idx & 63;
    int s  = (idx >> 6) & 2047;
    int bh = idx >> 17;
    size_t base = (((size_t)bh * SEQ + s) << 7);
    float c  = __ldg(cosb + s * 64 + d);
    float sn = __ldg(sinb + s * 64 + d);

    float q1 = g_q[base + d], q2 = g_q[base + d + 64];
    g_q[base + d]      = q1 * c - q2 * sn;
    g_q[base + d + 64] = q2 * c + q1 * sn;

    float k1 = g_k[base + d], k2 = g_k[base + d + 64];
    g_k[base + d]      = k1 * c - k2 * sn;
    g_k[base + d + 64] = k2 * c + k1 * sn;
}

// ---------------------------------------------------------------------------
// Flash attention with tf32 MMA (unchanged from R6 — passing at ~190us).
// Q-tile 128 rows, kv-tile 64, 256 threads = 8 warps; warp w owns q-rows
// [w*16, w*16+16) -> softmax stats are warp-local (quad shuffles only).
// ---------------------------------------------------------------------------
#define FL_QS   (128*132)
#define FL_KS   (64*132)
#define FL_VS   (64*136)
#define FL_PS   (128*68)
#define FLASH2_SMEM_FLOATS (FL_QS + FL_KS + FL_VS + FL_PS)   // 171 KB

__global__ __launch_bounds__(256, 1)
void flash_mma_kernel()
{
    extern __shared__ __align__(16) float sm[];
    float* Qs = sm;                 // [128][132]
    float* Ks = Qs + FL_QS;         // [64][132]
    float* Vs = Ks + FL_KS;         // [64][136]
    float* Ps = Vs + FL_VS;         // [128][68]

    const int bh = blockIdx.x;                       // 0..31
    const int qt = (int)gridDim.y - 1 - blockIdx.y;  // heavy tiles first
    const int m0 = qt * 128;
    const int t    = threadIdx.x;
    const int warp = t >> 5;
    const int lane = t & 31;
    const int g    = lane >> 2;
    const int tig  = lane & 3;
    const int r0   = warp * 16;
    const float scale = 0.08838834764831845f;        // 1/sqrt(128)

    const float* Qg = g_q + ((size_t)bh * SEQ + m0) * HD;
#pragma unroll
    for (int i = 0; i < 16; i++) {
        int lin = t + i * 256;
        int row = lin >> 5, c4 = lin & 31;
        float4 v = *(const float4*)(Qg + (size_t)row * HD + c4 * 4);
        float* dst = Qs + row * 132 + c4 * 4;
        dst[0] = to_tf32(v.x); dst[1] = to_tf32(v.y);
        dst[2] = to_tf32(v.z); dst[3] = to_tf32(v.w);
    }

    float oacc[16][4];
#pragma unroll
    for (int nt = 0; nt < 16; nt++)
#pragma unroll
        for (int r = 0; r < 4; r++) oacc[nt][r] = 0.f;
    float m0r = -INFINITY, m1r = -INFINITY;
    float l0r = 0.f, l1r = 0.f;

    const int gi0 = m0 + r0 + g;
    const int gi1 = gi0 + 8;
    const int ntiles = 2 * (qt + 1);

    for (int kt_i = 0; kt_i < ntiles; kt_i++) {
        int j0 = kt_i * 64;
        __syncthreads();

        const float* Kg = g_k + ((size_t)bh * SEQ + j0) * HD;
        const float* Vg = g_v + ((size_t)bh * SEQ + j0) * HD;
#pragma unroll
        for (int i = 0; i < 8; i++) {
            int lin = t + i * 256;
            int row = lin >> 5, c4 = lin & 31;
            float4 kv = *(const float4*)(Kg + (size_t)row * HD + c4 * 4);
            float* kd = Ks + row * 132 + c4 * 4;
            kd[0] = to_tf32(kv.x); kd[1] = to_tf32(kv.y);
            kd[2] = to_tf32(kv.z); kd[3] = to_tf32(kv.w);
            float4 vv = *(const float4*)(Vg + (size_t)row * HD + c4 * 4);
            float* vd = Vs + row * 136 + c4 * 4;
            vd[0] = to_tf32(vv.x); vd[1] = to_tf32(vv.y);
            vd[2] = to_tf32(vv.z); vd[3] = to_tf32(vv.w);
        }
        __syncthreads();

        float sacc[8][4];
#pragma unroll
        for (int nt = 0; nt < 8; nt++)
#pragma unroll
            for (int r = 0; r < 4; r++) sacc[nt][r] = 0.f;

#pragma unroll
        for (int ks = 0; ks < 16; ks++) {
            int kb = ks * 8;
            uint32_t a[4];
            a[0] = __float_as_uint(Qs[(r0 + g    ) * 132 + kb + tig    ]);
            a[1] = __float_as_uint(Qs[(r0 + g + 8) * 132 + kb + tig    ]);
            a[2] = __float_as_uint(Qs[(r0 + g    ) * 132 + kb + tig + 4]);
            a[3] = __float_as_uint(Qs[(r0 + g + 8) * 132 + kb + tig + 4]);
#pragma unroll
            for (int nt = 0; nt < 8; nt++) {
                uint32_t b[2];
                b[0] = __float_as_uint(Ks[(nt * 8 + g) * 132 + kb + tig    ]);
                b[1] = __float_as_uint(Ks[(nt * 8 + g) * 132 + kb + tig + 4]);
                mma_tf32(sacc[nt], a, b);
            }
        }

        float pm0 = -INFINITY, pm1 = -INFINITY;
#pragma unroll
        for (int nt = 0; nt < 8; nt++) {
            int c = j0 + nt * 8 + tig * 2;
            float s0 = sacc[nt][0] * scale; if (c     > gi0) s0 = -INFINITY;
            float s1 = sacc[nt][1] * scale; if (c + 1 > gi0) s1 = -INFINITY;
            float s2 = sacc[nt][2] * scale; if (c     > gi1) s2 = -INFINITY;
            float s3 = sacc[nt][3] * scale; if (c + 1 > gi1) s3 = -INFINITY;
            sacc[nt][0] = s0; sacc[nt][1] = s1;
            sacc[nt][2] = s2; sacc[nt][3] = s3;
            pm0 = fmaxf(pm0, fmaxf(s0, s1));
            pm1 = fmaxf(pm1, fmaxf(s2, s3));
        }
        pm0 = fmaxf(pm0, __shfl_xor_sync(0xFFFFFFFFu, pm0, 1));
        pm0 = fmaxf(pm0, __shfl_xor_sync(0xFFFFFFFFu, pm0, 2));
        pm1 = fmaxf(pm1, __shfl_xor_sync(0xFFFFFFFFu, pm1, 1));
        pm1 = fmaxf(pm1, __shfl_xor_sync(0xFFFFFFFFu, pm1, 2));

        float mn0 = fmaxf(m0r, pm0);
        float mn1 = fmaxf(m1r, pm1);
        float corr0 = __expf(m0r - mn0);
        float corr1 = __expf(m1r - mn1);

        float ps0 = 0.f, ps1 = 0.f;
#pragma unroll
        for (int nt = 0; nt < 8; nt++) {
            float p0 = __expf(sacc[nt][0] - mn0);
            float p1 = __expf(sacc[nt][1] - mn0);
            float p2 = __expf(sacc[nt][2] - mn1);
            float p3 = __expf(sacc[nt][3] - mn1);
            ps0 += p0 + p1; ps1 += p2 + p3;
            int jc = nt * 8 + tig * 2;
            *(float2*)(Ps + (r0 + g    ) * 68 + jc) =
                make_float2(to_tf32(p0), to_tf32(p1));
            *(float2*)(Ps + (r0 + g + 8) * 68 + jc) =
                make_float2(to_tf32(p2), to_tf32(p3));
        }
        ps0 += __shfl_xor_sync(0xFFFFFFFFu, ps0, 1);
        ps0 += __shfl_xor_sync(0xFFFFFFFFu, ps0, 2);
        ps1 += __shfl_xor_sync(0xFFFFFFFFu, ps1, 1);
        ps1 += __shfl_xor_sync(0xFFFFFFFFu, ps1, 2);

        l0r = l0r * corr0 + ps0;
        l1r = l1r * corr1 + ps1;
        m0r = mn0; m1r = mn1;

#pragma unroll
        for (int nt = 0; nt < 16; nt++) {
            oacc[nt][0] *= corr0; oacc[nt][1] *= corr0;
            oacc[nt][2] *= corr1; oacc[nt][3] *= corr1;
        }
        __syncwarp();

#pragma unroll
        for (int ks = 0; ks < 8; ks++) {
            int kb = ks * 8;
            uint32_t a[4];
            a[0] = __float_as_uint(Ps[(r0 + g    ) * 68 + kb + tig    ]);
            a[1] = __float_as_uint(Ps[(r0 + g + 8) * 68 + kb + tig    ]);
            a[2] = __float_as_uint(Ps[(r0 + g    ) * 68 + kb + tig + 4]);
            a[3] = __float_as_uint(Ps[(r0 + g + 8) * 68 + kb + tig + 4]);
#pragma unroll
            for (int nt = 0; nt < 16; nt++) {
                uint32_t b[2];
                b[0] = __float_as_uint(Vs[(kb + tig    ) * 136 + nt * 8 + g]);
                b[1] = __float_as_uint(Vs[(kb + tig + 4) * 136 + nt * 8 + g]);
                mma_tf32(oacc[nt], a, b);
            }
        }
    }

    float inv0 = 1.f / l0r, inv1 = 1.f / l1r;
    int b = bh >> 4, h = bh & 15;
    int row0 = m0 + r0 + g;
    float* O0 = g_att + ((size_t)b * SEQ + row0    ) * HID + h * HD;
    float* O1 = g_att + ((size_t)b * SEQ + row0 + 8) * HID + h * HD;
#pragma unroll
    for (int nt = 0; nt < 16; nt++) {
        int d = nt * 8 + tig * 2;
        *(float2*)(O0 + d) = make_float2(oacc[nt][0] * inv0, oacc[nt][1] * inv0);
        *(float2*)(O1 + d) = make_float2(oacc[nt][2] * inv1, oacc[nt][3] * inv1);
    }
}

// ---------------------------------------------------------------------------
extern "C" void kernel_launch(void* const* d_in, const int* in_sizes, int n_in,
                              void* d_out, int out_size)
{
    const float* x     = (const float*)d_in[0];
    const float* qkv_w = (const float*)d_in[1];
    const float* o_w   = (const float*)d_in[2];
    const float* cosb  = (const float*)d_in[3];
    const float* sinb  = (const float*)d_in[4];
    float* out = (float*)d_out;

    // 1) QKV projection: 256x128 tiles -> grid (48, 16)
    cudaFuncSetAttribute(mma_gemm<0>,
                         cudaFuncAttributeMaxDynamicSharedMemorySize,
                         GEMM_SMEM_BYTES);
    mma_gemm<0><<<dim3(6144 / 128, MROWS / 256), 256, GEMM_SMEM_BYTES>>>(
        x, qkv_w, nullptr, HID);

    // 2) rotary
    {
        int total = NBATCH * NHEADS * SEQ * 64;
        rotary_kernel<<<total / 256, 256>>>(cosb, sinb);
    }

    // 3) flash attention (tf32 MMA), 171 KB dynamic smem
    {
        const size_t smem = FLASH2_SMEM_FLOATS * sizeof(float);
        cudaFuncSetAttribute(flash_mma_kernel,
                             cudaFuncAttributeMaxDynamicSharedMemorySize,
                             (int)smem);
        flash_mma_kernel<<<dim3(NBATCH * NHEADS, SEQ / 128), 256, smem>>>();
    }

    // 4) output projection: grid (16, 16)
    cudaFuncSetAttribute(mma_gemm<1>,
                         cudaFuncAttributeMaxDynamicSharedMemorySize,
                         GEMM_SMEM_BYTES);
    mma_gemm<1><<<dim3(HID / 128, MROWS / 256), 256, GEMM_SMEM_BYTES>>>(
        nullptr, o_w, out, HID);
}

// round 9
// speedup vs baseline: 5.3985x; 1.5934x over previous
#include <cuda_runtime.h>
#include <cuda_fp16.h>
#include <math.h>
#include <stdint.h>

// Problem constants (fixed by the reference)
#define NBATCH 2
#define SEQ    2048
#define HID    2048
#define NHEADS 16
#define HD     128
#define MROWS  (NBATCH*SEQ)   // 4096

// ---------------------------------------------------------------------------
// Device scratch (allocation-free rule: __device__ globals)
// ---------------------------------------------------------------------------
__device__ float  g_q[(size_t)NBATCH*NHEADS*SEQ*HD];    // 32 MB [B][NH][S][D]
__device__ float  g_k[(size_t)NBATCH*NHEADS*SEQ*HD];    // 32 MB
__device__ float  g_v[(size_t)NBATCH*NHEADS*SEQ*HD];    // 32 MB
__device__ __half g_xh[(size_t)MROWS*HID];              // 16 MB fp16 x
__device__ __half g_wh[(size_t)4*HID*HID];              // 32 MB fp16 qkv_w|o_w
__device__ __half g_att_h[(size_t)MROWS*HID];           // 16 MB fp16 attn out

// ---------------------------------------------------------------------------
// tf32 helpers (flash kernel)
// ---------------------------------------------------------------------------
__device__ __forceinline__ float to_tf32(float x) {
    uint32_t u;
    asm("cvt.rna.tf32.f32 %0, %1;" : "=r"(u) : "f"(x));
    return __uint_as_float(u);
}

__device__ __forceinline__ void mma_tf32(float* c, const uint32_t* a,
                                         const uint32_t* b) {
    asm volatile(
        "mma.sync.aligned.m16n8k8.row.col.f32.tf32.tf32.f32 "
        "{%0,%1,%2,%3}, {%4,%5,%6,%7}, {%8,%9}, {%0,%1,%2,%3};"
        : "+f"(c[0]), "+f"(c[1]), "+f"(c[2]), "+f"(c[3])
        : "r"(a[0]), "r"(a[1]), "r"(a[2]), "r"(a[3]),
          "r"(b[0]), "r"(b[1]));
}

// fp16 MMA: D(f32) += A(f16) * B(f16),  m16n8k16
__device__ __forceinline__ void mma_f16(float* c, const uint32_t* a,
                                        const uint32_t* b) {
    asm volatile(
        "mma.sync.aligned.m16n8k16.row.col.f32.f16.f16.f32 "
        "{%0,%1,%2,%3}, {%4,%5,%6,%7}, {%8,%9}, {%0,%1,%2,%3};"
        : "+f"(c[0]), "+f"(c[1]), "+f"(c[2]), "+f"(c[3])
        : "r"(a[0]), "r"(a[1]), "r"(a[2]), "r"(a[3]),
          "r"(b[0]), "r"(b[1]));
}

__device__ __forceinline__ void cp16(uint32_t smem_dst, const void* gsrc) {
    asm volatile("cp.async.cg.shared.global [%0], [%1], 16;"
                 :: "r"(smem_dst), "l"(gsrc));
}
__device__ __forceinline__ void cp_commit() {
    asm volatile("cp.async.commit_group;");
}
__device__ __forceinline__ void cp_wait1() {
    asm volatile("cp.async.wait_group 1;" ::: "memory");
}

// ---------------------------------------------------------------------------
// fp32 -> fp16 (rn) conversion pre-passes. WHICH: 0=x, 1=qkv_w, 2=o_w
// ---------------------------------------------------------------------------
template<int WHICH>
__global__ __launch_bounds__(256)
void f2h_kernel(const float* __restrict__ src)
{
    __half* dst = (WHICH == 0) ? g_xh
                : (WHICH == 1) ? g_wh
                : g_wh + (size_t)3 * HID * HID;
    size_t i = ((size_t)blockIdx.x * 256 + threadIdx.x) * 4;
    float4 v = *(const float4*)(src + i);
    __half2 h0 = __floats2half2_rn(v.x, v.y);
    __half2 h1 = __floats2half2_rn(v.z, v.w);
    uint2 u;
    u.x = *(uint32_t*)&h0;
    u.y = *(uint32_t*)&h1;
    *(uint2*)(dst + i) = u;
}

// ---------------------------------------------------------------------------
// fp16 tensor-core GEMM  C[m][n] = sum_k A[m][k] * W[n][k]  (f32 accumulate)
// Block tile 256(M) x 128(N), BK=32, 256 threads = 8 warps (4x2), 64x64/warp.
// smem [row][40 halves] (20-word stride -> conflict-free LDS.32 frags),
// 2-stage cp.async double buffer, always-commit (wait_group 1 exact).
// MODE 0: A = g_xh, W = g_wh(qkv),  scatter into g_q/g_k/g_v ([B][NH][S][D])
// MODE 1: A = g_att_h, W = g_wh+3H^2 (o_w), C = d_out
// ---------------------------------------------------------------------------
#define HS_STRIDE 40                       // halves per row (80 B)
#define HS_ABUF   (256 * HS_STRIDE)        // 10240 halves
#define HS_BBUF   (128 * HS_STRIDE)        // 5120 halves
#define HS_BUF    (HS_ABUF + HS_BBUF)      // 15360 halves / stage
#define HGEMM_SMEM_BYTES (2 * HS_BUF * 2)  // 61440 B

template<int MODE>
__global__ __launch_bounds__(256)
void h_gemm(float* __restrict__ Cout)
{
    extern __shared__ __align__(16) __half hsm[];
    const uint32_t sbase = (uint32_t)__cvta_generic_to_shared(hsm);

    const __half* A = (MODE == 0) ? g_xh : g_att_h;
    const __half* W = (MODE == 0) ? g_wh : g_wh + (size_t)3 * HID * HID;
    const int K = HID;

    const int tid  = threadIdx.x;
    const int warp = tid >> 5;
    const int lane = tid & 31;
    const int g    = lane >> 2;
    const int tig  = lane & 3;
    const int wm   = (warp >> 1) * 64;      // 0,64,128,192
    const int wn   = (warp & 1)  * 64;      // 0,64
    const int m0   = blockIdx.y * 256;
    const int n0   = blockIdx.x * 128;

    const __half* Ab = A + (size_t)m0 * K;
    const __half* Wb = W + (size_t)n0 * K;

    const int prow = tid >> 2;              // 0..63
    const int pc   = tid & 3;               // 16B chunk (8 halves) along K

    float acc[4][8][4];
#pragma unroll
    for (int mt = 0; mt < 4; mt++)
#pragma unroll
        for (int nt = 0; nt < 8; nt++)
#pragma unroll
            for (int r = 0; r < 4; r++) acc[mt][nt][r] = 0.f;

    const int niter = K / 32;               // 64

    auto prefetch = [&](int kt, int buf) {
        const uint32_t b0 = sbase + (uint32_t)(buf * HS_BUF) * 2u;
#pragma unroll
        for (int j = 0; j < 4; j++) {        // A: 256 rows x 32 halves
            int row = prow + j * 64;
            cp16(b0 + (uint32_t)(row * HS_STRIDE + pc * 8) * 2u,
                 Ab + (size_t)row * K + kt * 32 + pc * 8);
        }
#pragma unroll
        for (int j = 0; j < 2; j++) {        // B: 128 rows x 32 halves
            int row = prow + j * 64;
            cp16(b0 + (uint32_t)(HS_ABUF + row * HS_STRIDE + pc * 8) * 2u,
                 Wb + (size_t)row * K + kt * 32 + pc * 8);
        }
    };

    prefetch(0, 0); cp_commit();
    prefetch(1, 1); cp_commit();

    for (int kt = 0; kt < niter; kt++) {
        const int p = kt & 1;
        cp_wait1();
        __syncthreads();

        const __half* As = hsm + p * HS_BUF;            // [256][40]
        const __half* Bs = As + HS_ABUF;                // [128][40]

#pragma unroll
        for (int ks = 0; ks < 2; ks++) {
            const int kb = ks * 16;
            uint32_t af[4][4];
#pragma unroll
            for (int mt = 0; mt < 4; mt++) {
                int m = wm + mt * 16 + g;
                const __half* ar0 = As + m       * HS_STRIDE + kb + tig * 2;
                const __half* ar1 = As + (m + 8) * HS_STRIDE + kb + tig * 2;
                af[mt][0] = *(const uint32_t*)(ar0);
                af[mt][1] = *(const uint32_t*)(ar1);
                af[mt][2] = *(const uint32_t*)(ar0 + 8);
                af[mt][3] = *(const uint32_t*)(ar1 + 8);
            }
            uint32_t bf[8][2];
#pragma unroll
            for (int nt = 0; nt < 8; nt++) {
                int n = wn + nt * 8 + g;
                const __half* br = Bs + n * HS_STRIDE + kb + tig * 2;
                bf[nt][0] = *(const uint32_t*)(br);
                bf[nt][1] = *(const uint32_t*)(br + 8);
            }
#pragma unroll
            for (int mt = 0; mt < 4; mt++)
#pragma unroll
                for (int nt = 0; nt < 8; nt++)
                    mma_f16(acc[mt][nt], af[mt], bf[nt]);
        }
        __syncthreads();
        if (kt + 2 < niter) prefetch(kt + 2, p);
        cp_commit();                         // always-commit keeps wait exact
    }

    // ---- epilogue ----
#pragma unroll
    for (int mt = 0; mt < 4; mt++) {
        int m = m0 + wm + mt * 16 + g;
        int b = m >> 11;
        int s = m & 2047;
#pragma unroll
        for (int nt = 0; nt < 8; nt++) {
            int n = n0 + wn + nt * 8 + tig * 2;
            if (MODE == 0) {
                int which = n >> 11;            // 0=q 1=k 2=v
                int hn    = (n & 2047) >> 7;    // head
                int d     = n & 127;
                float* dst = (which == 0) ? g_q : (which == 1) ? g_k : g_v;
                size_t idx = ((((size_t)b * NHEADS + hn) * SEQ + s) << 7) + d;
                *(float2*)(dst + idx) =
                    make_float2(acc[mt][nt][0], acc[mt][nt][1]);
                *(float2*)(dst + idx + (8u << 7)) =
                    make_float2(acc[mt][nt][2], acc[mt][nt][3]);
            } else {
                *(float2*)(Cout + (size_t)m * HID + n) =
                    make_float2(acc[mt][nt][0], acc[mt][nt][1]);
                *(float2*)(Cout + (size_t)(m + 8) * HID + n) =
                    make_float2(acc[mt][nt][2], acc[mt][nt][3]);
            }
        }
    }
}

// ---------------------------------------------------------------------------
// Rotary on q and k in place.
// ---------------------------------------------------------------------------
__global__ __launch_bounds__(256)
void rotary_kernel(const float* __restrict__ cosb,
                   const float* __restrict__ sinb)
{
    int idx = blockIdx.x * blockDim.x + threadIdx.x;
    int d  = idx & 63;
    int s  = (idx >> 6) & 2047;
    int bh = idx >> 17;
    size_t base = (((size_t)bh * SEQ + s) << 7);
    float c  = __ldg(cosb + s * 64 + d);
    float sn = __ldg(sinb + s * 64 + d);

    float q1 = g_q[base + d], q2 = g_q[base + d + 64];
    g_q[base + d]      = q1 * c - q2 * sn;
    g_q[base + d + 64] = q2 * c + q1 * sn;

    float k1 = g_k[base + d], k2 = g_k[base + d + 64];
    g_k[base + d]      = k1 * c - k2 * sn;
    g_k[base + d + 64] = k2 * c + k1 * sn;
}

// ---------------------------------------------------------------------------
// Flash attention with legacy tf32 MMA (math unchanged from R7; epilogue now
// writes fp16 into g_att_h, which is GEMM-1's A operand).
// ---------------------------------------------------------------------------
#define FL_QS   (128*132)
#define FL_KS   (64*132)
#define FL_VS   (64*136)
#define FL_PS   (128*68)
#define FLASH2_SMEM_FLOATS (FL_QS + FL_KS + FL_VS + FL_PS)   // 171 KB

__global__ __launch_bounds__(256, 1)
void flash_mma_kernel()
{
    extern __shared__ __align__(16) float sm[];
    float* Qs = sm;                 // [128][132]
    float* Ks = Qs + FL_QS;         // [64][132]
    float* Vs = Ks + FL_KS;         // [64][136]
    float* Ps = Vs + FL_VS;         // [128][68]

    const int bh = blockIdx.x;
    const int qt = (int)gridDim.y - 1 - blockIdx.y;
    const int m0 = qt * 128;
    const int t    = threadIdx.x;
    const int warp = t >> 5;
    const int lane = t & 31;
    const int g    = lane >> 2;
    const int tig  = lane & 3;
    const int r0   = warp * 16;
    const float scale = 0.08838834764831845f;

    const float* Qg = g_q + ((size_t)bh * SEQ + m0) * HD;
#pragma unroll
    for (int i = 0; i < 16; i++) {
        int lin = t + i * 256;
        int row = lin >> 5, c4 = lin & 31;
        float4 v = *(const float4*)(Qg + (size_t)row * HD + c4 * 4);
        float* dst = Qs + row * 132 + c4 * 4;
        dst[0] = to_tf32(v.x); dst[1] = to_tf32(v.y);
        dst[2] = to_tf32(v.z); dst[3] = to_tf32(v.w);
    }

    float oacc[16][4];
#pragma unroll
    for (int nt = 0; nt < 16; nt++)
#pragma unroll
        for (int r = 0; r < 4; r++) oacc[nt][r] = 0.f;
    float m0r = -INFINITY, m1r = -INFINITY;
    float l0r = 0.f, l1r = 0.f;

    const int gi0 = m0 + r0 + g;
    const int gi1 = gi0 + 8;
    const int ntiles = 2 * (qt + 1);

    for (int kt_i = 0; kt_i < ntiles; kt_i++) {
        int j0 = kt_i * 64;
        __syncthreads();

        const float* Kg = g_k + ((size_t)bh * SEQ + j0) * HD;
        const float* Vg = g_v + ((size_t)bh * SEQ + j0) * HD;
#pragma unroll
        for (int i = 0; i < 8; i++) {
            int lin = t + i * 256;
            int row = lin >> 5, c4 = lin & 31;
            float4 kv = *(const float4*)(Kg + (size_t)row * HD + c4 * 4);
            float* kd = Ks + row * 132 + c4 * 4;
            kd[0] = to_tf32(kv.x); kd[1] = to_tf32(kv.y);
            kd[2] = to_tf32(kv.z); kd[3] = to_tf32(kv.w);
            float4 vv = *(const float4*)(Vg + (size_t)row * HD + c4 * 4);
            float* vd = Vs + row * 136 + c4 * 4;
            vd[0] = to_tf32(vv.x); vd[1] = to_tf32(vv.y);
            vd[2] = to_tf32(vv.z); vd[3] = to_tf32(vv.w);
        }
        __syncthreads();

        float sacc[8][4];
#pragma unroll
        for (int nt = 0; nt < 8; nt++)
#pragma unroll
            for (int r = 0; r < 4; r++) sacc[nt][r] = 0.f;

#pragma unroll
        for (int ks = 0; ks < 16; ks++) {
            int kb = ks * 8;
            uint32_t a[4];
            a[0] = __float_as_uint(Qs[(r0 + g    ) * 132 + kb + tig    ]);
            a[1] = __float_as_uint(Qs[(r0 + g + 8) * 132 + kb + tig    ]);
            a[2] = __float_as_uint(Qs[(r0 + g    ) * 132 + kb + tig + 4]);
            a[3] = __float_as_uint(Qs[(r0 + g + 8) * 132 + kb + tig + 4]);
#pragma unroll
            for (int nt = 0; nt < 8; nt++) {
                uint32_t b[2];
                b[0] = __float_as_uint(Ks[(nt * 8 + g) * 132 + kb + tig    ]);
                b[1] = __float_as_uint(Ks[(nt * 8 + g) * 132 + kb + tig + 4]);
                mma_tf32(sacc[nt], a, b);
            }
        }

        float pm0 = -INFINITY, pm1 = -INFINITY;
#pragma unroll
        for (int nt = 0; nt < 8; nt++) {
            int c = j0 + nt * 8 + tig * 2;
            float s0 = sacc[nt][0] * scale; if (c     > gi0) s0 = -INFINITY;
            float s1 = sacc[nt][1] * scale; if (c + 1 > gi0) s1 = -INFINITY;
            float s2 = sacc[nt][2] * scale; if (c     > gi1) s2 = -INFINITY;
            float s3 = sacc[nt][3] * scale; if (c + 1 > gi1) s3 = -INFINITY;
            sacc[nt][0] = s0; sacc[nt][1] = s1;
            sacc[nt][2] = s2; sacc[nt][3] = s3;
            pm0 = fmaxf(pm0, fmaxf(s0, s1));
            pm1 = fmaxf(pm1, fmaxf(s2, s3));
        }
        pm0 = fmaxf(pm0, __shfl_xor_sync(0xFFFFFFFFu, pm0, 1));
        pm0 = fmaxf(pm0, __shfl_xor_sync(0xFFFFFFFFu, pm0, 2));
        pm1 = fmaxf(pm1, __shfl_xor_sync(0xFFFFFFFFu, pm1, 1));
        pm1 = fmaxf(pm1, __shfl_xor_sync(0xFFFFFFFFu, pm1, 2));

        float mn0 = fmaxf(m0r, pm0);
        float mn1 = fmaxf(m1r, pm1);
        float corr0 = __expf(m0r - mn0);
        float corr1 = __expf(m1r - mn1);

        float ps0 = 0.f, ps1 = 0.f;
#pragma unroll
        for (int nt = 0; nt < 8; nt++) {
            float p0 = __expf(sacc[nt][0] - mn0);
            float p1 = __expf(sacc[nt][1] - mn0);
            float p2 = __expf(sacc[nt][2] - mn1);
            float p3 = __expf(sacc[nt][3] - mn1);
            ps0 += p0 + p1; ps1 += p2 + p3;
            int jc = nt * 8 + tig * 2;
            *(float2*)(Ps + (r0 + g    ) * 68 + jc) =
                make_float2(to_tf32(p0), to_tf32(p1));
            *(float2*)(Ps + (r0 + g + 8) * 68 + jc) =
                make_float2(to_tf32(p2), to_tf32(p3));
        }
        ps0 += __shfl_xor_sync(0xFFFFFFFFu, ps0, 1);
        ps0 += __shfl_xor_sync(0xFFFFFFFFu, ps0, 2);
        ps1 += __shfl_xor_sync(0xFFFFFFFFu, ps1, 1);
        ps1 += __shfl_xor_sync(0xFFFFFFFFu, ps1, 2);

        l0r = l0r * corr0 + ps0;
        l1r = l1r * corr1 + ps1;
        m0r = mn0; m1r = mn1;

#pragma unroll
        for (int nt = 0; nt < 16; nt++) {
            oacc[nt][0] *= corr0; oacc[nt][1] *= corr0;
            oacc[nt][2] *= corr1; oacc[nt][3] *= corr1;
        }
        __syncwarp();

#pragma unroll
        for (int ks = 0; ks < 8; ks++) {
            int kb = ks * 8;
            uint32_t a[4];
            a[0] = __float_as_uint(Ps[(r0 + g    ) * 68 + kb + tig    ]);
            a[1] = __float_as_uint(Ps[(r0 + g + 8) * 68 + kb + tig    ]);
            a[2] = __float_as_uint(Ps[(r0 + g    ) * 68 + kb + tig + 4]);
            a[3] = __float_as_uint(Ps[(r0 + g + 8) * 68 + kb + tig + 4]);
#pragma unroll
            for (int nt = 0; nt < 16; nt++) {
                uint32_t b[2];
                b[0] = __float_as_uint(Vs[(kb + tig    ) * 136 + nt * 8 + g]);
                b[1] = __float_as_uint(Vs[(kb + tig + 4) * 136 + nt * 8 + g]);
                mma_tf32(oacc[nt], a, b);
            }
        }
    }

    // ---- normalize + write fp16 into g_att_h [B][S][H] ----
    float inv0 = 1.f / l0r, inv1 = 1.f / l1r;
    int b = bh >> 4, h = bh & 15;
    int row0 = m0 + r0 + g;
    __half* O0 = g_att_h + ((size_t)b * SEQ + row0    ) * HID + h * HD;
    __half* O1 = g_att_h + ((size_t)b * SEQ + row0 + 8) * HID + h * HD;
#pragma unroll
    for (int nt = 0; nt < 16; nt++) {
        int d = nt * 8 + tig * 2;
        *(__half2*)(O0 + d) =
            __floats2half2_rn(oacc[nt][0] * inv0, oacc[nt][1] * inv0);
        *(__half2*)(O1 + d) =
            __floats2half2_rn(oacc[nt][2] * inv1, oacc[nt][3] * inv1);
    }
}

// ---------------------------------------------------------------------------
extern "C" void kernel_launch(void* const* d_in, const int* in_sizes, int n_in,
                              void* d_out, int out_size)
{
    const float* x     = (const float*)d_in[0];
    const float* qkv_w = (const float*)d_in[1];
    const float* o_w   = (const float*)d_in[2];
    const float* cosb  = (const float*)d_in[3];
    const float* sinb  = (const float*)d_in[4];
    float* out = (float*)d_out;

    cudaFuncSetAttribute(h_gemm<0>,
        cudaFuncAttributeMaxDynamicSharedMemorySize, HGEMM_SMEM_BYTES);
    cudaFuncSetAttribute(h_gemm<1>,
        cudaFuncAttributeMaxDynamicSharedMemorySize, HGEMM_SMEM_BYTES);

    // 0) fp32 -> fp16 (rn) conversions of GEMM inputs
    f2h_kernel<0><<<(MROWS * HID) / 1024, 256>>>(x);
    f2h_kernel<1><<<(3 * HID * HID) / 1024, 256>>>(qkv_w);
    f2h_kernel<2><<<(HID * HID) / 1024, 256>>>(o_w);

    // 1) QKV projection: grid (48, 16)
    h_gemm<0><<<dim3(6144 / 128, MROWS / 256), 256, HGEMM_SMEM_BYTES>>>(nullptr);

    // 2) rotary
    rotary_kernel<<<(NBATCH * NHEADS * SEQ * 64) / 256, 256>>>(cosb, sinb);

    // 3) flash attention (tf32 MMA), 171 KB smem; writes g_att_h (fp16)
    {
        const size_t smem = FLASH2_SMEM_FLOATS * sizeof(float);
        cudaFuncSetAttribute(flash_mma_kernel,
                             cudaFuncAttributeMaxDynamicSharedMemorySize,
                             (int)smem);
        flash_mma_kernel<<<dim3(NBATCH * NHEADS, SEQ / 128), 256, smem>>>();
    }

    // 4) output projection: grid (16, 16)
    h_gemm<1><<<dim3(HID / 128, MROWS / 256), 256, HGEMM_SMEM_BYTES>>>(out);
}

// round 10
// speedup vs baseline: 5.5252x; 1.0235x over previous
#include <cuda_runtime.h>
#include <cuda_fp16.h>
#include <math.h>
#include <stdint.h>

// Problem constants (fixed by the reference)
#define NBATCH 2
#define SEQ    2048
#define HID    2048
#define NHEADS 16
#define HD     128
#define MROWS  (NBATCH*SEQ)   // 4096

// ---------------------------------------------------------------------------
// Device scratch (allocation-free rule: __device__ globals)
// ---------------------------------------------------------------------------
__device__ float  g_q[(size_t)NBATCH*NHEADS*SEQ*HD];    // 32 MB [B][NH][S][D]
__device__ float  g_k[(size_t)NBATCH*NHEADS*SEQ*HD];    // 32 MB
__device__ float  g_v[(size_t)NBATCH*NHEADS*SEQ*HD];    // 32 MB
__device__ __half g_xh[(size_t)MROWS*HID];              // 16 MB fp16 x
__device__ __half g_wh[(size_t)4*HID*HID];              // 32 MB fp16 qkv_w|o_w
__device__ __half g_att_h[(size_t)MROWS*HID];           // 16 MB fp16 attn out

// ---------------------------------------------------------------------------
// tf32 helpers (flash kernel)
// ---------------------------------------------------------------------------
__device__ __forceinline__ float to_tf32(float x) {
    uint32_t u;
    asm("cvt.rna.tf32.f32 %0, %1;" : "=r"(u) : "f"(x));
    return __uint_as_float(u);
}

__device__ __forceinline__ void mma_tf32(float* c, const uint32_t* a,
                                         const uint32_t* b) {
    asm volatile(
        "mma.sync.aligned.m16n8k8.row.col.f32.tf32.tf32.f32 "
        "{%0,%1,%2,%3}, {%4,%5,%6,%7}, {%8,%9}, {%0,%1,%2,%3};"
        : "+f"(c[0]), "+f"(c[1]), "+f"(c[2]), "+f"(c[3])
        : "r"(a[0]), "r"(a[1]), "r"(a[2]), "r"(a[3]),
          "r"(b[0]), "r"(b[1]));
}

// fp16 MMA: D(f32) += A(f16) * B(f16),  m16n8k16
__device__ __forceinline__ void mma_f16(float* c, const uint32_t* a,
                                        const uint32_t* b) {
    asm volatile(
        "mma.sync.aligned.m16n8k16.row.col.f32.f16.f16.f32 "
        "{%0,%1,%2,%3}, {%4,%5,%6,%7}, {%8,%9}, {%0,%1,%2,%3};"
        : "+f"(c[0]), "+f"(c[1]), "+f"(c[2]), "+f"(c[3])
        : "r"(a[0]), "r"(a[1]), "r"(a[2]), "r"(a[3]),
          "r"(b[0]), "r"(b[1]));
}

__device__ __forceinline__ void ldsm_x4(uint32_t* r, uint32_t saddr) {
    asm volatile(
        "ldmatrix.sync.aligned.m8n8.x4.shared.b16 {%0,%1,%2,%3}, [%4];"
        : "=r"(r[0]), "=r"(r[1]), "=r"(r[2]), "=r"(r[3]) : "r"(saddr));
}

__device__ __forceinline__ void cp16(uint32_t smem_dst, const void* gsrc) {
    asm volatile("cp.async.cg.shared.global [%0], [%1], 16;"
                 :: "r"(smem_dst), "l"(gsrc));
}
__device__ __forceinline__ void cp_commit() {
    asm volatile("cp.async.commit_group;");
}
__device__ __forceinline__ void cp_wait1() {
    asm volatile("cp.async.wait_group 1;" ::: "memory");
}

// ---------------------------------------------------------------------------
// fp32 -> fp16 (rn) conversion pre-passes. WHICH: 0=x, 1=qkv_w, 2=o_w
// ---------------------------------------------------------------------------
template<int WHICH>
__global__ __launch_bounds__(256)
void f2h_kernel(const float* __restrict__ src)
{
    __half* dst = (WHICH == 0) ? g_xh
                : (WHICH == 1) ? g_wh
                : g_wh + (size_t)3 * HID * HID;
    size_t i = ((size_t)blockIdx.x * 256 + threadIdx.x) * 4;
    float4 v = *(const float4*)(src + i);
    __half2 h0 = __floats2half2_rn(v.x, v.y);
    __half2 h1 = __floats2half2_rn(v.z, v.w);
    uint2 u;
    u.x = *(uint32_t*)&h0;
    u.y = *(uint32_t*)&h1;
    *(uint2*)(dst + i) = u;
}

// ---------------------------------------------------------------------------
// fp16 tensor-core GEMM  C[m][n] = sum_k A[m][k] * W[n][k]  (f32 accumulate)
// Block tile 256(M) x 128(N), BK=32, 256 threads = 8 warps (4x2), 64x64/warp.
// smem [row][40 halves] (80B stride: 8 consecutive rows hit 8 distinct 16B
// banks -> ldmatrix conflict-free). 2-stage cp.async double buffer.
// Fragments fed by ldmatrix.m8n8.x4 (4 regs / instruction).
// MODE 0: A = g_xh, W = g_wh(qkv),  scatter into g_q/g_k/g_v ([B][NH][S][D])
// MODE 1: A = g_att_h, W = g_wh+3H^2 (o_w), C = d_out
// ---------------------------------------------------------------------------
#define HS_STRIDE 40                       // halves per row (80 B)
#define HS_ABUF   (256 * HS_STRIDE)        // 10240 halves
#define HS_BBUF   (128 * HS_STRIDE)        // 5120 halves
#define HS_BUF    (HS_ABUF + HS_BBUF)      // 15360 halves / stage
#define HGEMM_SMEM_BYTES (2 * HS_BUF * 2)  // 61440 B

template<int MODE>
__global__ __launch_bounds__(256)
void h_gemm(float* __restrict__ Cout)
{
    extern __shared__ __align__(16) __half hsm[];
    const uint32_t sbase = (uint32_t)__cvta_generic_to_shared(hsm);

    const __half* A = (MODE == 0) ? g_xh : g_att_h;
    const __half* W = (MODE == 0) ? g_wh : g_wh + (size_t)3 * HID * HID;
    const int K = HID;

    const int tid  = threadIdx.x;
    const int warp = tid >> 5;
    const int lane = tid & 31;
    const int g    = lane >> 2;
    const int tig  = lane & 3;
    const int wm   = (warp >> 1) * 64;      // 0,64,128,192
    const int wn   = (warp & 1)  * 64;      // 0,64
    const int m0   = blockIdx.y * 256;
    const int n0   = blockIdx.x * 128;

    const __half* Ab = A + (size_t)m0 * K;
    const __half* Wb = W + (size_t)n0 * K;

    const int prow = tid >> 2;              // 0..63
    const int pc   = tid & 3;               // 16B chunk (8 halves) along K

    // ldmatrix lane -> smem coordinates
    const int lrA = lane & 15;              // A: row within 16-row tile
    const int lcA = (lane >> 4) * 8;        // A: k offset (0 or 8)
    const int lrB = (lane >> 4) * 8 + (lane & 7);   // B: n offset within pair
    const int lcB = ((lane >> 3) & 1) * 8;          // B: k offset (0 or 8)

    float acc[4][8][4];
#pragma unroll
    for (int mt = 0; mt < 4; mt++)
#pragma unroll
        for (int nt = 0; nt < 8; nt++)
#pragma unroll
            for (int r = 0; r < 4; r++) acc[mt][nt][r] = 0.f;

    const int niter = K / 32;               // 64

    auto prefetch = [&](int kt, int buf) {
        const uint32_t b0 = sbase + (uint32_t)(buf * HS_BUF) * 2u;
#pragma unroll
        for (int j = 0; j < 4; j++) {        // A: 256 rows x 32 halves
            int row = prow + j * 64;
            cp16(b0 + (uint32_t)(row * HS_STRIDE + pc * 8) * 2u,
                 Ab + (size_t)row * K + kt * 32 + pc * 8);
        }
#pragma unroll
        for (int j = 0; j < 2; j++) {        // B: 128 rows x 32 halves
            int row = prow + j * 64;
            cp16(b0 + (uint32_t)(HS_ABUF + row * HS_STRIDE + pc * 8) * 2u,
                 Wb + (size_t)row * K + kt * 32 + pc * 8);
        }
    };

    prefetch(0, 0); cp_commit();
    prefetch(1, 1); cp_commit();

    for (int kt = 0; kt < niter; kt++) {
        const int p = kt & 1;
        cp_wait1();
        __syncthreads();

        const uint32_t asb = sbase + (uint32_t)(p * HS_BUF) * 2u;
        const uint32_t bsb = asb + (uint32_t)HS_ABUF * 2u;

#pragma unroll
        for (int ks = 0; ks < 2; ks++) {
            const int kb = ks * 16;
            uint32_t af[4][4];
#pragma unroll
            for (int mt = 0; mt < 4; mt++) {
                uint32_t addr = asb +
                    (uint32_t)((wm + mt * 16 + lrA) * HS_STRIDE + kb + lcA) * 2u;
                ldsm_x4(af[mt], addr);
            }
            uint32_t bf[8][2];
#pragma unroll
            for (int nt2 = 0; nt2 < 4; nt2++) {
                uint32_t r[4];
                uint32_t addr = bsb +
                    (uint32_t)((wn + nt2 * 16 + lrB) * HS_STRIDE + kb + lcB) * 2u;
                ldsm_x4(r, addr);
                bf[nt2 * 2][0]     = r[0];
                bf[nt2 * 2][1]     = r[1];
                bf[nt2 * 2 + 1][0] = r[2];
                bf[nt2 * 2 + 1][1] = r[3];
            }
#pragma unroll
            for (int mt = 0; mt < 4; mt++)
#pragma unroll
                for (int nt = 0; nt < 8; nt++)
                    mma_f16(acc[mt][nt], af[mt], bf[nt]);
        }
        __syncthreads();
        if (kt + 2 < niter) prefetch(kt + 2, p);
        cp_commit();                         // always-commit keeps wait exact
    }

    // ---- epilogue ----
#pragma unroll
    for (int mt = 0; mt < 4; mt++) {
        int m = m0 + wm + mt * 16 + g;
        int b = m >> 11;
        int s = m & 2047;
#pragma unroll
        for (int nt = 0; nt < 8; nt++) {
            int n = n0 + wn + nt * 8 + tig * 2;
            if (MODE == 0) {
                int which = n >> 11;            // 0=q 1=k 2=v
                int hn    = (n & 2047) >> 7;    // head
                int d     = n & 127;
                float* dst = (which == 0) ? g_q : (which == 1) ? g_k : g_v;
                size_t idx = ((((size_t)b * NHEADS + hn) * SEQ + s) << 7) + d;
                *(float2*)(dst + idx) =
                    make_float2(acc[mt][nt][0], acc[mt][nt][1]);
                *(float2*)(dst + idx + (8u << 7)) =
                    make_float2(acc[mt][nt][2], acc[mt][nt][3]);
            } else {
                *(float2*)(Cout + (size_t)m * HID + n) =
                    make_float2(acc[mt][nt][0], acc[mt][nt][1]);
                *(float2*)(Cout + (size_t)(m + 8) * HID + n) =
                    make_float2(acc[mt][nt][2], acc[mt][nt][3]);
            }
        }
    }
}

// ---------------------------------------------------------------------------
// Rotary on q and k in place.
// ---------------------------------------------------------------------------
__global__ __launch_bounds__(256)
void rotary_kernel(const float* __restrict__ cosb,
                   const float* __restrict__ sinb)
{
    int idx = blockIdx.x * blockDim.x + threadIdx.x;
    int d  = idx & 63;
    int s  = (idx >> 6) & 2047;
    int bh = idx >> 17;
    size_t base = (((size_t)bh * SEQ + s) << 7);
    float c  = __ldg(cosb + s * 64 + d);
    float sn = __ldg(sinb + s * 64 + d);

    float q1 = g_q[base + d], q2 = g_q[base + d + 64];
    g_q[base + d]      = q1 * c - q2 * sn;
    g_q[base + d + 64] = q2 * c + q1 * sn;

    float k1 = g_k[base + d], k2 = g_k[base + d + 64];
    g_k[base + d]      = k1 * c - k2 * sn;
    g_k[base + d + 64] = k2 * c + k1 * sn;
}

// ---------------------------------------------------------------------------
// Flash attention with legacy tf32 MMA (unchanged math; writes fp16 g_att_h).
// ---------------------------------------------------------------------------
#define FL_QS   (128*132)
#define FL_KS   (64*132)
#define FL_VS   (64*136)
#define FL_PS   (128*68)
#define FLASH2_SMEM_FLOATS (FL_QS + FL_KS + FL_VS + FL_PS)   // 171 KB

__global__ __launch_bounds__(256, 1)
void flash_mma_kernel()
{
    extern __shared__ __align__(16) float sm[];
    float* Qs = sm;                 // [128][132]
    float* Ks = Qs + FL_QS;         // [64][132]
    float* Vs = Ks + FL_KS;         // [64][136]
    float* Ps = Vs + FL_VS;         // [128][68]

    const int bh = blockIdx.x;
    const int qt = (int)gridDim.y - 1 - blockIdx.y;
    const int m0 = qt * 128;
    const int t    = threadIdx.x;
    const int warp = t >> 5;
    const int lane = t & 31;
    const int g    = lane >> 2;
    const int tig  = lane & 3;
    const int r0   = warp * 16;
    const float scale = 0.08838834764831845f;

    const float* Qg = g_q + ((size_t)bh * SEQ + m0) * HD;
#pragma unroll
    for (int i = 0; i < 16; i++) {
        int lin = t + i * 256;
        int row = lin >> 5, c4 = lin & 31;
        float4 v = *(const float4*)(Qg + (size_t)row * HD + c4 * 4);
        float* dst = Qs + row * 132 + c4 * 4;
        dst[0] = to_tf32(v.x); dst[1] = to_tf32(v.y);
        dst[2] = to_tf32(v.z); dst[3] = to_tf32(v.w);
    }

    float oacc[16][4];
#pragma unroll
    for (int nt = 0; nt < 16; nt++)
#pragma unroll
        for (int r = 0; r < 4; r++) oacc[nt][r] = 0.f;
    float m0r = -INFINITY, m1r = -INFINITY;
    float l0r = 0.f, l1r = 0.f;

    const int gi0 = m0 + r0 + g;
    const int gi1 = gi0 + 8;
    const int ntiles = 2 * (qt + 1);

    for (int kt_i = 0; kt_i < ntiles; kt_i++) {
        int j0 = kt_i * 64;
        __syncthreads();

        const float* Kg = g_k + ((size_t)bh * SEQ + j0) * HD;
        const float* Vg = g_v + ((size_t)bh * SEQ + j0) * HD;
#pragma unroll
        for (int i = 0; i < 8; i++) {
            int lin = t + i * 256;
            int row = lin >> 5, c4 = lin & 31;
            float4 kv = *(const float4*)(Kg + (size_t)row * HD + c4 * 4);
            float* kd = Ks + row * 132 + c4 * 4;
            kd[0] = to_tf32(kv.x); kd[1] = to_tf32(kv.y);
            kd[2] = to_tf32(kv.z); kd[3] = to_tf32(kv.w);
            float4 vv = *(const float4*)(Vg + (size_t)row * HD + c4 * 4);
            float* vd = Vs + row * 136 + c4 * 4;
            vd[0] = to_tf32(vv.x); vd[1] = to_tf32(vv.y);
            vd[2] = to_tf32(vv.z); vd[3] = to_tf32(vv.w);
        }
        __syncthreads();

        float sacc[8][4];
#pragma unroll
        for (int nt = 0; nt < 8; nt++)
#pragma unroll
            for (int r = 0; r < 4; r++) sacc[nt][r] = 0.f;

#pragma unroll
        for (int ks = 0; ks < 16; ks++) {
            int kb = ks * 8;
            uint32_t a[4];
            a[0] = __float_as_uint(Qs[(r0 + g    ) * 132 + kb + tig    ]);
            a[1] = __float_as_uint(Qs[(r0 + g + 8) * 132 + kb + tig    ]);
            a[2] = __float_as_uint(Qs[(r0 + g    ) * 132 + kb + tig + 4]);
            a[3] = __float_as_uint(Qs[(r0 + g + 8) * 132 + kb + tig + 4]);
#pragma unroll
            for (int nt = 0; nt < 8; nt++) {
                uint32_t b[2];
                b[0] = __float_as_uint(Ks[(nt * 8 + g) * 132 + kb + tig    ]);
                b[1] = __float_as_uint(Ks[(nt * 8 + g) * 132 + kb + tig + 4]);
                mma_tf32(sacc[nt], a, b);
            }
        }

        float pm0 = -INFINITY, pm1 = -INFINITY;
#pragma unroll
        for (int nt = 0; nt < 8; nt++) {
            int c = j0 + nt * 8 + tig * 2;
            float s0 = sacc[nt][0] * scale; if (c     > gi0) s0 = -INFINITY;
            float s1 = sacc[nt][1] * scale; if (c + 1 > gi0) s1 = -INFINITY;
            float s2 = sacc[nt][2] * scale; if (c     > gi1) s2 = -INFINITY;
            float s3 = sacc[nt][3] * scale; if (c + 1 > gi1) s3 = -INFINITY;
            sacc[nt][0] = s0; sacc[nt][1] = s1;
            sacc[nt][2] = s2; sacc[nt][3] = s3;
            pm0 = fmaxf(pm0, fmaxf(s0, s1));
            pm1 = fmaxf(pm1, fmaxf(s2, s3));
        }
        pm0 = fmaxf(pm0, __shfl_xor_sync(0xFFFFFFFFu, pm0, 1));
        pm0 = fmaxf(pm0, __shfl_xor_sync(0xFFFFFFFFu, pm0, 2));
        pm1 = fmaxf(pm1, __shfl_xor_sync(0xFFFFFFFFu, pm1, 1));
        pm1 = fmaxf(pm1, __shfl_xor_sync(0xFFFFFFFFu, pm1, 2));

        float mn0 = fmaxf(m0r, pm0);
        float mn1 = fmaxf(m1r, pm1);
        float corr0 = __expf(m0r - mn0);
        float corr1 = __expf(m1r - mn1);

        float ps0 = 0.f, ps1 = 0.f;
#pragma unroll
        for (int nt = 0; nt < 8; nt++) {
            float p0 = __expf(sacc[nt][0] - mn0);
            float p1 = __expf(sacc[nt][1] - mn0);
            float p2 = __expf(sacc[nt][2] - mn1);
            float p3 = __expf(sacc[nt][3] - mn1);
            ps0 += p0 + p1; ps1 += p2 + p3;
            int jc = nt * 8 + tig * 2;
            *(float2*)(Ps + (r0 + g    ) * 68 + jc) =
                make_float2(to_tf32(p0), to_tf32(p1));
            *(float2*)(Ps + (r0 + g + 8) * 68 + jc) =
                make_float2(to_tf32(p2), to_tf32(p3));
        }
        ps0 += __shfl_xor_sync(0xFFFFFFFFu, ps0, 1);
        ps0 += __shfl_xor_sync(0xFFFFFFFFu, ps0, 2);
        ps1 += __shfl_xor_sync(0xFFFFFFFFu, ps1, 1);
        ps1 += __shfl_xor_sync(0xFFFFFFFFu, ps1, 2);

        l0r = l0r * corr0 + ps0;
        l1r = l1r * corr1 + ps1;
        m0r = mn0; m1r = mn1;

#pragma unroll
        for (int nt = 0; nt < 16; nt++) {
            oacc[nt][0] *= corr0; oacc[nt][1] *= corr0;
            oacc[nt][2] *= corr1; oacc[nt][3] *= corr1;
        }
        __syncwarp();

#pragma unroll
        for (int ks = 0; ks < 8; ks++) {
            int kb = ks * 8;
            uint32_t a[4];
            a[0] = __float_as_uint(Ps[(r0 + g    ) * 68 + kb + tig    ]);
            a[1] = __float_as_uint(Ps[(r0 + g + 8) * 68 + kb + tig    ]);
            a[2] = __float_as_uint(Ps[(r0 + g    ) * 68 + kb + tig + 4]);
            a[3] = __float_as_uint(Ps[(r0 + g + 8) * 68 + kb + tig + 4]);
#pragma unroll
            for (int nt = 0; nt < 16; nt++) {
                uint32_t b[2];
                b[0] = __float_as_uint(Vs[(kb + tig    ) * 136 + nt * 8 + g]);
                b[1] = __float_as_uint(Vs[(kb + tig + 4) * 136 + nt * 8 + g]);
                mma_tf32(oacc[nt], a, b);
            }
        }
    }

    // ---- normalize + write fp16 into g_att_h [B][S][H] ----
    float inv0 = 1.f / l0r, inv1 = 1.f / l1r;
    int b = bh >> 4, h = bh & 15;
    int row0 = m0 + r0 + g;
    __half* O0 = g_att_h + ((size_t)b * SEQ + row0    ) * HID + h * HD;
    __half* O1 = g_att_h + ((size_t)b * SEQ + row0 + 8) * HID + h * HD;
#pragma unroll
    for (int nt = 0; nt < 16; nt++) {
        int d = nt * 8 + tig * 2;
        *(__half2*)(O0 + d) =
            __floats2half2_rn(oacc[nt][0] * inv0, oacc[nt][1] * inv0);
        *(__half2*)(O1 + d) =
            __floats2half2_rn(oacc[nt][2] * inv1, oacc[nt][3] * inv1);
    }
}

// ---------------------------------------------------------------------------
extern "C" void kernel_launch(void* const* d_in, const int* in_sizes, int n_in,
                              void* d_out, int out_size)
{
    const float* x     = (const float*)d_in[0];
    const float* qkv_w = (const float*)d_in[1];
    const float* o_w   = (const float*)d_in[2];
    const float* cosb  = (const float*)d_in[3];
    const float* sinb  = (const float*)d_in[4];
    float* out = (float*)d_out;

    cudaFuncSetAttribute(h_gemm<0>,
        cudaFuncAttributeMaxDynamicSharedMemorySize, HGEMM_SMEM_BYTES);
    cudaFuncSetAttribute(h_gemm<1>,
        cudaFuncAttributeMaxDynamicSharedMemorySize, HGEMM_SMEM_BYTES);

    // 0) fp32 -> fp16 (rn) conversions of GEMM inputs
    f2h_kernel<0><<<(MROWS * HID) / 1024, 256>>>(x);
    f2h_kernel<1><<<(3 * HID * HID) / 1024, 256>>>(qkv_w);
    f2h_kernel<2><<<(HID * HID) / 1024, 256>>>(o_w);

    // 1) QKV projection: grid (48, 16)
    h_gemm<0><<<dim3(6144 / 128, MROWS / 256), 256, HGEMM_SMEM_BYTES>>>(nullptr);

    // 2) rotary
    rotary_kernel<<<(NBATCH * NHEADS * SEQ * 64) / 256, 256>>>(cosb, sinb);

    // 3) flash attention (tf32 MMA), 171 KB smem; writes g_att_h (fp16)
    {
        const size_t smem = FLASH2_SMEM_FLOATS * sizeof(float);
        cudaFuncSetAttribute(flash_mma_kernel,
                             cudaFuncAttributeMaxDynamicSharedMemorySize,
                             (int)smem);
        flash_mma_kernel<<<dim3(NBATCH * NHEADS, SEQ / 128), 256, smem>>>();
    }

    // 4) output projection: grid (16, 16)
    h_gemm<1><<<dim3(HID / 128, MROWS / 256), 256, HGEMM_SMEM_BYTES>>>(out);
}

// round 14
// speedup vs baseline: 6.4353x; 1.1647x over previous
#include <cuda_runtime.h>
#include <cuda_fp16.h>
#include <math.h>
#include <stdint.h>

// Problem constants (fixed by the reference)
#define NBATCH 2
#define SEQ    2048
#define HID    2048
#define NHEADS 16
#define HD     128
#define MROWS  (NBATCH*SEQ)   // 4096

// ---------------------------------------------------------------------------
// Device scratch (allocation-free rule: __device__ globals)
// ---------------------------------------------------------------------------
__device__ float  g_q[(size_t)NBATCH*NHEADS*SEQ*HD];    // 32 MB [B][NH][S][D]
__device__ float  g_k[(size_t)NBATCH*NHEADS*SEQ*HD];    // 32 MB
__device__ float  g_v[(size_t)NBATCH*NHEADS*SEQ*HD];    // 32 MB
__device__ __half g_xh[(size_t)MROWS*HID];              // 16 MB fp16 x
__device__ __half g_wh[(size_t)4*HID*HID];              // 32 MB fp16 qkv_w|o_w
__device__ __half g_att_h[(size_t)MROWS*HID];           // 16 MB fp16 attn out

// ---------------------------------------------------------------------------
// tf32 helpers (flash kernel)
// ---------------------------------------------------------------------------
__device__ __forceinline__ float to_tf32(float x) {
    uint32_t u;
    asm("cvt.rna.tf32.f32 %0, %1;" : "=r"(u) : "f"(x));
    return __uint_as_float(u);
}

__device__ __forceinline__ void mma_tf32(float* c, const uint32_t* a,
                                         const uint32_t* b) {
    asm volatile(
        "mma.sync.aligned.m16n8k8.row.col.f32.tf32.tf32.f32 "
        "{%0,%1,%2,%3}, {%4,%5,%6,%7}, {%8,%9}, {%0,%1,%2,%3};"
        : "+f"(c[0]), "+f"(c[1]), "+f"(c[2]), "+f"(c[3])
        : "r"(a[0]), "r"(a[1]), "r"(a[2]), "r"(a[3]),
          "r"(b[0]), "r"(b[1]));
}

// fp16 MMA: D(f32) += A(f16) * B(f16),  m16n8k16
__device__ __forceinline__ void mma_f16(float* c, const uint32_t* a,
                                        const uint32_t* b) {
    asm volatile(
        "mma.sync.aligned.m16n8k16.row.col.f32.f16.f16.f32 "
        "{%0,%1,%2,%3}, {%4,%5,%6,%7}, {%8,%9}, {%0,%1,%2,%3};"
        : "+f"(c[0]), "+f"(c[1]), "+f"(c[2]), "+f"(c[3])
        : "r"(a[0]), "r"(a[1]), "r"(a[2]), "r"(a[3]),
          "r"(b[0]), "r"(b[1]));
}

__device__ __forceinline__ void ldsm_x4(uint32_t* r, uint32_t saddr) {
    asm volatile(
        "ldmatrix.sync.aligned.m8n8.x4.shared.b16 {%0,%1,%2,%3}, [%4];"
        : "=r"(r[0]), "=r"(r[1]), "=r"(r[2]), "=r"(r[3]) : "r"(saddr));
}

__device__ __forceinline__ void cp16(uint32_t smem_dst, const void* gsrc) {
    asm volatile("cp.async.cg.shared.global [%0], [%1], 16;"
                 :: "r"(smem_dst), "l"(gsrc));
}
__device__ __forceinline__ void cp_commit() {
    asm volatile("cp.async.commit_group;");
}
__device__ __forceinline__ void cp_wait1() {
    asm volatile("cp.async.wait_group 1;" ::: "memory");
}

// ---------------------------------------------------------------------------
// fp32 -> fp16 (rn) conversion pre-passes. WHICH: 0=x, 1=qkv_w, 2=o_w
// ---------------------------------------------------------------------------
template<int WHICH>
__global__ __launch_bounds__(256)
void f2h_kernel(const float* __restrict__ src)
{
    __half* dst = (WHICH == 0) ? g_xh
                : (WHICH == 1) ? g_wh
                : g_wh + (size_t)3 * HID * HID;
    size_t i = ((size_t)blockIdx.x * 256 + threadIdx.x) * 4;
    float4 v = *(const float4*)(src + i);
    __half2 h0 = __floats2half2_rn(v.x, v.y);
    __half2 h1 = __floats2half2_rn(v.z, v.w);
    uint2 u;
    u.x = *(uint32_t*)&h0;
    u.y = *(uint32_t*)&h1;
    *(uint2*)(dst + i) = u;
}

// ---------------------------------------------------------------------------
// fp16 tensor-core GEMM  C[m][n] = sum_k A[m][k] * W[n][k]  (f32 accumulate)
// Block tile 128(M) x 128(N), BK=64, 256 threads = 8 warps (4x2),
// warp tile 32x64.  TWO CTAs per SM (launch_bounds(256,2)) so one CTA's
// barrier/prefetch phase overlaps the other's MMA phase.
// smem [row][72 halves] (144B stride = 9 x 16B units -> ldmatrix
// conflict-free: r*9 mod 8 = r mod 8). 2-stage cp.async double buffer.
// MODE 0: A = g_xh, W = g_wh(qkv), scatter into g_q/g_k/g_v ([B][NH][S][D])
// MODE 1: A = g_att_h, W = g_wh+3H^2 (o_w), C = d_out
// ---------------------------------------------------------------------------
#define HS_STRIDE 72                       // halves per row (144 B)
#define HS_ABUF   (128 * HS_STRIDE)        // 9216 halves
#define HS_BUF    (2 * HS_ABUF)            // 18432 halves / stage (A+B)
#define HGEMM_SMEM_BYTES (2 * HS_BUF * 2)  // 73728 B

template<int MODE>
__global__ __launch_bounds__(256, 2)
void h_gemm(float* __restrict__ Cout)
{
    extern __shared__ __align__(16) __half hsm[];
    const uint32_t sbase = (uint32_t)__cvta_generic_to_shared(hsm);

    const __half* A = (MODE == 0) ? g_xh : g_att_h;
    const __half* W = (MODE == 0) ? g_wh : g_wh + (size_t)3 * HID * HID;
    const int K = HID;

    const int tid  = threadIdx.x;
    const int warp = tid >> 5;
    const int lane = tid & 31;
    const int g    = lane >> 2;
    const int tig  = lane & 3;
    const int wm   = (warp >> 1) * 32;      // 0,32,64,96
    const int wn   = (warp & 1)  * 64;      // 0,64
    const int m0   = blockIdx.y * 128;
    const int n0   = blockIdx.x * 128;

    const __half* Ab = A + (size_t)m0 * K;
    const __half* Wb = W + (size_t)n0 * K;

    // ldmatrix lane -> smem coordinates
    const int lrA = lane & 15;              // A: row within 16-row tile
    const int lcA = (lane >> 4) * 8;        // A: k offset (0 or 8)
    const int lrB = (lane >> 4) * 8 + (lane & 7);   // B: n offset within pair
    const int lcB = ((lane >> 3) & 1) * 8;          // B: k offset (0 or 8)

    float acc[2][8][4];
#pragma unroll
    for (int mt = 0; mt < 2; mt++)
#pragma unroll
        for (int nt = 0; nt < 8; nt++)
#pragma unroll
            for (int r = 0; r < 4; r++) acc[mt][nt][r] = 0.f;

    const int niter = K / 64;               // 32

    auto prefetch = [&](int kt, int buf) {
        const uint32_t b0 = sbase + (uint32_t)(buf * HS_BUF) * 2u;
#pragma unroll
        for (int j = 0; j < 4; j++) {        // A: 128 rows x 8 chunks (16B)
            int id = tid + j * 256;          // 0..1023
            int row = id >> 3, c = id & 7;
            cp16(b0 + (uint32_t)(row * HS_STRIDE + c * 8) * 2u,
                 Ab + (size_t)row * K + kt * 64 + c * 8);
        }
#pragma unroll
        for (int j = 0; j < 4; j++) {        // B: 128 rows x 8 chunks
            int id = tid + j * 256;
            int row = id >> 3, c = id & 7;
            cp16(b0 + (uint32_t)(HS_ABUF + row * HS_STRIDE + c * 8) * 2u,
                 Wb + (size_t)row * K + kt * 64 + c * 8);
        }
    };

    prefetch(0, 0); cp_commit();
    prefetch(1, 1); cp_commit();

    for (int kt = 0; kt < niter; kt++) {
        const int p = kt & 1;
        cp_wait1();
        __syncthreads();

        const uint32_t asb = sbase + (uint32_t)(p * HS_BUF) * 2u;
        const uint32_t bsb = asb + (uint32_t)HS_ABUF * 2u;

#pragma unroll
        for (int ks = 0; ks < 4; ks++) {
            const int kb = ks * 16;
            uint32_t af[2][4];
#pragma unroll
            for (int mt = 0; mt < 2; mt++) {
                uint32_t addr = asb +
                    (uint32_t)((wm + mt * 16 + lrA) * HS_STRIDE + kb + lcA) * 2u;
                ldsm_x4(af[mt], addr);
            }
            uint32_t bf[8][2];
#pragma unroll
            for (int nt2 = 0; nt2 < 4; nt2++) {
                uint32_t r[4];
                uint32_t addr = bsb +
                    (uint32_t)((wn + nt2 * 16 + lrB) * HS_STRIDE + kb + lcB) * 2u;
                ldsm_x4(r, addr);
                bf[nt2 * 2][0]     = r[0];
                bf[nt2 * 2][1]     = r[1];
                bf[nt2 * 2 + 1][0] = r[2];
                bf[nt2 * 2 + 1][1] = r[3];
            }
#pragma unroll
            for (int mt = 0; mt < 2; mt++)
#pragma unroll
                for (int nt = 0; nt < 8; nt++)
                    mma_f16(acc[mt][nt], af[mt], bf[nt]);
        }
        __syncthreads();
        if (kt + 2 < niter) prefetch(kt + 2, p);
        cp_commit();                         // always-commit keeps wait exact
    }

    // ---- epilogue (N tile = exactly one head in MODE 0) ----
#pragma unroll
    for (int mt = 0; mt < 2; mt++) {
        int m = m0 + wm + mt * 16 + g;
        int b = m >> 11;
        int s = m & 2047;
#pragma unroll
        for (int nt = 0; nt < 8; nt++) {
            int n = n0 + wn + nt * 8 + tig * 2;
            if (MODE == 0) {
                int which = n >> 11;            // 0=q 1=k 2=v
                int hn    = (n & 2047) >> 7;    // head
                int d     = n & 127;
                float* dst = (which == 0) ? g_q : (which == 1) ? g_k : g_v;
                size_t idx = ((((size_t)b * NHEADS + hn) * SEQ + s) << 7) + d;
                *(float2*)(dst + idx) =
                    make_float2(acc[mt][nt][0], acc[mt][nt][1]);
                *(float2*)(dst + idx + (8u << 7)) =
                    make_float2(acc[mt][nt][2], acc[mt][nt][3]);
            } else {
                *(float2*)(Cout + (size_t)m * HID + n) =
                    make_float2(acc[mt][nt][0], acc[mt][nt][1]);
                *(float2*)(Cout + (size_t)(m + 8) * HID + n) =
                    make_float2(acc[mt][nt][2], acc[mt][nt][3]);
            }
        }
    }
}

// ---------------------------------------------------------------------------
// Rotary on q and k in place.
// ---------------------------------------------------------------------------
__global__ __launch_bounds__(256)
void rotary_kernel(const float* __restrict__ cosb,
                   const float* __restrict__ sinb)
{
    int idx = blockIdx.x * blockDim.x + threadIdx.x;
    int d  = idx & 63;
    int s  = (idx >> 6) & 2047;
    int bh = idx >> 17;
    size_t base = (((size_t)bh * SEQ + s) << 7);
    float c  = __ldg(cosb + s * 64 + d);
    float sn = __ldg(sinb + s * 64 + d);

    float q1 = g_q[base + d], q2 = g_q[base + d + 64];
    g_q[base + d]      = q1 * c - q2 * sn;
    g_q[base + d + 64] = q2 * c + q1 * sn;

    float k1 = g_k[base + d], k2 = g_k[base + d + 64];
    g_k[base + d]      = k1 * c - k2 * sn;
    g_k[base + d + 64] = k2 * c + k1 * sn;
}

// ---------------------------------------------------------------------------
// Flash attention with legacy tf32 MMA (unchanged math; writes fp16 g_att_h).
// ---------------------------------------------------------------------------
#define FL_QS   (128*132)
#define FL_KS   (64*132)
#define FL_VS   (64*136)
#define FL_PS   (128*68)
#define FLASH2_SMEM_FLOATS (FL_QS + FL_KS + FL_VS + FL_PS)   // 171 KB

__global__ __launch_bounds__(256, 1)
void flash_mma_kernel()
{
    extern __shared__ __align__(16) float sm[];
    float* Qs = sm;                 // [128][132]
    float* Ks = Qs + FL_QS;         // [64][132]
    float* Vs = Ks + FL_KS;         // [64][136]
    float* Ps = Vs + FL_VS;         // [128][68]

    const int bh = blockIdx.x;
    const int qt = (int)gridDim.y - 1 - blockIdx.y;
    const int m0 = qt * 128;
    const int t    = threadIdx.x;
    const int warp = t >> 5;
    const int lane = t & 31;
    const int g    = lane >> 2;
    const int tig  = lane & 3;
    const int r0   = warp * 16;
    const float scale = 0.08838834764831845f;

    const float* Qg = g_q + ((size_t)bh * SEQ + m0) * HD;
#pragma unroll
    for (int i = 0; i < 16; i++) {
        int lin = t + i * 256;
        int row = lin >> 5, c4 = lin & 31;
        float4 v = *(const float4*)(Qg + (size_t)row * HD + c4 * 4);
        float* dst = Qs + row * 132 + c4 * 4;
        dst[0] = to_tf32(v.x); dst[1] = to_tf32(v.y);
        dst[2] = to_tf32(v.z); dst[3] = to_tf32(v.w);
    }

    float oacc[16][4];
#pragma unroll
    for (int nt = 0; nt < 16; nt++)
#pragma unroll
        for (int r = 0; r < 4; r++) oacc[nt][r] = 0.f;
    float m0r = -INFINITY, m1r = -INFINITY;
    float l0r = 0.f, l1r = 0.f;

    const int gi0 = m0 + r0 + g;
    const int gi1 = gi0 + 8;
    const int ntiles = 2 * (qt + 1);

    for (int kt_i = 0; kt_i < ntiles; kt_i++) {
        int j0 = kt_i * 64;
        __syncthreads();

        const float* Kg = g_k + ((size_t)bh * SEQ + j0) * HD;
        const float* Vg = g_v + ((size_t)bh * SEQ + j0) * HD;
#pragma unroll
        for (int i = 0; i < 8; i++) {
            int lin = t + i * 256;
            int row = lin >> 5, c4 = lin & 31;
            float4 kv = *(const float4*)(Kg + (size_t)row * HD + c4 * 4);
            float* kd = Ks + row * 132 + c4 * 4;
            kd[0] = to_tf32(kv.x); kd[1] = to_tf32(kv.y);
            kd[2] = to_tf32(kv.z); kd[3] = to_tf32(kv.w);
            float4 vv = *(const float4*)(Vg + (size_t)row * HD + c4 * 4);
            float* vd = Vs + row * 136 + c4 * 4;
            vd[0] = to_tf32(vv.x); vd[1] = to_tf32(vv.y);
            vd[2] = to_tf32(vv.z); vd[3] = to_tf32(vv.w);
        }
        __syncthreads();

        float sacc[8][4];
#pragma unroll
        for (int nt = 0; nt < 8; nt++)
#pragma unroll
            for (int r = 0; r < 4; r++) sacc[nt][r] = 0.f;

#pragma unroll
        for (int ks = 0; ks < 16; ks++) {
            int kb = ks * 8;
            uint32_t a[4];
            a[0] = __float_as_uint(Qs[(r0 + g    ) * 132 + kb + tig    ]);
            a[1] = __float_as_uint(Qs[(r0 + g + 8) * 132 + kb + tig    ]);
            a[2] = __float_as_uint(Qs[(r0 + g    ) * 132 + kb + tig + 4]);
            a[3] = __float_as_uint(Qs[(r0 + g + 8) * 132 + kb + tig + 4]);
#pragma unroll
            for (int nt = 0; nt < 8; nt++) {
                uint32_t b[2];
                b[0] = __float_as_uint(Ks[(nt * 8 + g) * 132 + kb + tig    ]);
                b[1] = __float_as_uint(Ks[(nt * 8 + g) * 132 + kb + tig + 4]);
                mma_tf32(sacc[nt], a, b);
            }
        }

        float pm0 = -INFINITY, pm1 = -INFINITY;
#pragma unroll
        for (int nt = 0; nt < 8; nt++) {
            int c = j0 + nt * 8 + tig * 2;
            float s0 = sacc[nt][0] * scale; if (c     > gi0) s0 = -INFINITY;
            float s1 = sacc[nt][1] * scale; if (c + 1 > gi0) s1 = -INFINITY;
            float s2 = sacc[nt][2] * scale; if (c     > gi1) s2 = -INFINITY;
            float s3 = sacc[nt][3] * scale; if (c + 1 > gi1) s3 = -INFINITY;
            sacc[nt][0] = s0; sacc[nt][1] = s1;
            sacc[nt][2] = s2; sacc[nt][3] = s3;
            pm0 = fmaxf(pm0, fmaxf(s0, s1));
            pm1 = fmaxf(pm1, fmaxf(s2, s3));
        }
        pm0 = fmaxf(pm0, __shfl_xor_sync(0xFFFFFFFFu, pm0, 1));
        pm0 = fmaxf(pm0, __shfl_xor_sync(0xFFFFFFFFu, pm0, 2));
        pm1 = fmaxf(pm1, __shfl_xor_sync(0xFFFFFFFFu, pm1, 1));
        pm1 = fmaxf(pm1, __shfl_xor_sync(0xFFFFFFFFu, pm1, 2));

        float mn0 = fmaxf(m0r, pm0);
        float mn1 = fmaxf(m1r, pm1);
        float corr0 = __expf(m0r - mn0);
        float corr1 = __expf(m1r - mn1);

        float ps0 = 0.f, ps1 = 0.f;
#pragma unroll
        for (int nt = 0; nt < 8; nt++) {
            float p0 = __expf(sacc[nt][0] - mn0);
            float p1 = __expf(sacc[nt][1] - mn0);
            float p2 = __expf(sacc[nt][2] - mn1);
            float p3 = __expf(sacc[nt][3] - mn1);
            ps0 += p0 + p1; ps1 += p2 + p3;
            int jc = nt * 8 + tig * 2;
            *(float2*)(Ps + (r0 + g    ) * 68 + jc) =
                make_float2(to_tf32(p0), to_tf32(p1));
            *(float2*)(Ps + (r0 + g + 8) * 68 + jc) =
                make_float2(to_tf32(p2), to_tf32(p3));
        }
        ps0 += __shfl_xor_sync(0xFFFFFFFFu, ps0, 1);
        ps0 += __shfl_xor_sync(0xFFFFFFFFu, ps0, 2);
        ps1 += __shfl_xor_sync(0xFFFFFFFFu, ps1, 1);
        ps1 += __shfl_xor_sync(0xFFFFFFFFu, ps1, 2);

        l0r = l0r * corr0 + ps0;
        l1r = l1r * corr1 + ps1;
        m0r = mn0; m1r = mn1;

#pragma unroll
        for (int nt = 0; nt < 16; nt++) {
            oacc[nt][0] *= corr0; oacc[nt][1] *= corr0;
            oacc[nt][2] *= corr1; oacc[nt][3] *= corr1;
        }
        __syncwarp();

#pragma unroll
        for (int ks = 0; ks < 8; ks++) {
            int kb = ks * 8;
            uint32_t a[4];
            a[0] = __float_as_uint(Ps[(r0 + g    ) * 68 + kb + tig    ]);
            a[1] = __float_as_uint(Ps[(r0 + g + 8) * 68 + kb + tig    ]);
            a[2] = __float_as_uint(Ps[(r0 + g    ) * 68 + kb + tig + 4]);
            a[3] = __float_as_uint(Ps[(r0 + g + 8) * 68 + kb + tig + 4]);
#pragma unroll
            for (int nt = 0; nt < 16; nt++) {
                uint32_t b[2];
                b[0] = __float_as_uint(Vs[(kb + tig    ) * 136 + nt * 8 + g]);
                b[1] = __float_as_uint(Vs[(kb + tig + 4) * 136 + nt * 8 + g]);
                mma_tf32(oacc[nt], a, b);
            }
        }
    }

    // ---- normalize + write fp16 into g_att_h [B][S][H] ----
    float inv0 = 1.f / l0r, inv1 = 1.f / l1r;
    int b = bh >> 4, h = bh & 15;
    int row0 = m0 + r0 + g;
    __half* O0 = g_att_h + ((size_t)b * SEQ + row0    ) * HID + h * HD;
    __half* O1 = g_att_h + ((size_t)b * SEQ + row0 + 8) * HID + h * HD;
#pragma unroll
    for (int nt = 0; nt < 16; nt++) {
        int d = nt * 8 + tig * 2;
        *(__half2*)(O0 + d) =
            __floats2half2_rn(oacc[nt][0] * inv0, oacc[nt][1] * inv0);
        *(__half2*)(O1 + d) =
            __floats2half2_rn(oacc[nt][2] * inv1, oacc[nt][3] * inv1);
    }
}

// ---------------------------------------------------------------------------
extern "C" void kernel_launch(void* const* d_in, const int* in_sizes, int n_in,
                              void* d_out, int out_size)
{
    const float* x     = (const float*)d_in[0];
    const float* qkv_w = (const float*)d_in[1];
    const float* o_w   = (const float*)d_in[2];
    const float* cosb  = (const float*)d_in[3];
    const float* sinb  = (const float*)d_in[4];
    float* out = (float*)d_out;

    cudaFuncSetAttribute(h_gemm<0>,
        cudaFuncAttributeMaxDynamicSharedMemorySize, HGEMM_SMEM_BYTES);
    cudaFuncSetAttribute(h_gemm<1>,
        cudaFuncAttributeMaxDynamicSharedMemorySize, HGEMM_SMEM_BYTES);

    // 0) fp32 -> fp16 (rn) conversions of GEMM inputs
    f2h_kernel<0><<<(MROWS * HID) / 1024, 256>>>(x);
    f2h_kernel<1><<<(3 * HID * HID) / 1024, 256>>>(qkv_w);
    f2h_kernel<2><<<(HID * HID) / 1024, 256>>>(o_w);

    // 1) QKV projection: grid (48, 32), 128x128 tiles
    h_gemm<0><<<dim3(6144 / 128, MROWS / 128), 256, HGEMM_SMEM_BYTES>>>(nullptr);

    // 2) rotary
    rotary_kernel<<<(NBATCH * NHEADS * SEQ * 64) / 256, 256>>>(cosb, sinb);

    // 3) flash attention (tf32 MMA), 171 KB smem; writes g_att_h (fp16)
    {
        const size_t smem = FLASH2_SMEM_FLOATS * sizeof(float);
        cudaFuncSetAttribute(flash_mma_kernel,
                             cudaFuncAttributeMaxDynamicSharedMemorySize,
                             (int)smem);
        flash_mma_kernel<<<dim3(NBATCH * NHEADS, SEQ / 128), 256, smem>>>();
    }

    // 4) output projection: grid (16, 32)
    h_gemm<1><<<dim3(HID / 128, MROWS / 128), 256, HGEMM_SMEM_BYTES>>>(out);
}

// round 15
// speedup vs baseline: 8.0005x; 1.2432x over previous
#include <cuda_runtime.h>
#include <cuda_fp16.h>
#include <math.h>
#include <stdint.h>

// Problem constants (fixed by the reference)
#define NBATCH 2
#define SEQ    2048
#define HID    2048
#define NHEADS 16
#define HD     128
#define MROWS  (NBATCH*SEQ)   // 4096

// ---------------------------------------------------------------------------
// Device scratch (allocation-free rule: __device__ globals)
// ---------------------------------------------------------------------------
__device__ __half g_qh[(size_t)NBATCH*NHEADS*SEQ*HD];   // 16 MB [B][NH][S][D]
__device__ __half g_kh[(size_t)NBATCH*NHEADS*SEQ*HD];   // 16 MB
__device__ __half g_vh[(size_t)NBATCH*NHEADS*SEQ*HD];   // 16 MB
__device__ __half g_xh[(size_t)MROWS*HID];              // 16 MB fp16 x
__device__ __half g_wh[(size_t)4*HID*HID];              // 32 MB fp16 qkv_w|o_w
__device__ __half g_att_h[(size_t)MROWS*HID];           // 16 MB fp16 attn out

// ---------------------------------------------------------------------------
// MMA / ldmatrix / cp.async helpers
// ---------------------------------------------------------------------------
// fp16 MMA: D(f32) += A(f16) * B(f16),  m16n8k16
__device__ __forceinline__ void mma_f16(float* c, const uint32_t* a,
                                        const uint32_t* b) {
    asm volatile(
        "mma.sync.aligned.m16n8k16.row.col.f32.f16.f16.f32 "
        "{%0,%1,%2,%3}, {%4,%5,%6,%7}, {%8,%9}, {%0,%1,%2,%3};"
        : "+f"(c[0]), "+f"(c[1]), "+f"(c[2]), "+f"(c[3])
        : "r"(a[0]), "r"(a[1]), "r"(a[2]), "r"(a[3]),
          "r"(b[0]), "r"(b[1]));
}

__device__ __forceinline__ void ldsm_x4(uint32_t* r, uint32_t saddr) {
    asm volatile(
        "ldmatrix.sync.aligned.m8n8.x4.shared.b16 {%0,%1,%2,%3}, [%4];"
        : "=r"(r[0]), "=r"(r[1]), "=r"(r[2]), "=r"(r[3]) : "r"(saddr));
}
__device__ __forceinline__ void ldsm_x4_t(uint32_t* r, uint32_t saddr) {
    asm volatile(
        "ldmatrix.sync.aligned.m8n8.x4.trans.shared.b16 {%0,%1,%2,%3}, [%4];"
        : "=r"(r[0]), "=r"(r[1]), "=r"(r[2]), "=r"(r[3]) : "r"(saddr));
}

__device__ __forceinline__ void cp16(uint32_t smem_dst, const void* gsrc) {
    asm volatile("cp.async.cg.shared.global [%0], [%1], 16;"
                 :: "r"(smem_dst), "l"(gsrc));
}
__device__ __forceinline__ void cp_commit() {
    asm volatile("cp.async.commit_group;");
}
__device__ __forceinline__ void cp_wait1() {
    asm volatile("cp.async.wait_group 1;" ::: "memory");
}

// ---------------------------------------------------------------------------
// fp32 -> fp16 (rn) conversion pre-passes. WHICH: 0=x, 1=qkv_w, 2=o_w
// ---------------------------------------------------------------------------
template<int WHICH>
__global__ __launch_bounds__(256)
void f2h_kernel(const float* __restrict__ src)
{
    __half* dst = (WHICH == 0) ? g_xh
                : (WHICH == 1) ? g_wh
                : g_wh + (size_t)3 * HID * HID;
    size_t i = ((size_t)blockIdx.x * 256 + threadIdx.x) * 4;
    float4 v = *(const float4*)(src + i);
    __half2 h0 = __floats2half2_rn(v.x, v.y);
    __half2 h1 = __floats2half2_rn(v.z, v.w);
    uint2 u;
    u.x = *(uint32_t*)&h0;
    u.y = *(uint32_t*)&h1;
    *(uint2*)(dst + i) = u;
}

// ---------------------------------------------------------------------------
// fp16 tensor-core GEMM  C[m][n] = sum_k A[m][k] * W[n][k]  (f32 accumulate)
// Block tile 128x128, BK=64, 256 threads, 2 CTAs/SM. (See R14 — proven.)
// MODE 0: A = g_xh, W = g_wh(qkv), scatter fp16 into g_qh/g_kh/g_vh
// MODE 1: A = g_att_h, W = g_wh+3H^2 (o_w), C = d_out (fp32)
// ---------------------------------------------------------------------------
#define HS_STRIDE 72                       // halves per row (144 B)
#define HS_ABUF   (128 * HS_STRIDE)        // 9216 halves
#define HS_BUF    (2 * HS_ABUF)            // 18432 halves / stage (A+B)
#define HGEMM_SMEM_BYTES (2 * HS_BUF * 2)  // 73728 B

template<int MODE>
__global__ __launch_bounds__(256, 2)
void h_gemm(float* __restrict__ Cout)
{
    extern __shared__ __align__(16) __half hsm[];
    const uint32_t sbase = (uint32_t)__cvta_generic_to_shared(hsm);

    const __half* A = (MODE == 0) ? g_xh : g_att_h;
    const __half* W = (MODE == 0) ? g_wh : g_wh + (size_t)3 * HID * HID;
    const int K = HID;

    const int tid  = threadIdx.x;
    const int warp = tid >> 5;
    const int lane = tid & 31;
    const int g    = lane >> 2;
    const int tig  = lane & 3;
    const int wm   = (warp >> 1) * 32;      // 0,32,64,96
    const int wn   = (warp & 1)  * 64;      // 0,64
    const int m0   = blockIdx.y * 128;
    const int n0   = blockIdx.x * 128;

    const __half* Ab = A + (size_t)m0 * K;
    const __half* Wb = W + (size_t)n0 * K;

    const int lrA = lane & 15;
    const int lcA = (lane >> 4) * 8;
    const int lrB = (lane >> 4) * 8 + (lane & 7);
    const int lcB = ((lane >> 3) & 1) * 8;

    float acc[2][8][4];
#pragma unroll
    for (int mt = 0; mt < 2; mt++)
#pragma unroll
        for (int nt = 0; nt < 8; nt++)
#pragma unroll
            for (int r = 0; r < 4; r++) acc[mt][nt][r] = 0.f;

    const int niter = K / 64;               // 32

    auto prefetch = [&](int kt, int buf) {
        const uint32_t b0 = sbase + (uint32_t)(buf * HS_BUF) * 2u;
#pragma unroll
        for (int j = 0; j < 4; j++) {
            int id = tid + j * 256;
            int row = id >> 3, c = id & 7;
            cp16(b0 + (uint32_t)(row * HS_STRIDE + c * 8) * 2u,
                 Ab + (size_t)row * K + kt * 64 + c * 8);
        }
#pragma unroll
        for (int j = 0; j < 4; j++) {
            int id = tid + j * 256;
            int row = id >> 3, c = id & 7;
            cp16(b0 + (uint32_t)(HS_ABUF + row * HS_STRIDE + c * 8) * 2u,
                 Wb + (size_t)row * K + kt * 64 + c * 8);
        }
    };

    prefetch(0, 0); cp_commit();
    prefetch(1, 1); cp_commit();

    for (int kt = 0; kt < niter; kt++) {
        const int p = kt & 1;
        cp_wait1();
        __syncthreads();

        const uint32_t asb = sbase + (uint32_t)(p * HS_BUF) * 2u;
        const uint32_t bsb = asb + (uint32_t)HS_ABUF * 2u;

#pragma unroll
        for (int ks = 0; ks < 4; ks++) {
            const int kb = ks * 16;
            uint32_t af[2][4];
#pragma unroll
            for (int mt = 0; mt < 2; mt++) {
                uint32_t addr = asb +
                    (uint32_t)((wm + mt * 16 + lrA) * HS_STRIDE + kb + lcA) * 2u;
                ldsm_x4(af[mt], addr);
            }
            uint32_t bf[8][2];
#pragma unroll
            for (int nt2 = 0; nt2 < 4; nt2++) {
                uint32_t r[4];
                uint32_t addr = bsb +
                    (uint32_t)((wn + nt2 * 16 + lrB) * HS_STRIDE + kb + lcB) * 2u;
                ldsm_x4(r, addr);
                bf[nt2 * 2][0]     = r[0];
                bf[nt2 * 2][1]     = r[1];
                bf[nt2 * 2 + 1][0] = r[2];
                bf[nt2 * 2 + 1][1] = r[3];
            }
#pragma unroll
            for (int mt = 0; mt < 2; mt++)
#pragma unroll
                for (int nt = 0; nt < 8; nt++)
                    mma_f16(acc[mt][nt], af[mt], bf[nt]);
        }
        __syncthreads();
        if (kt + 2 < niter) prefetch(kt + 2, p);
        cp_commit();
    }

    // ---- epilogue ----
#pragma unroll
    for (int mt = 0; mt < 2; mt++) {
        int m = m0 + wm + mt * 16 + g;
        int b = m >> 11;
        int s = m & 2047;
#pragma unroll
        for (int nt = 0; nt < 8; nt++) {
            int n = n0 + wn + nt * 8 + tig * 2;
            if (MODE == 0) {
                int which = n >> 11;            // 0=q 1=k 2=v
                int hn    = (n & 2047) >> 7;    // head
                int d     = n & 127;
                __half* dst = (which == 0) ? g_qh : (which == 1) ? g_kh : g_vh;
                size_t idx = ((((size_t)b * NHEADS + hn) * SEQ + s) << 7) + d;
                *(__half2*)(dst + idx) =
                    __floats2half2_rn(acc[mt][nt][0], acc[mt][nt][1]);
                *(__half2*)(dst + idx + (8u << 7)) =
                    __floats2half2_rn(acc[mt][nt][2], acc[mt][nt][3]);
            } else {
                *(float2*)(Cout + (size_t)m * HID + n) =
                    make_float2(acc[mt][nt][0], acc[mt][nt][1]);
                *(float2*)(Cout + (size_t)(m + 8) * HID + n) =
                    make_float2(acc[mt][nt][2], acc[mt][nt][3]);
            }
        }
    }
}

// ---------------------------------------------------------------------------
// Rotary on fp16 q and k in place (fp32 math). Thread = 2 consecutive dims.
// ---------------------------------------------------------------------------
__global__ __launch_bounds__(256)
void rotary_h_kernel(const float* __restrict__ cosb,
                     const float* __restrict__ sinb)
{
    int idx = blockIdx.x * blockDim.x + threadIdx.x;  // 2^21 threads
    int d2 = (idx & 31) * 2;                          // 0,2,..,62
    int s  = (idx >> 5) & 2047;
    int bh = idx >> 16;                               // 0..31
    size_t base = (((size_t)bh * SEQ + s) << 7);
    float c0 = __ldg(cosb + s * 64 + d2), c1 = __ldg(cosb + s * 64 + d2 + 1);
    float s0 = __ldg(sinb + s * 64 + d2), s1 = __ldg(sinb + s * 64 + d2 + 1);

    float2 q1 = __half22float2(*(__half2*)(g_qh + base + d2));
    float2 q2 = __half22float2(*(__half2*)(g_qh + base + d2 + 64));
    *(__half2*)(g_qh + base + d2) =
        __floats2half2_rn(q1.x * c0 - q2.x * s0, q1.y * c1 - q2.y * s1);
    *(__half2*)(g_qh + base + d2 + 64) =
        __floats2half2_rn(q2.x * c0 + q1.x * s0, q2.y * c1 + q1.y * s1);

    float2 k1 = __half22float2(*(__half2*)(g_kh + base + d2));
    float2 k2 = __half22float2(*(__half2*)(g_kh + base + d2 + 64));
    *(__half2*)(g_kh + base + d2) =
        __floats2half2_rn(k1.x * c0 - k2.x * s0, k1.y * c1 - k2.y * s1);
    *(__half2*)(g_kh + base + d2 + 64) =
        __floats2half2_rn(k2.x * c0 + k1.x * s0, k2.y * c1 + k1.y * s1);
}

// ---------------------------------------------------------------------------
// Flash attention, fp16 MMA (m16n8k16), fp32 accum/softmax.
// Q-tile 128, kv-tile 64, 256 threads = 8 warps; warp w owns q-rows
// [w*16, w*16+16) -> warp-local softmax (quad shuffles only).
// smem (halves): Qs[128][136], Ks[64][136], Vs[64][136], Ps[128][72].
// Strides 136 = 17x16B and 72 = 9x16B -> ldmatrix conflict-free.
// QK^T: A ldsm(Qs), B ldsm(Ks [n][k]).  PV: A ldsm(Ps), B ldsm.trans(Vs [j][d]).
// ---------------------------------------------------------------------------
#define F3_QS (128*136)
#define F3_KS (64*136)
#define F3_VS (64*136)
#define F3_PS (128*72)
#define FLASH3_SMEM_HALVES (F3_QS + F3_KS + F3_VS + F3_PS)   // 44032 -> 86 KB

__global__ __launch_bounds__(256, 1)
void flash_h_kernel()
{
    extern __shared__ __align__(16) __half hsm[];
    __half* Qs = hsm;
    __half* Ks = Qs + F3_QS;
    __half* Vs = Ks + F3_KS;
    __half* Ps = Vs + F3_VS;
    const uint32_t sb   = (uint32_t)__cvta_generic_to_shared(hsm);
    const uint32_t ksb  = sb + (uint32_t)F3_QS * 2u;
    const uint32_t vsb  = ksb + (uint32_t)F3_KS * 2u;
    const uint32_t psb  = vsb + (uint32_t)F3_VS * 2u;

    const int bh = blockIdx.x;
    const int qt = (int)gridDim.y - 1 - blockIdx.y;  // heavy tiles first
    const int m0 = qt * 128;
    const int t    = threadIdx.x;
    const int warp = t >> 5;
    const int lane = t & 31;
    const int g    = lane >> 2;
    const int tig  = lane & 3;
    const int r0   = warp * 16;
    const float scale = 0.08838834764831845f;        // 1/sqrt(128)

    const int lrA = lane & 15;              // ldsm A: row in 16-tile
    const int lcA = (lane >> 4) * 8;        // ldsm A: k offset
    const int lrB = (lane >> 4) * 8 + (lane & 7);   // ldsm B: n offset
    const int lcB = ((lane >> 3) & 1) * 8;          // ldsm B: k offset
    const int lrT = lane & 15;              // ldsm.trans: k row
    const int lcT = (lane >> 4) * 8;        // ldsm.trans: n offset

    // ---- load Q tile (128 rows x 128 halves) ----
    const __half* Qg = g_qh + ((size_t)bh * SEQ + m0) * HD;
#pragma unroll
    for (int i = 0; i < 8; i++) {
        int lin = t + i * 256;              // 0..2047 (16B chunks)
        int row = lin >> 4, c = lin & 15;
        uint4 v = *(const uint4*)(Qg + (size_t)row * HD + c * 8);
        *(uint4*)(Qs + row * 136 + c * 8) = v;
    }

    float oacc[16][4];
#pragma unroll
    for (int nt = 0; nt < 16; nt++)
#pragma unroll
        for (int r = 0; r < 4; r++) oacc[nt][r] = 0.f;
    float m0r = -INFINITY, m1r = -INFINITY;
    float l0r = 0.f, l1r = 0.f;

    const int gi0 = m0 + r0 + g;
    const int gi1 = gi0 + 8;
    const int ntiles = 2 * (qt + 1);

    for (int kt_i = 0; kt_i < ntiles; kt_i++) {
        int j0 = kt_i * 64;
        __syncthreads();                    // prior PV reads of Vs done

        const __half* Kg = g_kh + ((size_t)bh * SEQ + j0) * HD;
        const __half* Vg = g_vh + ((size_t)bh * SEQ + j0) * HD;
#pragma unroll
        for (int i = 0; i < 4; i++) {
            int lin = t + i * 256;          // 0..1023
            int row = lin >> 4, c = lin & 15;
            uint4 kv = *(const uint4*)(Kg + (size_t)row * HD + c * 8);
            *(uint4*)(Ks + row * 136 + c * 8) = kv;
            uint4 vv = *(const uint4*)(Vg + (size_t)row * HD + c * 8);
            *(uint4*)(Vs + row * 136 + c * 8) = vv;
        }
        __syncthreads();

        // ---- S = Q K^T : 8 k16-steps over d=128 ----
        float sacc[8][4];
#pragma unroll
        for (int nt = 0; nt < 8; nt++)
#pragma unroll
            for (int r = 0; r < 4; r++) sacc[nt][r] = 0.f;

#pragma unroll
        for (int ks = 0; ks < 8; ks++) {
            const int kb = ks * 16;
            uint32_t af[4];
            ldsm_x4(af, sb + (uint32_t)((r0 + lrA) * 136 + kb + lcA) * 2u);
            uint32_t bf[8][2];
#pragma unroll
            for (int nt2 = 0; nt2 < 4; nt2++) {
                uint32_t r[4];
                ldsm_x4(r, ksb + (uint32_t)((nt2 * 16 + lrB) * 136 + kb + lcB) * 2u);
                bf[nt2 * 2][0]     = r[0];
                bf[nt2 * 2][1]     = r[1];
                bf[nt2 * 2 + 1][0] = r[2];
                bf[nt2 * 2 + 1][1] = r[3];
            }
#pragma unroll
            for (int nt = 0; nt < 8; nt++)
                mma_f16(sacc[nt], af, bf[nt]);
        }

        // ---- softmax (warp-local; quad lanes share rows g / g+8) ----
        float pm0 = -INFINITY, pm1 = -INFINITY;
#pragma unroll
        for (int nt = 0; nt < 8; nt++) {
            int c = j0 + nt * 8 + tig * 2;
            float s0 = sacc[nt][0] * scale; if (c     > gi0) s0 = -INFINITY;
            float s1 = sacc[nt][1] * scale; if (c + 1 > gi0) s1 = -INFINITY;
            float s2 = sacc[nt][2] * scale; if (c     > gi1) s2 = -INFINITY;
            float s3 = sacc[nt][3] * scale; if (c + 1 > gi1) s3 = -INFINITY;
            sacc[nt][0] = s0; sacc[nt][1] = s1;
            sacc[nt][2] = s2; sacc[nt][3] = s3;
            pm0 = fmaxf(pm0, fmaxf(s0, s1));
            pm1 = fmaxf(pm1, fmaxf(s2, s3));
        }
        pm0 = fmaxf(pm0, __shfl_xor_sync(0xFFFFFFFFu, pm0, 1));
        pm0 = fmaxf(pm0, __shfl_xor_sync(0xFFFFFFFFu, pm0, 2));
        pm1 = fmaxf(pm1, __shfl_xor_sync(0xFFFFFFFFu, pm1, 1));
        pm1 = fmaxf(pm1, __shfl_xor_sync(0xFFFFFFFFu, pm1, 2));

        float mn0 = fmaxf(m0r, pm0);
        float mn1 = fmaxf(m1r, pm1);
        float corr0 = __expf(m0r - mn0);     // 0 on first tile
        float corr1 = __expf(m1r - mn1);

        float ps0 = 0.f, ps1 = 0.f;
#pragma unroll
        for (int nt = 0; nt < 8; nt++) {
            float p0 = __expf(sacc[nt][0] - mn0);
            float p1 = __expf(sacc[nt][1] - mn0);
            float p2 = __expf(sacc[nt][2] - mn1);
            float p3 = __expf(sacc[nt][3] - mn1);
            ps0 += p0 + p1; ps1 += p2 + p3;
            int jc = nt * 8 + tig * 2;
            *(__half2*)(Ps + (r0 + g    ) * 72 + jc) = __floats2half2_rn(p0, p1);
            *(__half2*)(Ps + (r0 + g + 8) * 72 + jc) = __floats2half2_rn(p2, p3);
        }
        ps0 += __shfl_xor_sync(0xFFFFFFFFu, ps0, 1);
        ps0 += __shfl_xor_sync(0xFFFFFFFFu, ps0, 2);
        ps1 += __shfl_xor_sync(0xFFFFFFFFu, ps1, 1);
        ps1 += __shfl_xor_sync(0xFFFFFFFFu, ps1, 2);

        l0r = l0r * corr0 + ps0;
        l1r = l1r * corr1 + ps1;
        m0r = mn0; m1r = mn1;

#pragma unroll
        for (int nt = 0; nt < 16; nt++) {
            oacc[nt][0] *= corr0; oacc[nt][1] *= corr0;
            oacc[nt][2] *= corr1; oacc[nt][3] *= corr1;
        }
        __syncwarp();                        // own-warp Ps visible

        // ---- O += P V : 4 k16-steps over j=64, 16 d-tiles ----
#pragma unroll
        for (int ks = 0; ks < 4; ks++) {
            const int kb = ks * 16;
            uint32_t af[4];
            ldsm_x4(af, psb + (uint32_t)((r0 + lrA) * 72 + kb + lcA) * 2u);
#pragma unroll
            for (int nt2 = 0; nt2 < 8; nt2++) {
                uint32_t r[4];
                ldsm_x4_t(r, vsb +
                    (uint32_t)((kb + lrT) * 136 + nt2 * 16 + lcT) * 2u);
                mma_f16(oacc[nt2 * 2],     af, r);       // b = {r0,r1}
                mma_f16(oacc[nt2 * 2 + 1], af, r + 2);   // b = {r2,r3}
            }
        }
    }

    // ---- normalize + write fp16 into g_att_h [B][S][H] ----
    float inv0 = 1.f / l0r, inv1 = 1.f / l1r;
    int b = bh >> 4, h = bh & 15;
    int row0 = m0 + r0 + g;
    __half* O0 = g_att_h + ((size_t)b * SEQ + row0    ) * HID + h * HD;
    __half* O1 = g_att_h + ((size_t)b * SEQ + row0 + 8) * HID + h * HD;
#pragma unroll
    for (int nt = 0; nt < 16; nt++) {
        int d = nt * 8 + tig * 2;
        *(__half2*)(O0 + d) =
            __floats2half2_rn(oacc[nt][0] * inv0, oacc[nt][1] * inv0);
        *(__half2*)(O1 + d) =
            __floats2half2_rn(oacc[nt][2] * inv1, oacc[nt][3] * inv1);
    }
}

// ---------------------------------------------------------------------------
extern "C" void kernel_launch(void* const* d_in, const int* in_sizes, int n_in,
                              void* d_out, int out_size)
{
    const float* x     = (const float*)d_in[0];
    const float* qkv_w = (const float*)d_in[1];
    const float* o_w   = (const float*)d_in[2];
    const float* cosb  = (const float*)d_in[3];
    const float* sinb  = (const float*)d_in[4];
    float* out = (float*)d_out;

    cudaFuncSetAttribute(h_gemm<0>,
        cudaFuncAttributeMaxDynamicSharedMemorySize, HGEMM_SMEM_BYTES);
    cudaFuncSetAttribute(h_gemm<1>,
        cudaFuncAttributeMaxDynamicSharedMemorySize, HGEMM_SMEM_BYTES);

    // 0) fp32 -> fp16 (rn) conversions of GEMM inputs
    f2h_kernel<0><<<(MROWS * HID) / 1024, 256>>>(x);
    f2h_kernel<1><<<(3 * HID * HID) / 1024, 256>>>(qkv_w);
    f2h_kernel<2><<<(HID * HID) / 1024, 256>>>(o_w);

    // 1) QKV projection: grid (48, 32), 128x128 tiles -> fp16 q/k/v
    h_gemm<0><<<dim3(6144 / 128, MROWS / 128), 256, HGEMM_SMEM_BYTES>>>(nullptr);

    // 2) rotary (fp16 in place)
    rotary_h_kernel<<<(NBATCH * NHEADS * SEQ * 32) / 256, 256>>>(cosb, sinb);

    // 3) flash attention (fp16 MMA), 86 KB smem; writes g_att_h (fp16)
    {
        const size_t smem = FLASH3_SMEM_HALVES * sizeof(__half); // 88064 B
        cudaFuncSetAttribute(flash_h_kernel,
                             cudaFuncAttributeMaxDynamicSharedMemorySize,
                             (int)smem);
        flash_h_kernel<<<dim3(NBATCH * NHEADS, SEQ / 128), 256, smem>>>();
    }

    // 4) output projection: grid (16, 32)
    h_gemm<1><<<dim3(HID / 128, MROWS / 128), 256, HGEMM_SMEM_BYTES>>>(out);
}

// round 16
// speedup vs baseline: 8.0290x; 1.0036x over previous
#include <cuda_runtime.h>
#include <cuda_fp16.h>
#include <math.h>
#include <stdint.h>

// Problem constants (fixed by the reference)
#define NBATCH 2
#define SEQ    2048
#define HID    2048
#define NHEADS 16
#define HD     128
#define MROWS  (NBATCH*SEQ)   // 4096

// ---------------------------------------------------------------------------
// Device scratch (allocation-free rule: __device__ globals)
// ---------------------------------------------------------------------------
__device__ __half g_qh[(size_t)NBATCH*NHEADS*SEQ*HD];   // 16 MB [B][NH][S][D]
__device__ __half g_kh[(size_t)NBATCH*NHEADS*SEQ*HD];   // 16 MB
__device__ __half g_vh[(size_t)NBATCH*NHEADS*SEQ*HD];   // 16 MB
__device__ __half g_xh[(size_t)MROWS*HID];              // 16 MB fp16 x
__device__ __half g_wh[(size_t)4*HID*HID];              // 32 MB fp16 qkv_w|o_w
__device__ __half g_att_h[(size_t)MROWS*HID];           // 16 MB fp16 attn out

// ---------------------------------------------------------------------------
// MMA / ldmatrix / cp.async helpers
// ---------------------------------------------------------------------------
__device__ __forceinline__ void mma_f16(float* c, const uint32_t* a,
                                        const uint32_t* b) {
    asm volatile(
        "mma.sync.aligned.m16n8k16.row.col.f32.f16.f16.f32 "
        "{%0,%1,%2,%3}, {%4,%5,%6,%7}, {%8,%9}, {%0,%1,%2,%3};"
        : "+f"(c[0]), "+f"(c[1]), "+f"(c[2]), "+f"(c[3])
        : "r"(a[0]), "r"(a[1]), "r"(a[2]), "r"(a[3]),
          "r"(b[0]), "r"(b[1]));
}

__device__ __forceinline__ void ldsm_x4(uint32_t* r, uint32_t saddr) {
    asm volatile(
        "ldmatrix.sync.aligned.m8n8.x4.shared.b16 {%0,%1,%2,%3}, [%4];"
        : "=r"(r[0]), "=r"(r[1]), "=r"(r[2]), "=r"(r[3]) : "r"(saddr));
}
__device__ __forceinline__ void ldsm_x4_t(uint32_t* r, uint32_t saddr) {
    asm volatile(
        "ldmatrix.sync.aligned.m8n8.x4.trans.shared.b16 {%0,%1,%2,%3}, [%4];"
        : "=r"(r[0]), "=r"(r[1]), "=r"(r[2]), "=r"(r[3]) : "r"(saddr));
}

__device__ __forceinline__ void cp16(uint32_t smem_dst, const void* gsrc) {
    asm volatile("cp.async.cg.shared.global [%0], [%1], 16;"
                 :: "r"(smem_dst), "l"(gsrc));
}
__device__ __forceinline__ void cp_commit() {
    asm volatile("cp.async.commit_group;");
}
__device__ __forceinline__ void cp_wait1() {
    asm volatile("cp.async.wait_group 1;" ::: "memory");
}

// ---------------------------------------------------------------------------
// fp32 -> fp16 (rn) conversion pre-passes. WHICH: 0=x, 1=qkv_w, 2=o_w
// ---------------------------------------------------------------------------
template<int WHICH>
__global__ __launch_bounds__(256)
void f2h_kernel(const float* __restrict__ src)
{
    __half* dst = (WHICH == 0) ? g_xh
                : (WHICH == 1) ? g_wh
                : g_wh + (size_t)3 * HID * HID;
    size_t i = ((size_t)blockIdx.x * 256 + threadIdx.x) * 4;
    float4 v = *(const float4*)(src + i);
    __half2 h0 = __floats2half2_rn(v.x, v.y);
    __half2 h1 = __floats2half2_rn(v.z, v.w);
    uint2 u;
    u.x = *(uint32_t*)&h0;
    u.y = *(uint32_t*)&h1;
    *(uint2*)(dst + i) = u;
}

// ---------------------------------------------------------------------------
// fp16 tensor-core GEMM  C[m][n] = sum_k A[m][k] * W[n][k]  (f32 accumulate)
// Block tile 128x128, BK=64, 256 threads, 2 CTAs/SM.
// THREE-stage cp.async pipeline, ONE __syncthreads per iteration: the
// prefetch target stage (kt+2)%3 == (kt-1)%3 was fully read before this
// iteration's barrier, so prefetch issues right after the sync and overlaps
// the MMA block. Always-commit keeps wait_group 1 exact in the tail.
// MODE 0: A = g_xh, W = g_wh(qkv), scatter fp16 into g_qh/g_kh/g_vh
// MODE 1: A = g_att_h, W = g_wh+3H^2 (o_w), C = d_out (fp32)
// ---------------------------------------------------------------------------
#define HS_STRIDE 72                       // halves per row (144 B)
#define HS_ABUF   (128 * HS_STRIDE)        // 9216 halves
#define HS_BUF    (2 * HS_ABUF)            // 18432 halves / stage (A+B)
#define HGEMM_SMEM_BYTES (3 * HS_BUF * 2)  // 110592 B (3 stages)

template<int MODE>
__global__ __launch_bounds__(256, 2)
void h_gemm(float* __restrict__ Cout)
{
    extern __shared__ __align__(16) __half hsm[];
    const uint32_t sbase = (uint32_t)__cvta_generic_to_shared(hsm);

    const __half* A = (MODE == 0) ? g_xh : g_att_h;
    const __half* W = (MODE == 0) ? g_wh : g_wh + (size_t)3 * HID * HID;
    const int K = HID;

    const int tid  = threadIdx.x;
    const int warp = tid >> 5;
    const int lane = tid & 31;
    const int g    = lane >> 2;
    const int tig  = lane & 3;
    const int wm   = (warp >> 1) * 32;      // 0,32,64,96
    const int wn   = (warp & 1)  * 64;      // 0,64
    const int m0   = blockIdx.y * 128;
    const int n0   = blockIdx.x * 128;

    const __half* Ab = A + (size_t)m0 * K;
    const __half* Wb = W + (size_t)n0 * K;

    const int lrA = lane & 15;
    const int lcA = (lane >> 4) * 8;
    const int lrB = (lane >> 4) * 8 + (lane & 7);
    const int lcB = ((lane >> 3) & 1) * 8;

    float acc[2][8][4];
#pragma unroll
    for (int mt = 0; mt < 2; mt++)
#pragma unroll
        for (int nt = 0; nt < 8; nt++)
#pragma unroll
            for (int r = 0; r < 4; r++) acc[mt][nt][r] = 0.f;

    const int niter = K / 64;               // 32

    auto prefetch = [&](int kt, int buf) {
        const uint32_t b0 = sbase + (uint32_t)(buf * HS_BUF) * 2u;
#pragma unroll
        for (int j = 0; j < 4; j++) {        // A: 128 rows x 8 chunks (16B)
            int id = tid + j * 256;
            int row = id >> 3, c = id & 7;
            cp16(b0 + (uint32_t)(row * HS_STRIDE + c * 8) * 2u,
                 Ab + (size_t)row * K + kt * 64 + c * 8);
        }
#pragma unroll
        for (int j = 0; j < 4; j++) {        // B: 128 rows x 8 chunks
            int id = tid + j * 256;
            int row = id >> 3, c = id & 7;
            cp16(b0 + (uint32_t)(HS_ABUF + row * HS_STRIDE + c * 8) * 2u,
                 Wb + (size_t)row * K + kt * 64 + c * 8);
        }
    };

    prefetch(0, 0); cp_commit();
    prefetch(1, 1); cp_commit();

    for (int kt = 0; kt < niter; kt++) {
        const int s = kt % 3;
        cp_wait1();                          // tile kt resident
        __syncthreads();                     // ONE barrier per iteration

        // prefetch tile kt+2 into stage (kt+2)%3 == (kt-1)%3 (reads done)
        if (kt + 2 < niter) prefetch(kt + 2, (kt + 2) % 3);
        cp_commit();                         // always-commit (tail-exact)

        const uint32_t asb = sbase + (uint32_t)(s * HS_BUF) * 2u;
        const uint32_t bsb = asb + (uint32_t)HS_ABUF * 2u;

#pragma unroll
        for (int ks = 0; ks < 4; ks++) {
            const int kb = ks * 16;
            uint32_t af[2][4];
#pragma unroll
            for (int mt = 0; mt < 2; mt++) {
                uint32_t addr = asb +
                    (uint32_t)((wm + mt * 16 + lrA) * HS_STRIDE + kb + lcA) * 2u;
                ldsm_x4(af[mt], addr);
            }
            uint32_t bf[8][2];
#pragma unroll
            for (int nt2 = 0; nt2 < 4; nt2++) {
                uint32_t r[4];
                uint32_t addr = bsb +
                    (uint32_t)((wn + nt2 * 16 + lrB) * HS_STRIDE + kb + lcB) * 2u;
                ldsm_x4(r, addr);
                bf[nt2 * 2][0]     = r[0];
                bf[nt2 * 2][1]     = r[1];
                bf[nt2 * 2 + 1][0] = r[2];
                bf[nt2 * 2 + 1][1] = r[3];
            }
#pragma unroll
            for (int mt = 0; mt < 2; mt++)
#pragma unroll
                for (int nt = 0; nt < 8; nt++)
                    mma_f16(acc[mt][nt], af[mt], bf[nt]);
        }
    }

    // ---- epilogue ----
#pragma unroll
    for (int mt = 0; mt < 2; mt++) {
        int m = m0 + wm + mt * 16 + g;
        int b = m >> 11;
        int s = m & 2047;
#pragma unroll
        for (int nt = 0; nt < 8; nt++) {
            int n = n0 + wn + nt * 8 + tig * 2;
            if (MODE == 0) {
                int which = n >> 11;            // 0=q 1=k 2=v
                int hn    = (n & 2047) >> 7;    // head
                int d     = n & 127;
                __half* dst = (which == 0) ? g_qh : (which == 1) ? g_kh : g_vh;
                size_t idx = ((((size_t)b * NHEADS + hn) * SEQ + s) << 7) + d;
                *(__half2*)(dst + idx) =
                    __floats2half2_rn(acc[mt][nt][0], acc[mt][nt][1]);
                *(__half2*)(dst + idx + (8u << 7)) =
                    __floats2half2_rn(acc[mt][nt][2], acc[mt][nt][3]);
            } else {
                *(float2*)(Cout + (size_t)m * HID + n) =
                    make_float2(acc[mt][nt][0], acc[mt][nt][1]);
                *(float2*)(Cout + (size_t)(m + 8) * HID + n) =
                    make_float2(acc[mt][nt][2], acc[mt][nt][3]);
            }
        }
    }
}

// ---------------------------------------------------------------------------
// Rotary on fp16 q and k in place (fp32 math). Thread = 2 consecutive dims.
// ---------------------------------------------------------------------------
__global__ __launch_bounds__(256)
void rotary_h_kernel(const float* __restrict__ cosb,
                     const float* __restrict__ sinb)
{
    int idx = blockIdx.x * blockDim.x + threadIdx.x;  // 2^21 threads
    int d2 = (idx & 31) * 2;                          // 0,2,..,62
    int s  = (idx >> 5) & 2047;
    int bh = idx >> 16;                               // 0..31
    size_t base = (((size_t)bh * SEQ + s) << 7);
    float c0 = __ldg(cosb + s * 64 + d2), c1 = __ldg(cosb + s * 64 + d2 + 1);
    float s0 = __ldg(sinb + s * 64 + d2), s1 = __ldg(sinb + s * 64 + d2 + 1);

    float2 q1 = __half22float2(*(__half2*)(g_qh + base + d2));
    float2 q2 = __half22float2(*(__half2*)(g_qh + base + d2 + 64));
    *(__half2*)(g_qh + base + d2) =
        __floats2half2_rn(q1.x * c0 - q2.x * s0, q1.y * c1 - q2.y * s1);
    *(__half2*)(g_qh + base + d2 + 64) =
        __floats2half2_rn(q2.x * c0 + q1.x * s0, q2.y * c1 + q1.y * s1);

    float2 k1 = __half22float2(*(__half2*)(g_kh + base + d2));
    float2 k2 = __half22float2(*(__half2*)(g_kh + base + d2 + 64));
    *(__half2*)(g_kh + base + d2) =
        __floats2half2_rn(k1.x * c0 - k2.x * s0, k1.y * c1 - k2.y * s1);
    *(__half2*)(g_kh + base + d2 + 64) =
        __floats2half2_rn(k2.x * c0 + k1.x * s0, k2.y * c1 + k1.y * s1);
}

// ---------------------------------------------------------------------------
// Flash attention, fp16 MMA (m16n8k16), fp32 accum/softmax. (R15 — proven.)
// ---------------------------------------------------------------------------
#define F3_QS (128*136)
#define F3_KS (64*136)
#define F3_VS (64*136)
#define F3_PS (128*72)
#define FLASH3_SMEM_HALVES (F3_QS + F3_KS + F3_VS + F3_PS)   // 44032 -> 86 KB

__global__ __launch_bounds__(256, 1)
void flash_h_kernel()
{
    extern __shared__ __align__(16) __half hsm[];
    __half* Qs = hsm;
    __half* Ks = Qs + F3_QS;
    __half* Vs = Ks + F3_KS;
    __half* Ps = Vs + F3_VS;
    const uint32_t sb   = (uint32_t)__cvta_generic_to_shared(hsm);
    const uint32_t ksb  = sb + (uint32_t)F3_QS * 2u;
    const uint32_t vsb  = ksb + (uint32_t)F3_KS * 2u;
    const uint32_t psb  = vsb + (uint32_t)F3_VS * 2u;

    const int bh = blockIdx.x;
    const int qt = (int)gridDim.y - 1 - blockIdx.y;  // heavy tiles first
    const int m0 = qt * 128;
    const int t    = threadIdx.x;
    const int warp = t >> 5;
    const int lane = t & 31;
    const int g    = lane >> 2;
    const int tig  = lane & 3;
    const int r0   = warp * 16;
    const float scale = 0.08838834764831845f;        // 1/sqrt(128)

    const int lrA = lane & 15;
    const int lcA = (lane >> 4) * 8;
    const int lrB = (lane >> 4) * 8 + (lane & 7);
    const int lcB = ((lane >> 3) & 1) * 8;
    const int lrT = lane & 15;
    const int lcT = (lane >> 4) * 8;

    const __half* Qg = g_qh + ((size_t)bh * SEQ + m0) * HD;
#pragma unroll
    for (int i = 0; i < 8; i++) {
        int lin = t + i * 256;
        int row = lin >> 4, c = lin & 15;
        uint4 v = *(const uint4*)(Qg + (size_t)row * HD + c * 8);
        *(uint4*)(Qs + row * 136 + c * 8) = v;
    }

    float oacc[16][4];
#pragma unroll
    for (int nt = 0; nt < 16; nt++)
#pragma unroll
        for (int r = 0; r < 4; r++) oacc[nt][r] = 0.f;
    float m0r = -INFINITY, m1r = -INFINITY;
    float l0r = 0.f, l1r = 0.f;

    const int gi0 = m0 + r0 + g;
    const int gi1 = gi0 + 8;
    const int ntiles = 2 * (qt + 1);

    for (int kt_i = 0; kt_i < ntiles; kt_i++) {
        int j0 = kt_i * 64;
        __syncthreads();

        const __half* Kg = g_kh + ((size_t)bh * SEQ + j0) * HD;
        const __half* Vg = g_vh + ((size_t)bh * SEQ + j0) * HD;
#pragma unroll
        for (int i = 0; i < 4; i++) {
            int lin = t + i * 256;
            int row = lin >> 4, c = lin & 15;
            uint4 kv = *(const uint4*)(Kg + (size_t)row * HD + c * 8);
            *(uint4*)(Ks + row * 136 + c * 8) = kv;
            uint4 vv = *(const uint4*)(Vg + (size_t)row * HD + c * 8);
            *(uint4*)(Vs + row * 136 + c * 8) = vv;
        }
        __syncthreads();

        float sacc[8][4];
#pragma unroll
        for (int nt = 0; nt < 8; nt++)
#pragma unroll
            for (int r = 0; r < 4; r++) sacc[nt][r] = 0.f;

#pragma unroll
        for (int ks = 0; ks < 8; ks++) {
            const int kb = ks * 16;
            uint32_t af[4];
            ldsm_x4(af, sb + (uint32_t)((r0 + lrA) * 136 + kb + lcA) * 2u);
            uint32_t bf[8][2];
#pragma unroll
            for (int nt2 = 0; nt2 < 4; nt2++) {
                uint32_t r[4];
                ldsm_x4(r, ksb + (uint32_t)((nt2 * 16 + lrB) * 136 + kb + lcB) * 2u);
                bf[nt2 * 2][0]     = r[0];
                bf[nt2 * 2][1]     = r[1];
                bf[nt2 * 2 + 1][0] = r[2];
                bf[nt2 * 2 + 1][1] = r[3];
            }
#pragma unroll
            for (int nt = 0; nt < 8; nt++)
                mma_f16(sacc[nt], af, bf[nt]);
        }

        float pm0 = -INFINITY, pm1 = -INFINITY;
#pragma unroll
        for (int nt = 0; nt < 8; nt++) {
            int c = j0 + nt * 8 + tig * 2;
            float s0 = sacc[nt][0] * scale; if (c     > gi0) s0 = -INFINITY;
            float s1 = sacc[nt][1] * scale; if (c + 1 > gi0) s1 = -INFINITY;
            float s2 = sacc[nt][2] * scale; if (c     > gi1) s2 = -INFINITY;
            float s3 = sacc[nt][3] * scale; if (c + 1 > gi1) s3 = -INFINITY;
            sacc[nt][0] = s0; sacc[nt][1] = s1;
            sacc[nt][2] = s2; sacc[nt][3] = s3;
            pm0 = fmaxf(pm0, fmaxf(s0, s1));
            pm1 = fmaxf(pm1, fmaxf(s2, s3));
        }
        pm0 = fmaxf(pm0, __shfl_xor_sync(0xFFFFFFFFu, pm0, 1));
        pm0 = fmaxf(pm0, __shfl_xor_sync(0xFFFFFFFFu, pm0, 2));
        pm1 = fmaxf(pm1, __shfl_xor_sync(0xFFFFFFFFu, pm1, 1));
        pm1 = fmaxf(pm1, __shfl_xor_sync(0xFFFFFFFFu, pm1, 2));

        float mn0 = fmaxf(m0r, pm0);
        float mn1 = fmaxf(m1r, pm1);
        float corr0 = __expf(m0r - mn0);
        float corr1 = __expf(m1r - mn1);

        float ps0 = 0.f, ps1 = 0.f;
#pragma unroll
        for (int nt = 0; nt < 8; nt++) {
            float p0 = __expf(sacc[nt][0] - mn0);
            float p1 = __expf(sacc[nt][1] - mn0);
            float p2 = __expf(sacc[nt][2] - mn1);
            float p3 = __expf(sacc[nt][3] - mn1);
            ps0 += p0 + p1; ps1 += p2 + p3;
            int jc = nt * 8 + tig * 2;
            *(__half2*)(Ps + (r0 + g    ) * 72 + jc) = __floats2half2_rn(p0, p1);
            *(__half2*)(Ps + (r0 + g + 8) * 72 + jc) = __floats2half2_rn(p2, p3);
        }
        ps0 += __shfl_xor_sync(0xFFFFFFFFu, ps0, 1);
        ps0 += __shfl_xor_sync(0xFFFFFFFFu, ps0, 2);
        ps1 += __shfl_xor_sync(0xFFFFFFFFu, ps1, 1);
        ps1 += __shfl_xor_sync(0xFFFFFFFFu, ps1, 2);

        l0r = l0r * corr0 + ps0;
        l1r = l1r * corr1 + ps1;
        m0r = mn0; m1r = mn1;

#pragma unroll
        for (int nt = 0; nt < 16; nt++) {
            oacc[nt][0] *= corr0; oacc[nt][1] *= corr0;
            oacc[nt][2] *= corr1; oacc[nt][3] *= corr1;
        }
        __syncwarp();

#pragma unroll
        for (int ks = 0; ks < 4; ks++) {
            const int kb = ks * 16;
            uint32_t af[4];
            ldsm_x4(af, psb + (uint32_t)((r0 + lrA) * 72 + kb + lcA) * 2u);
#pragma unroll
            for (int nt2 = 0; nt2 < 8; nt2++) {
                uint32_t r[4];
                ldsm_x4_t(r, vsb +
                    (uint32_t)((kb + lrT) * 136 + nt2 * 16 + lcT) * 2u);
                mma_f16(oacc[nt2 * 2],     af, r);
                mma_f16(oacc[nt2 * 2 + 1], af, r + 2);
            }
        }
    }

    float inv0 = 1.f / l0r, inv1 = 1.f / l1r;
    int b = bh >> 4, h = bh & 15;
    int row0 = m0 + r0 + g;
    __half* O0 = g_att_h + ((size_t)b * SEQ + row0    ) * HID + h * HD;
    __half* O1 = g_att_h + ((size_t)b * SEQ + row0 + 8) * HID + h * HD;
#pragma unroll
    for (int nt = 0; nt < 16; nt++) {
        int d = nt * 8 + tig * 2;
        *(__half2*)(O0 + d) =
            __floats2half2_rn(oacc[nt][0] * inv0, oacc[nt][1] * inv0);
        *(__half2*)(O1 + d) =
            __floats2half2_rn(oacc[nt][2] * inv1, oacc[nt][3] * inv1);
    }
}

// ---------------------------------------------------------------------------
extern "C" void kernel_launch(void* const* d_in, const int* in_sizes, int n_in,
                              void* d_out, int out_size)
{
    const float* x     = (const float*)d_in[0];
    const float* qkv_w = (const float*)d_in[1];
    const float* o_w   = (const float*)d_in[2];
    const float* cosb  = (const float*)d_in[3];
    const float* sinb  = (const float*)d_in[4];
    float* out = (float*)d_out;

    cudaFuncSetAttribute(h_gemm<0>,
        cudaFuncAttributeMaxDynamicSharedMemorySize, HGEMM_SMEM_BYTES);
    cudaFuncSetAttribute(h_gemm<1>,
        cudaFuncAttributeMaxDynamicSharedMemorySize, HGEMM_SMEM_BYTES);

    // 0) fp32 -> fp16 (rn) conversions of GEMM inputs
    f2h_kernel<0><<<(MROWS * HID) / 1024, 256>>>(x);
    f2h_kernel<1><<<(3 * HID * HID) / 1024, 256>>>(qkv_w);
    f2h_kernel<2><<<(HID * HID) / 1024, 256>>>(o_w);

    // 1) QKV projection: grid (48, 32), 128x128 tiles -> fp16 q/k/v
    h_gemm<0><<<dim3(6144 / 128, MROWS / 128), 256, HGEMM_SMEM_BYTES>>>(nullptr);

    // 2) rotary (fp16 in place)
    rotary_h_kernel<<<(NBATCH * NHEADS * SEQ * 32) / 256, 256>>>(cosb, sinb);

    // 3) flash attention (fp16 MMA), 86 KB smem; writes g_att_h (fp16)
    {
        const size_t smem = FLASH3_SMEM_HALVES * sizeof(__half); // 88064 B
        cudaFuncSetAttribute(flash_h_kernel,
                             cudaFuncAttributeMaxDynamicSharedMemorySize,
                             (int)smem);
        flash_h_kernel<<<dim3(NBATCH * NHEADS, SEQ / 128), 256, smem>>>();
    }

    // 4) output projection: grid (16, 32)
    h_gemm<1><<<dim3(HID / 128, MROWS / 128), 256, HGEMM_SMEM_BYTES>>>(out);
}

// round 17
// speedup vs baseline: 8.7080x; 1.0846x over previous
#include <cuda_runtime.h>
#include <cuda_fp16.h>
#include <math.h>
#include <stdint.h>

// Problem constants (fixed by the reference)
#define NBATCH 2
#define SEQ    2048
#define HID    2048
#define NHEADS 16
#define HD     128
#define MROWS  (NBATCH*SEQ)   // 4096

// ---------------------------------------------------------------------------
// Device scratch (allocation-free rule: __device__ globals)
// ---------------------------------------------------------------------------
__device__ __half g_qh[(size_t)NBATCH*NHEADS*SEQ*HD];   // 16 MB [B][NH][S][D]
__device__ __half g_kh[(size_t)NBATCH*NHEADS*SEQ*HD];   // 16 MB
__device__ __half g_vh[(size_t)NBATCH*NHEADS*SEQ*HD];   // 16 MB
__device__ __half g_xh[(size_t)MROWS*HID];              // 16 MB fp16 x
__device__ __half g_wh[(size_t)4*HID*HID];              // 32 MB fp16 qkv_w|o_w
__device__ __half g_att_h[(size_t)MROWS*HID];           // 16 MB fp16 attn out

// ---------------------------------------------------------------------------
// MMA / ldmatrix / cp.async helpers
// ---------------------------------------------------------------------------
__device__ __forceinline__ void mma_f16(float* c, const uint32_t* a,
                                        const uint32_t* b) {
    asm volatile(
        "mma.sync.aligned.m16n8k16.row.col.f32.f16.f16.f32 "
        "{%0,%1,%2,%3}, {%4,%5,%6,%7}, {%8,%9}, {%0,%1,%2,%3};"
        : "+f"(c[0]), "+f"(c[1]), "+f"(c[2]), "+f"(c[3])
        : "r"(a[0]), "r"(a[1]), "r"(a[2]), "r"(a[3]),
          "r"(b[0]), "r"(b[1]));
}

__device__ __forceinline__ void ldsm_x4(uint32_t* r, uint32_t saddr) {
    asm volatile(
        "ldmatrix.sync.aligned.m8n8.x4.shared.b16 {%0,%1,%2,%3}, [%4];"
        : "=r"(r[0]), "=r"(r[1]), "=r"(r[2]), "=r"(r[3]) : "r"(saddr));
}
__device__ __forceinline__ void ldsm_x4_t(uint32_t* r, uint32_t saddr) {
    asm volatile(
        "ldmatrix.sync.aligned.m8n8.x4.trans.shared.b16 {%0,%1,%2,%3}, [%4];"
        : "=r"(r[0]), "=r"(r[1]), "=r"(r[2]), "=r"(r[3]) : "r"(saddr));
}

__device__ __forceinline__ void cp16(uint32_t smem_dst, const void* gsrc) {
    asm volatile("cp.async.cg.shared.global [%0], [%1], 16;"
                 :: "r"(smem_dst), "l"(gsrc));
}
__device__ __forceinline__ void cp_commit() {
    asm volatile("cp.async.commit_group;");
}
__device__ __forceinline__ void cp_wait1() {
    asm volatile("cp.async.wait_group 1;" ::: "memory");
}

// ---------------------------------------------------------------------------
// fp32 -> fp16 (rn) conversion pre-passes. WHICH: 0=x, 1=qkv_w, 2=o_w
// ---------------------------------------------------------------------------
template<int WHICH>
__global__ __launch_bounds__(256)
void f2h_kernel(const float* __restrict__ src)
{
    __half* dst = (WHICH == 0) ? g_xh
                : (WHICH == 1) ? g_wh
                : g_wh + (size_t)3 * HID * HID;
    size_t i = ((size_t)blockIdx.x * 256 + threadIdx.x) * 4;
    float4 v = *(const float4*)(src + i);
    __half2 h0 = __floats2half2_rn(v.x, v.y);
    __half2 h1 = __floats2half2_rn(v.z, v.w);
    uint2 u;
    u.x = *(uint32_t*)&h0;
    u.y = *(uint32_t*)&h1;
    *(uint2*)(dst + i) = u;
}

// ---------------------------------------------------------------------------
// fp16 tensor-core GEMM  C[m][n] = sum_k A[m][k] * W[n][k]  (f32 accumulate)
// Block tile 128x128, BK=64, 128 threads = 4 warps (2x2), warp tile 64x64.
// THREE CTAs per SM (launch_bounds(128,3), reg cap 170) — smem-BW economics:
// 64x64 warp tiles need 1/16 B/MAC of fragment traffic (vs 3/32 at 32x64),
// which fits under the 128 B/cyc smem crossbar at full tensor rate.
// smem [row][72 halves] (ldmatrix conflict-free), 2-stage cp.async.
// MODE 0: A = g_xh, W = g_wh(qkv), scatter fp16 into g_qh/g_kh/g_vh
// MODE 1: A = g_att_h, W = g_wh+3H^2 (o_w), C = d_out (fp32)
// ---------------------------------------------------------------------------
#define HS_STRIDE 72                       // halves per row (144 B)
#define HS_ABUF   (128 * HS_STRIDE)        // 9216 halves
#define HS_BUF    (2 * HS_ABUF)            // 18432 halves / stage (A+B)
#define HGEMM_SMEM_BYTES (2 * HS_BUF * 2)  // 73728 B (x3 CTAs = 221 KB)

template<int MODE>
__global__ __launch_bounds__(128, 3)
void h_gemm(float* __restrict__ Cout)
{
    extern __shared__ __align__(16) __half hsm[];
    const uint32_t sbase = (uint32_t)__cvta_generic_to_shared(hsm);

    const __half* A = (MODE == 0) ? g_xh : g_att_h;
    const __half* W = (MODE == 0) ? g_wh : g_wh + (size_t)3 * HID * HID;
    const int K = HID;

    const int tid  = threadIdx.x;
    const int warp = tid >> 5;
    const int lane = tid & 31;
    const int g    = lane >> 2;
    const int tig  = lane & 3;
    const int wm   = (warp >> 1) * 64;      // 0,64
    const int wn   = (warp & 1)  * 64;      // 0,64
    const int m0   = blockIdx.y * 128;
    const int n0   = blockIdx.x * 128;

    const __half* Ab = A + (size_t)m0 * K;
    const __half* Wb = W + (size_t)n0 * K;

    const int lrA = lane & 15;
    const int lcA = (lane >> 4) * 8;
    const int lrB = (lane >> 4) * 8 + (lane & 7);
    const int lcB = ((lane >> 3) & 1) * 8;

    float acc[4][8][4];
#pragma unroll
    for (int mt = 0; mt < 4; mt++)
#pragma unroll
        for (int nt = 0; nt < 8; nt++)
#pragma unroll
            for (int r = 0; r < 4; r++) acc[mt][nt][r] = 0.f;

    const int niter = K / 64;               // 32

    auto prefetch = [&](int kt, int buf) {
        const uint32_t b0 = sbase + (uint32_t)(buf * HS_BUF) * 2u;
#pragma unroll
        for (int j = 0; j < 8; j++) {        // A: 128 rows x 8 chunks (16B)
            int id = tid + j * 128;          // 0..1023
            int row = id >> 3, c = id & 7;
            cp16(b0 + (uint32_t)(row * HS_STRIDE + c * 8) * 2u,
                 Ab + (size_t)row * K + kt * 64 + c * 8);
        }
#pragma unroll
        for (int j = 0; j < 8; j++) {        // B: 128 rows x 8 chunks
            int id = tid + j * 128;
            int row = id >> 3, c = id & 7;
            cp16(b0 + (uint32_t)(HS_ABUF + row * HS_STRIDE + c * 8) * 2u,
                 Wb + (size_t)row * K + kt * 64 + c * 8);
        }
    };

    prefetch(0, 0); cp_commit();
    prefetch(1, 1); cp_commit();

    for (int kt = 0; kt < niter; kt++) {
        const int p = kt & 1;
        cp_wait1();
        __syncthreads();

        const uint32_t asb = sbase + (uint32_t)(p * HS_BUF) * 2u;
        const uint32_t bsb = asb + (uint32_t)HS_ABUF * 2u;

#pragma unroll
        for (int ks = 0; ks < 4; ks++) {
            const int kb = ks * 16;
            uint32_t af[4][4];
#pragma unroll
            for (int mt = 0; mt < 4; mt++) {
                uint32_t addr = asb +
                    (uint32_t)((wm + mt * 16 + lrA) * HS_STRIDE + kb + lcA) * 2u;
                ldsm_x4(af[mt], addr);
            }
#pragma unroll
            for (int nt2 = 0; nt2 < 4; nt2++) {
                uint32_t r[4];                // transient B pair (low liveness)
                uint32_t addr = bsb +
                    (uint32_t)((wn + nt2 * 16 + lrB) * HS_STRIDE + kb + lcB) * 2u;
                ldsm_x4(r, addr);
#pragma unroll
                for (int mt = 0; mt < 4; mt++) {
                    mma_f16(acc[mt][nt2 * 2],     af[mt], r);
                    mma_f16(acc[mt][nt2 * 2 + 1], af[mt], r + 2);
                }
            }
        }
        __syncthreads();
        if (kt + 2 < niter) prefetch(kt + 2, p);
        cp_commit();                         // always-commit keeps wait exact
    }

    // ---- epilogue (N tile = exactly one head in MODE 0) ----
#pragma unroll
    for (int mt = 0; mt < 4; mt++) {
        int m = m0 + wm + mt * 16 + g;
        int b = m >> 11;
        int s = m & 2047;
#pragma unroll
        for (int nt = 0; nt < 8; nt++) {
            int n = n0 + wn + nt * 8 + tig * 2;
            if (MODE == 0) {
                int which = n >> 11;            // 0=q 1=k 2=v
                int hn    = (n & 2047) >> 7;    // head
                int d     = n & 127;
                __half* dst = (which == 0) ? g_qh : (which == 1) ? g_kh : g_vh;
                size_t idx = ((((size_t)b * NHEADS + hn) * SEQ + s) << 7) + d;
                *(__half2*)(dst + idx) =
                    __floats2half2_rn(acc[mt][nt][0], acc[mt][nt][1]);
                *(__half2*)(dst + idx + (8u << 7)) =
                    __floats2half2_rn(acc[mt][nt][2], acc[mt][nt][3]);
            } else {
                *(float2*)(Cout + (size_t)m * HID + n) =
                    make_float2(acc[mt][nt][0], acc[mt][nt][1]);
                *(float2*)(Cout + (size_t)(m + 8) * HID + n) =
                    make_float2(acc[mt][nt][2], acc[mt][nt][3]);
            }
        }
    }
}

// ---------------------------------------------------------------------------
// Rotary on fp16 q and k in place (fp32 math). Thread = 2 consecutive dims.
// ---------------------------------------------------------------------------
__global__ __launch_bounds__(256)
void rotary_h_kernel(const float* __restrict__ cosb,
                     const float* __restrict__ sinb)
{
    int idx = blockIdx.x * blockDim.x + threadIdx.x;  // 2^21 threads
    int d2 = (idx & 31) * 2;                          // 0,2,..,62
    int s  = (idx >> 5) & 2047;
    int bh = idx >> 16;                               // 0..31
    size_t base = (((size_t)bh * SEQ + s) << 7);
    float c0 = __ldg(cosb + s * 64 + d2), c1 = __ldg(cosb + s * 64 + d2 + 1);
    float s0 = __ldg(sinb + s * 64 + d2), s1 = __ldg(sinb + s * 64 + d2 + 1);

    float2 q1 = __half22float2(*(__half2*)(g_qh + base + d2));
    float2 q2 = __half22float2(*(__half2*)(g_qh + base + d2 + 64));
    *(__half2*)(g_qh + base + d2) =
        __floats2half2_rn(q1.x * c0 - q2.x * s0, q1.y * c1 - q2.y * s1);
    *(__half2*)(g_qh + base + d2 + 64) =
        __floats2half2_rn(q2.x * c0 + q1.x * s0, q2.y * c1 + q1.y * s1);

    float2 k1 = __half22float2(*(__half2*)(g_kh + base + d2));
    float2 k2 = __half22float2(*(__half2*)(g_kh + base + d2 + 64));
    *(__half2*)(g_kh + base + d2) =
        __floats2half2_rn(k1.x * c0 - k2.x * s0, k1.y * c1 - k2.y * s1);
    *(__half2*)(g_kh + base + d2 + 64) =
        __floats2half2_rn(k2.x * c0 + k1.x * s0, k2.y * c1 + k1.y * s1);
}

// ---------------------------------------------------------------------------
// Flash attention, fp16 MMA (m16n8k16), fp32 accum/softmax.
// Now launch_bounds(256, 2): two CTAs per SM so the per-tile barrier/load
// phases of one CTA overlap the MMA/softmax phases of the other.
// ---------------------------------------------------------------------------
#define F3_QS (128*136)
#define F3_KS (64*136)
#define F3_VS (64*136)
#define F3_PS (128*72)
#define FLASH3_SMEM_HALVES (F3_QS + F3_KS + F3_VS + F3_PS)   // 44032 -> 86 KB

__global__ __launch_bounds__(256, 2)
void flash_h_kernel()
{
    extern __shared__ __align__(16) __half hsm[];
    __half* Qs = hsm;
    __half* Ks = Qs + F3_QS;
    __half* Vs = Ks + F3_KS;
    __half* Ps = Vs + F3_VS;
    const uint32_t sb   = (uint32_t)__cvta_generic_to_shared(hsm);
    const uint32_t ksb  = sb + (uint32_t)F3_QS * 2u;
    const uint32_t vsb  = ksb + (uint32_t)F3_KS * 2u;
    const uint32_t psb  = vsb + (uint32_t)F3_VS * 2u;

    const int bh = blockIdx.x;
    const int qt = (int)gridDim.y - 1 - blockIdx.y;  // heavy tiles first
    const int m0 = qt * 128;
    const int t    = threadIdx.x;
    const int warp = t >> 5;
    const int lane = t & 31;
    const int g    = lane >> 2;
    const int tig  = lane & 3;
    const int r0   = warp * 16;
    const float scale = 0.08838834764831845f;        // 1/sqrt(128)

    const int lrA = lane & 15;
    const int lcA = (lane >> 4) * 8;
    const int lrB = (lane >> 4) * 8 + (lane & 7);
    const int lcB = ((lane >> 3) & 1) * 8;
    const int lrT = lane & 15;
    const int lcT = (lane >> 4) * 8;

    const __half* Qg = g_qh + ((size_t)bh * SEQ + m0) * HD;
#pragma unroll
    for (int i = 0; i < 8; i++) {
        int lin = t + i * 256;
        int row = lin >> 4, c = lin & 15;
        uint4 v = *(const uint4*)(Qg + (size_t)row * HD + c * 8);
        *(uint4*)(Qs + row * 136 + c * 8) = v;
    }

    float oacc[16][4];
#pragma unroll
    for (int nt = 0; nt < 16; nt++)
#pragma unroll
        for (int r = 0; r < 4; r++) oacc[nt][r] = 0.f;
    float m0r = -INFINITY, m1r = -INFINITY;
    float l0r = 0.f, l1r = 0.f;

    const int gi0 = m0 + r0 + g;
    const int gi1 = gi0 + 8;
    const int ntiles = 2 * (qt + 1);

    for (int kt_i = 0; kt_i < ntiles; kt_i++) {
        int j0 = kt_i * 64;
        __syncthreads();

        const __half* Kg = g_kh + ((size_t)bh * SEQ + j0) * HD;
        const __half* Vg = g_vh + ((size_t)bh * SEQ + j0) * HD;
#pragma unroll
        for (int i = 0; i < 4; i++) {
            int lin = t + i * 256;
            int row = lin >> 4, c = lin & 15;
            uint4 kv = *(const uint4*)(Kg + (size_t)row * HD + c * 8);
            *(uint4*)(Ks + row * 136 + c * 8) = kv;
            uint4 vv = *(const uint4*)(Vg + (size_t)row * HD + c * 8);
            *(uint4*)(Vs + row * 136 + c * 8) = vv;
        }
        __syncthreads();

        float sacc[8][4];
#pragma unroll
        for (int nt = 0; nt < 8; nt++)
#pragma unroll
            for (int r = 0; r < 4; r++) sacc[nt][r] = 0.f;

#pragma unroll
        for (int ks = 0; ks < 8; ks++) {
            const int kb = ks * 16;
            uint32_t af[4];
            ldsm_x4(af, sb + (uint32_t)((r0 + lrA) * 136 + kb + lcA) * 2u);
#pragma unroll
            for (int nt2 = 0; nt2 < 4; nt2++) {
                uint32_t r[4];
                ldsm_x4(r, ksb + (uint32_t)((nt2 * 16 + lrB) * 136 + kb + lcB) * 2u);
                mma_f16(sacc[nt2 * 2],     af, r);
                mma_f16(sacc[nt2 * 2 + 1], af, r + 2);
            }
        }

        float pm0 = -INFINITY, pm1 = -INFINITY;
#pragma unroll
        for (int nt = 0; nt < 8; nt++) {
            int c = j0 + nt * 8 + tig * 2;
            float s0 = sacc[nt][0] * scale; if (c     > gi0) s0 = -INFINITY;
            float s1 = sacc[nt][1] * scale; if (c + 1 > gi0) s1 = -INFINITY;
            float s2 = sacc[nt][2] * scale; if (c     > gi1) s2 = -INFINITY;
            float s3 = sacc[nt][3] * scale; if (c + 1 > gi1) s3 = -INFINITY;
            sacc[nt][0] = s0; sacc[nt][1] = s1;
            sacc[nt][2] = s2; sacc[nt][3] = s3;
            pm0 = fmaxf(pm0, fmaxf(s0, s1));
            pm1 = fmaxf(pm1, fmaxf(s2, s3));
        }
        pm0 = fmaxf(pm0, __shfl_xor_sync(0xFFFFFFFFu, pm0, 1));
        pm0 = fmaxf(pm0, __shfl_xor_sync(0xFFFFFFFFu, pm0, 2));
        pm1 = fmaxf(pm1, __shfl_xor_sync(0xFFFFFFFFu, pm1, 1));
        pm1 = fmaxf(pm1, __shfl_xor_sync(0xFFFFFFFFu, pm1, 2));

        float mn0 = fmaxf(m0r, pm0);
        float mn1 = fmaxf(m1r, pm1);
        float corr0 = __expf(m0r - mn0);
        float corr1 = __expf(m1r - mn1);

        float ps0 = 0.f, ps1 = 0.f;
#pragma unroll
        for (int nt = 0; nt < 8; nt++) {
            float p0 = __expf(sacc[nt][0] - mn0);
            float p1 = __expf(sacc[nt][1] - mn0);
            float p2 = __expf(sacc[nt][2] - mn1);
            float p3 = __expf(sacc[nt][3] - mn1);
            ps0 += p0 + p1; ps1 += p2 + p3;
            int jc = nt * 8 + tig * 2;
            *(__half2*)(Ps + (r0 + g    ) * 72 + jc) = __floats2half2_rn(p0, p1);
            *(__half2*)(Ps + (r0 + g + 8) * 72 + jc) = __floats2half2_rn(p2, p3);
        }
        ps0 += __shfl_xor_sync(0xFFFFFFFFu, ps0, 1);
        ps0 += __shfl_xor_sync(0xFFFFFFFFu, ps0, 2);
        ps1 += __shfl_xor_sync(0xFFFFFFFFu, ps1, 1);
        ps1 += __shfl_xor_sync(0xFFFFFFFFu, ps1, 2);

        l0r = l0r * corr0 + ps0;
        l1r = l1r * corr1 + ps1;
        m0r = mn0; m1r = mn1;

#pragma unroll
        for (int nt = 0; nt < 16; nt++) {
            oacc[nt][0] *= corr0; oacc[nt][1] *= corr0;
            oacc[nt][2] *= corr1; oacc[nt][3] *= corr1;
        }
        __syncwarp();

#pragma unroll
        for (int ks = 0; ks < 4; ks++) {
            const int kb = ks * 16;
            uint32_t af[4];
            ldsm_x4(af, psb + (uint32_t)((r0 + lrA) * 72 + kb + lcA) * 2u);
#pragma unroll
            for (int nt2 = 0; nt2 < 8; nt2++) {
                uint32_t r[4];
                ldsm_x4_t(r, vsb +
                    (uint32_t)((kb + lrT) * 136 + nt2 * 16 + lcT) * 2u);
                mma_f16(oacc[nt2 * 2],     af, r);
                mma_f16(oacc[nt2 * 2 + 1], af, r + 2);
            }
        }
    }

    float inv0 = 1.f / l0r, inv1 = 1.f / l1r;
    int b = bh >> 4, h = bh & 15;
    int row0 = m0 + r0 + g;
    __half* O0 = g_att_h + ((size_t)b * SEQ + row0    ) * HID + h * HD;
    __half* O1 = g_att_h + ((size_t)b * SEQ + row0 + 8) * HID + h * HD;
#pragma unroll
    for (int nt = 0; nt < 16; nt++) {
        int d = nt * 8 + tig * 2;
        *(__half2*)(O0 + d) =
            __floats2half2_rn(oacc[nt][0] * inv0, oacc[nt][1] * inv0);
        *(__half2*)(O1 + d) =
            __floats2half2_rn(oacc[nt][2] * inv1, oacc[nt][3] * inv1);
    }
}

// ---------------------------------------------------------------------------
extern "C" void kernel_launch(void* const* d_in, const int* in_sizes, int n_in,
                              void* d_out, int out_size)
{
    const float* x     = (const float*)d_in[0];
    const float* qkv_w = (const float*)d_in[1];
    const float* o_w   = (const float*)d_in[2];
    const float* cosb  = (const float*)d_in[3];
    const float* sinb  = (const float*)d_in[4];
    float* out = (float*)d_out;

    cudaFuncSetAttribute(h_gemm<0>,
        cudaFuncAttributeMaxDynamicSharedMemorySize, HGEMM_SMEM_BYTES);
    cudaFuncSetAttribute(h_gemm<1>,
        cudaFuncAttributeMaxDynamicSharedMemorySize, HGEMM_SMEM_BYTES);

    // 0) fp32 -> fp16 (rn) conversions of GEMM inputs
    f2h_kernel<0><<<(MROWS * HID) / 1024, 256>>>(x);
    f2h_kernel<1><<<(3 * HID * HID) / 1024, 256>>>(qkv_w);
    f2h_kernel<2><<<(HID * HID) / 1024, 256>>>(o_w);

    // 1) QKV projection: grid (48, 32), 128x128 tiles, 128 threads
    h_gemm<0><<<dim3(6144 / 128, MROWS / 128), 128, HGEMM_SMEM_BYTES>>>(nullptr);

    // 2) rotary (fp16 in place)
    rotary_h_kernel<<<(NBATCH * NHEADS * SEQ * 32) / 256, 256>>>(cosb, sinb);

    // 3) flash attention (fp16 MMA), 86 KB smem, 2 CTAs/SM
    {
        const size_t smem = FLASH3_SMEM_HALVES * sizeof(__half); // 88064 B
        cudaFuncSetAttribute(flash_h_kernel,
                             cudaFuncAttributeMaxDynamicSharedMemorySize,
                             (int)smem);
        flash_h_kernel<<<dim3(NBATCH * NHEADS, SEQ / 128), 256, smem>>>();
    }

    // 4) output projection: grid (16, 32), 128 threads
    h_gemm<1><<<dim3(HID / 128, MROWS / 128), 128, HGEMM_SMEM_BYTES>>>(out);
}